// round 1
// baseline (speedup 1.0000x reference)
#include <cuda_runtime.h>
#include <cuda_bf16.h>

// Problem constants
#define WS 7
#define NTOK 49            // tokens per window
#define DIM 256
#define H 8
#define DH 32              // DIM / H
#define BWIN 2048          // total windows
#define NW 64              // windows per image (mask leading dim)
#define QKV_COLS 768       // 3*DIM
#define MROWS (BWIN * NTOK)  // 100352

// Scratch (allocation-free rule: device globals)
__device__ float g_qkv[(size_t)MROWS * QKV_COLS];      // [b*49+n][s*256 + h*32 + d]
__device__ float g_attn_out[(size_t)MROWS * DIM];      // [b*49+n][h*32 + d]

// ---------------------------------------------------------------------------
// Tiled NT GEMM: C[m][n] = sum_k A[m][k] * W[n][k] + bias[n]
// A: [M,K] row-major, W: [N,K] row-major. M%64==0, N%64==0, K%16==0 assumed.
// ---------------------------------------------------------------------------
#define BM 64
#define BN 64
#define BK 16

__global__ __launch_bounds__(256) void gemm_nt_bias(
    const float* __restrict__ A, const float* __restrict__ W,
    const float* __restrict__ bias, float* __restrict__ C,
    int M, int N, int K)
{
    __shared__ float As[BK][BM];
    __shared__ float Ws[BK][BN];

    const int tid = threadIdx.x;
    const int block_m = blockIdx.y * BM;
    const int block_n = blockIdx.x * BN;
    const int tx = tid & 15;        // 0..15 -> cols (x4)
    const int ty = tid >> 4;        // 0..15 -> rows (x4)

    // load mapping: each thread loads one float4 along K for A and W
    const int lr = tid >> 2;        // 0..63 row within tile
    const int lc = (tid & 3) << 2;  // 0,4,8,12 k-offset

    const float* Aptr = A + (size_t)(block_m + lr) * K + lc;
    const float* Wptr = W + (size_t)(block_n + lr) * K + lc;

    float acc[4][4];
    #pragma unroll
    for (int i = 0; i < 4; i++)
        #pragma unroll
        for (int j = 0; j < 4; j++) acc[i][j] = 0.f;

    for (int k0 = 0; k0 < K; k0 += BK) {
        float4 av = *reinterpret_cast<const float4*>(Aptr + k0);
        float4 wv = *reinterpret_cast<const float4*>(Wptr + k0);
        As[lc + 0][lr] = av.x; As[lc + 1][lr] = av.y;
        As[lc + 2][lr] = av.z; As[lc + 3][lr] = av.w;
        Ws[lc + 0][lr] = wv.x; Ws[lc + 1][lr] = wv.y;
        Ws[lc + 2][lr] = wv.z; Ws[lc + 3][lr] = wv.w;
        __syncthreads();

        #pragma unroll
        for (int kk = 0; kk < BK; kk++) {
            float ar[4], wr[4];
            #pragma unroll
            for (int i = 0; i < 4; i++) ar[i] = As[kk][ty * 4 + i];
            #pragma unroll
            for (int j = 0; j < 4; j++) wr[j] = Ws[kk][tx * 4 + j];
            #pragma unroll
            for (int i = 0; i < 4; i++)
                #pragma unroll
                for (int j = 0; j < 4; j++)
                    acc[i][j] += ar[i] * wr[j];
        }
        __syncthreads();
    }

    #pragma unroll
    for (int i = 0; i < 4; i++) {
        const int m = block_m + ty * 4 + i;
        #pragma unroll
        for (int j = 0; j < 4; j++) {
            const int n = block_n + tx * 4 + j;
            C[(size_t)m * N + n] = acc[i][j] + bias[n];
        }
    }
}

// ---------------------------------------------------------------------------
// Attention core: one block per (window b, head h). 128 threads.
// ---------------------------------------------------------------------------
__global__ __launch_bounds__(128) void attn_kernel(
    const float* __restrict__ qkv,       // g_qkv
    const float* __restrict__ mask,      // [64][49][49]
    const float* __restrict__ rpb_table, // [169][8]
    const int* __restrict__ rel_index,   // [49*49]
    float* __restrict__ out)             // g_attn_out
{
    const int b = blockIdx.x >> 3;
    const int h = blockIdx.x & 7;
    const int tid = threadIdx.x;
    const float scale = 0.17677669529663687f;  // 32^-0.5

    __shared__ float qs[NTOK][DH + 1];
    __shared__ float ks[NTOK][DH + 1];
    __shared__ float vs[NTOK][DH + 1];
    __shared__ float at[NTOK][NTOK + 3];

    const size_t base = (size_t)b * NTOK * QKV_COLS + h * DH;
    for (int idx = tid; idx < NTOK * DH; idx += 128) {
        const int n = idx >> 5;
        const int d = idx & 31;
        const size_t row = base + (size_t)n * QKV_COLS + d;
        qs[n][d] = qkv[row] * scale;
        ks[n][d] = qkv[row + 256];
        vs[n][d] = qkv[row + 512];
    }
    __syncthreads();

    // scores + rpb + mask
    const float* mrow = mask + (size_t)(b & (NW - 1)) * NTOK * NTOK;
    for (int idx = tid; idx < NTOK * NTOK; idx += 128) {
        const int i = idx / NTOK;
        const int j = idx - i * NTOK;
        float s = 0.f;
        #pragma unroll
        for (int d = 0; d < DH; d++) s += qs[i][d] * ks[j][d];
        s += rpb_table[rel_index[idx] * H + h];
        s += mrow[idx];
        at[i][j] = s;
    }
    __syncthreads();

    // row softmax (one thread per row)
    if (tid < NTOK) {
        float mx = -1e30f;
        #pragma unroll 7
        for (int j = 0; j < NTOK; j++) mx = fmaxf(mx, at[tid][j]);
        float sum = 0.f;
        #pragma unroll 7
        for (int j = 0; j < NTOK; j++) {
            const float e = __expf(at[tid][j] - mx);
            at[tid][j] = e;
            sum += e;
        }
        const float inv = 1.f / sum;
        #pragma unroll 7
        for (int j = 0; j < NTOK; j++) at[tid][j] *= inv;
    }
    __syncthreads();

    // out = attn @ v
    for (int idx = tid; idx < NTOK * DH; idx += 128) {
        const int n = idx >> 5;
        const int d = idx & 31;
        float acc = 0.f;
        #pragma unroll 7
        for (int m = 0; m < NTOK; m++) acc += at[n][m] * vs[m][d];
        out[((size_t)b * NTOK + n) * DIM + h * DH + d] = acc;
    }
}

// ---------------------------------------------------------------------------
// Launch
// ---------------------------------------------------------------------------
extern "C" void kernel_launch(void* const* d_in, const int* in_sizes, int n_in,
                              void* d_out, int out_size) {
    const float* x         = (const float*)d_in[0];  // [2048,49,256]
    const float* mask      = (const float*)d_in[1];  // [64,49,49]
    const float* qkv_w     = (const float*)d_in[2];  // [768,256]
    const float* qkv_b     = (const float*)d_in[3];  // [768]
    const float* proj_w    = (const float*)d_in[4];  // [256,256]
    const float* proj_b    = (const float*)d_in[5];  // [256]
    const float* rpb_table = (const float*)d_in[6];  // [169,8]
    const int*   rel_index = (const int*)d_in[7];    // [49,49]
    float* out = (float*)d_out;

    float* qkv;      cudaGetSymbolAddress((void**)&qkv, g_qkv);
    float* attn_out; cudaGetSymbolAddress((void**)&attn_out, g_attn_out);

    // 1) QKV projection: [100352,256] x [768,256]^T
    {
        dim3 grid(QKV_COLS / BN, MROWS / BM);
        gemm_nt_bias<<<grid, 256>>>(x, qkv_w, qkv_b, qkv, MROWS, QKV_COLS, DIM);
    }
    // 2) Attention per (window, head)
    attn_kernel<<<BWIN * H, 128>>>(qkv, mask, rpb_table, rel_index, attn_out);
    // 3) Output projection: [100352,256] x [256,256]^T
    {
        dim3 grid(DIM / BN, MROWS / BM);
        gemm_nt_bias<<<grid, 256>>>(attn_out, proj_w, proj_b, out, MROWS, DIM, DIM);
    }
}

// round 2
// speedup vs baseline: 2.4095x; 2.4095x over previous
#include <cuda_runtime.h>
#include <cuda_bf16.h>
#include <cstdint>

// Problem constants
#define NTOK 49            // tokens per window
#define NPAD 52            // padded token count (multiple of 4)
#define DIM 256
#define H 8
#define DH 32              // DIM / H
#define BWIN 2048          // total windows
#define NW 64              // windows per image
#define QKV_COLS 768       // 3*DIM
#define MROWS (BWIN * NTOK)  // 100352

// Scratch (allocation-free rule: device globals)
__device__ float g_qkv[(size_t)MROWS * QKV_COLS];
__device__ float g_attn_out[(size_t)MROWS * DIM];

// ---------------------------------------------------------------------------
// Helpers: cp.async, tf32 cvt, mma
// ---------------------------------------------------------------------------
__device__ __forceinline__ void cp_async16(void* s, const void* g) {
    uint32_t sa = (uint32_t)__cvta_generic_to_shared(s);
    asm volatile("cp.async.cg.shared.global [%0], [%1], 16;" :: "r"(sa), "l"(g));
}
__device__ __forceinline__ void cp_commit() {
    asm volatile("cp.async.commit_group;");
}
template<int Nw> __device__ __forceinline__ void cp_wait() {
    asm volatile("cp.async.wait_group %0;" :: "n"(Nw));
}
__device__ __forceinline__ uint32_t f2tf(float x) {
    uint32_t r;
    asm("cvt.rna.tf32.f32 %0, %1;" : "=r"(r) : "f"(x));
    return r;
}
__device__ __forceinline__ void mma_tf32(float c[4], const uint32_t a[4], const uint32_t b[2]) {
    asm volatile(
        "mma.sync.aligned.m16n8k8.row.col.f32.tf32.tf32.f32 "
        "{%0,%1,%2,%3}, {%4,%5,%6,%7}, {%8,%9}, {%0,%1,%2,%3};"
        : "+f"(c[0]), "+f"(c[1]), "+f"(c[2]), "+f"(c[3])
        : "r"(a[0]), "r"(a[1]), "r"(a[2]), "r"(a[3]), "r"(b[0]), "r"(b[1]));
}

// ---------------------------------------------------------------------------
// TF32 tensor-core NT GEMM + bias: C[m][n] = sum_k A[m][k]*W[n][k] + bias[n]
// Block tile 128(M) x 64(N), BK=32, 8 warps (4x2), warp tile 32x32.
// Requires M%128==0, N%64==0, K%32==0.
// ---------------------------------------------------------------------------
#define GBM 128
#define GBN 64
#define GBK 32
#define GSTR 36  // smem row stride in floats (bank = (4*row+col)%32, conflict-free frags)

#define GEMM_SMEM_BYTES ((2*GBM*GSTR + 2*GBN*GSTR) * 4)  // 55296

__global__ __launch_bounds__(256) void gemm_tf32_nt_bias(
    const float* __restrict__ A, const float* __restrict__ W,
    const float* __restrict__ bias, float* __restrict__ C,
    int M, int N, int K)
{
    extern __shared__ float smem[];
    float* As0 = smem;                       // [2][128*36]
    float* Bs0 = smem + 2 * GBM * GSTR;      // [2][64*36]

    const int tid  = threadIdx.x;
    const int lane = tid & 31;
    const int warp = tid >> 5;
    const int wm = warp >> 1;        // 0..3
    const int wn = warp & 1;         // 0..1
    const int group = lane >> 2;     // 0..7
    const int tig   = lane & 3;      // 0..3

    const int bm = blockIdx.y * GBM;
    const int bn = blockIdx.x * GBN;

    // cooperative load mapping: 8 threads per row, float4 each
    const int ra = tid >> 3;          // 0..31
    const int ca = (tid & 7) << 2;    // 0,4,...,28

    const float* Ag = A + (size_t)(bm + ra) * K + ca;
    const float* Wg = W + (size_t)(bn + ra) * K + ca;

    float acc[2][4][4];
    #pragma unroll
    for (int mt = 0; mt < 2; mt++)
        #pragma unroll
        for (int nt = 0; nt < 4; nt++)
            #pragma unroll
            for (int r = 0; r < 4; r++) acc[mt][nt][r] = 0.f;

    const int NS = K >> 5;   // stages of BK=32

    // prefetch stage 0
    {
        float* as = As0;
        float* bs = Bs0;
        #pragma unroll
        for (int p = 0; p < 4; p++)
            cp_async16(&as[(ra + p*32)*GSTR + ca], Ag + (size_t)p*32*K);
        #pragma unroll
        for (int p = 0; p < 2; p++)
            cp_async16(&bs[(ra + p*32)*GSTR + ca], Wg + (size_t)p*32*K);
        cp_commit();
    }

    for (int s = 0; s < NS; s++) {
        if (s + 1 < NS) {
            const int nb = (s + 1) & 1;
            const int k0 = (s + 1) << 5;
            float* as = As0 + nb * GBM * GSTR;
            float* bs = Bs0 + nb * GBN * GSTR;
            #pragma unroll
            for (int p = 0; p < 4; p++)
                cp_async16(&as[(ra + p*32)*GSTR + ca], Ag + k0 + (size_t)p*32*K);
            #pragma unroll
            for (int p = 0; p < 2; p++)
                cp_async16(&bs[(ra + p*32)*GSTR + ca], Wg + k0 + (size_t)p*32*K);
            cp_commit();
            cp_wait<1>();
        } else {
            cp_wait<0>();
        }
        __syncthreads();

        const float* as = As0 + (s & 1) * GBM * GSTR;
        const float* bs = Bs0 + (s & 1) * GBN * GSTR;

        #pragma unroll
        for (int kk = 0; kk < 4; kk++) {
            const int k8 = kk * 8;
            uint32_t af[2][4], bf[4][2];
            #pragma unroll
            for (int mt = 0; mt < 2; mt++) {
                const float* p = as + (wm*32 + mt*16 + group) * GSTR + k8;
                af[mt][0] = f2tf(p[tig]);
                af[mt][1] = f2tf(p[8*GSTR + tig]);
                af[mt][2] = f2tf(p[tig + 4]);
                af[mt][3] = f2tf(p[8*GSTR + tig + 4]);
            }
            #pragma unroll
            for (int nt = 0; nt < 4; nt++) {
                const float* p = bs + (wn*32 + nt*8 + group) * GSTR + k8;
                bf[nt][0] = f2tf(p[tig]);
                bf[nt][1] = f2tf(p[tig + 4]);
            }
            #pragma unroll
            for (int mt = 0; mt < 2; mt++)
                #pragma unroll
                for (int nt = 0; nt < 4; nt++)
                    mma_tf32(acc[mt][nt], af[mt], bf[nt]);
        }
        __syncthreads();
    }

    // epilogue
    #pragma unroll
    for (int mt = 0; mt < 2; mt++) {
        const int r = bm + wm*32 + mt*16 + group;
        #pragma unroll
        for (int nt = 0; nt < 4; nt++) {
            const int c = bn + wn*32 + nt*8 + tig*2;
            const float bx = bias[c], by = bias[c + 1];
            float2 v0 = make_float2(acc[mt][nt][0] + bx, acc[mt][nt][1] + by);
            float2 v1 = make_float2(acc[mt][nt][2] + bx, acc[mt][nt][3] + by);
            *reinterpret_cast<float2*>(&C[(size_t)r * N + c]) = v0;
            *reinterpret_cast<float2*>(&C[(size_t)(r + 8) * N + c]) = v1;
        }
    }
}

// ---------------------------------------------------------------------------
// Attention core: one block per (window b, head h). 128 threads.
// 4x4 register blocking with float4 LDS; padded to 52 tokens.
// ---------------------------------------------------------------------------
__global__ __launch_bounds__(128) void attn_kernel(
    const float* __restrict__ qkv,
    const float* __restrict__ mask,      // [64][49][49]
    const float* __restrict__ rpb_table, // [169][8]
    const int* __restrict__ rel_index,   // [49*49]
    float* __restrict__ out)
{
    const int b = blockIdx.x >> 3;
    const int h = blockIdx.x & 7;
    const int tid = threadIdx.x;
    const float scale = 0.17677669529663687f;  // 32^-0.5

    __shared__ float qs[NPAD][DH];
    __shared__ float ks[NPAD][DH];
    __shared__ float vs[NPAD][DH];
    __shared__ float at[NPAD][NPAD];
    __shared__ float rinv[NPAD];

    // load q/k/v (vectorized), scale q
    const size_t base = (size_t)b * NTOK * QKV_COLS + h * DH;
    for (int idx = tid; idx < NTOK * 8; idx += 128) {
        const int n = idx >> 3;
        const int d4 = (idx & 7) << 2;
        const float* row = qkv + base + (size_t)n * QKV_COLS + d4;
        float4 qv = *reinterpret_cast<const float4*>(row);
        float4 kv = *reinterpret_cast<const float4*>(row + DIM);
        float4 vv = *reinterpret_cast<const float4*>(row + 2 * DIM);
        qv.x *= scale; qv.y *= scale; qv.z *= scale; qv.w *= scale;
        *reinterpret_cast<float4*>(&qs[n][d4]) = qv;
        *reinterpret_cast<float4*>(&ks[n][d4]) = kv;
        *reinterpret_cast<float4*>(&vs[n][d4]) = vv;
    }
    // zero the 3 padded rows
    if (tid < 96) {
        const int r = NTOK + tid / 32;
        const int d = tid & 31;
        qs[r][d] = 0.f; ks[r][d] = 0.f; vs[r][d] = 0.f;
    }
    __syncthreads();

    // scores: 13x13 grid of 4x4 tiles
    for (int t = tid; t < 169; t += 128) {
        const int i0 = (t / 13) * 4;
        const int j0 = (t % 13) * 4;
        float acc[4][4];
        #pragma unroll
        for (int a = 0; a < 4; a++)
            #pragma unroll
            for (int c = 0; c < 4; c++) acc[a][c] = 0.f;

        #pragma unroll
        for (int d = 0; d < DH; d += 4) {
            float4 qv[4], kv[4];
            #pragma unroll
            for (int a = 0; a < 4; a++) qv[a] = *reinterpret_cast<const float4*>(&qs[i0 + a][d]);
            #pragma unroll
            for (int c = 0; c < 4; c++) kv[c] = *reinterpret_cast<const float4*>(&ks[j0 + c][d]);
            #pragma unroll
            for (int a = 0; a < 4; a++)
                #pragma unroll
                for (int c = 0; c < 4; c++)
                    acc[a][c] += qv[a].x * kv[c].x + qv[a].y * kv[c].y
                               + qv[a].z * kv[c].z + qv[a].w * kv[c].w;
        }
        #pragma unroll
        for (int a = 0; a < 4; a++)
            #pragma unroll
            for (int c = 0; c < 4; c++)
                at[i0 + a][j0 + c] = acc[a][c];
    }
    __syncthreads();

    // add rpb + mask (valid region), set padded cols to -inf
    const float* mrow = mask + (size_t)(b & (NW - 1)) * NTOK * NTOK;
    for (int idx = tid; idx < NTOK * NTOK; idx += 128) {
        const int i = idx / NTOK;
        const int j = idx - i * NTOK;
        at[i][j] += rpb_table[rel_index[idx] * H + h] + mrow[idx];
    }
    for (int idx = tid; idx < NPAD * 3; idx += 128) {
        const int i = idx / 3;
        const int j = NTOK + idx % 3;
        at[i][j] = -1e30f;
    }
    __syncthreads();

    // softmax per row (unnormalized exp; 1/sum saved for epilogue)
    if (tid < NTOK) {
        float4* row = reinterpret_cast<float4*>(at[tid]);
        float mx = -1e30f;
        #pragma unroll
        for (int c = 0; c < 13; c++) {
            float4 v = row[c];
            mx = fmaxf(mx, fmaxf(fmaxf(v.x, v.y), fmaxf(v.z, v.w)));
        }
        float sum = 0.f;
        #pragma unroll
        for (int c = 0; c < 13; c++) {
            float4 v = row[c];
            v.x = __expf(v.x - mx); v.y = __expf(v.y - mx);
            v.z = __expf(v.z - mx); v.w = __expf(v.w - mx);
            row[c] = v;
            sum += v.x + v.y + v.z + v.w;
        }
        rinv[tid] = 1.f / sum;
    } else if (tid < NPAD) {
        rinv[tid] = 0.f;
    }
    __syncthreads();

    // out = (attn @ v) * rinv ; 13 n-tiles x 8 d-tiles = 104 threads active
    if (tid < 104) {
        const int n0 = (tid >> 3) * 4;
        const int d0 = (tid & 7) * 4;
        float4 acc4[4];
        #pragma unroll
        for (int a = 0; a < 4; a++) acc4[a] = make_float4(0.f, 0.f, 0.f, 0.f);

        for (int m = 0; m < NPAD; m += 4) {
            float4 v0 = *reinterpret_cast<const float4*>(&vs[m + 0][d0]);
            float4 v1 = *reinterpret_cast<const float4*>(&vs[m + 1][d0]);
            float4 v2 = *reinterpret_cast<const float4*>(&vs[m + 2][d0]);
            float4 v3 = *reinterpret_cast<const float4*>(&vs[m + 3][d0]);
            #pragma unroll
            for (int a = 0; a < 4; a++) {
                float4 w = *reinterpret_cast<const float4*>(&at[n0 + a][m]);
                acc4[a].x += w.x * v0.x + w.y * v1.x + w.z * v2.x + w.w * v3.x;
                acc4[a].y += w.x * v0.y + w.y * v1.y + w.z * v2.y + w.w * v3.y;
                acc4[a].z += w.x * v0.z + w.y * v1.z + w.z * v2.z + w.w * v3.z;
                acc4[a].w += w.x * v0.w + w.y * v1.w + w.z * v2.w + w.w * v3.w;
            }
        }
        #pragma unroll
        for (int a = 0; a < 4; a++) {
            const int n = n0 + a;
            if (n < NTOK) {
                const float ri = rinv[n];
                float4 o = make_float4(acc4[a].x * ri, acc4[a].y * ri,
                                       acc4[a].z * ri, acc4[a].w * ri);
                *reinterpret_cast<float4*>(
                    &out[((size_t)b * NTOK + n) * DIM + h * DH + d0]) = o;
            }
        }
    }
}

// ---------------------------------------------------------------------------
// Launch
// ---------------------------------------------------------------------------
extern "C" void kernel_launch(void* const* d_in, const int* in_sizes, int n_in,
                              void* d_out, int out_size) {
    const float* x         = (const float*)d_in[0];
    const float* mask      = (const float*)d_in[1];
    const float* qkv_w     = (const float*)d_in[2];
    const float* qkv_b     = (const float*)d_in[3];
    const float* proj_w    = (const float*)d_in[4];
    const float* proj_b    = (const float*)d_in[5];
    const float* rpb_table = (const float*)d_in[6];
    const int*   rel_index = (const int*)d_in[7];
    float* out = (float*)d_out;

    float* qkv;      cudaGetSymbolAddress((void**)&qkv, g_qkv);
    float* attn_out; cudaGetSymbolAddress((void**)&attn_out, g_attn_out);

    cudaFuncSetAttribute(gemm_tf32_nt_bias,
                         cudaFuncAttributeMaxDynamicSharedMemorySize,
                         GEMM_SMEM_BYTES);

    // 1) QKV projection: [100352,256] x [768,256]^T (tf32 tensor cores)
    {
        dim3 grid(QKV_COLS / GBN, MROWS / GBM);
        gemm_tf32_nt_bias<<<grid, 256, GEMM_SMEM_BYTES>>>(
            x, qkv_w, qkv_b, qkv, MROWS, QKV_COLS, DIM);
    }
    // 2) Attention per (window, head)
    attn_kernel<<<BWIN * H, 128>>>(qkv, mask, rpb_table, rel_index, attn_out);
    // 3) Output projection: [100352,256] x [256,256]^T
    {
        dim3 grid(DIM / GBN, MROWS / GBM);
        gemm_tf32_nt_bias<<<grid, 256, GEMM_SMEM_BYTES>>>(
            attn_out, proj_w, proj_b, out, MROWS, DIM, DIM);
    }
}

// round 3
// speedup vs baseline: 2.9280x; 1.2152x over previous
#include <cuda_runtime.h>
#include <cuda_bf16.h>
#include <cstdint>

// Problem constants
#define NTOK 49
#define DIM 256
#define H 8
#define DH 32
#define BWIN 2048
#define NW 64
#define QKV_COLS 768
#define MROWS (BWIN * NTOK)  // 100352

// Scratch (allocation-free rule: device globals)
__device__ float g_qkv[(size_t)MROWS * QKV_COLS];
__device__ float g_attn_out[(size_t)MROWS * DIM];
__device__ float g_bias[(size_t)NW * H * NTOK * NTOK];  // mask + rpb precombined

// ---------------------------------------------------------------------------
// Helpers
// ---------------------------------------------------------------------------
__device__ __forceinline__ uint32_t f2tf(float x) {
    uint32_t r;
    asm("cvt.rna.tf32.f32 %0, %1;" : "=r"(r) : "f"(x));
    return r;
}
__device__ __forceinline__ void mma_tf32(float c[4], const uint32_t a[4], const uint32_t b[2]) {
    asm volatile(
        "mma.sync.aligned.m16n8k8.row.col.f32.tf32.tf32.f32 "
        "{%0,%1,%2,%3}, {%4,%5,%6,%7}, {%8,%9}, {%0,%1,%2,%3};"
        : "+f"(c[0]), "+f"(c[1]), "+f"(c[2]), "+f"(c[3])
        : "r"(a[0]), "r"(a[1]), "r"(a[2]), "r"(a[3]), "r"(b[0]), "r"(b[1]));
}

// ---------------------------------------------------------------------------
// Bias precompute: g_bias[w][h][i][j] = mask[w][i][j] + rpb[rel_index[i][j]][h]
// ---------------------------------------------------------------------------
__global__ __launch_bounds__(256) void bias_pre(
    const float* __restrict__ mask, const float* __restrict__ rpb,
    const int* __restrict__ ridx, float* __restrict__ biasAll)
{
    const int wh = blockIdx.x;          // w*8 + h
    const int w = wh >> 3, h = wh & 7;
    const float* m = mask + (size_t)w * (NTOK * NTOK);
    float* o = biasAll + (size_t)wh * (NTOK * NTOK);
    for (int ij = threadIdx.x; ij < NTOK * NTOK; ij += 256)
        o[ij] = m[ij] + rpb[ridx[ij] * H + h];
}

// ---------------------------------------------------------------------------
// TF32 tensor-core NT GEMM + bias. Block 128x64, BK=32, 8 warps (4x2).
// tf32 conversion at smem-fill time (reg staged), pure LDS+MMA inner loop.
// ---------------------------------------------------------------------------
#define GBM 128
#define GBN 64
#define GSTR 36
#define GEMM_SMEM_BYTES ((2*GBM*GSTR + 2*GBN*GSTR) * 4)  // 55296

__global__ __launch_bounds__(256, 2) void gemm_tf32_nt_bias(
    const float* __restrict__ A, const float* __restrict__ W,
    const float* __restrict__ bias, float* __restrict__ C,
    int M, int N, int K)
{
    extern __shared__ uint32_t usm[];
    uint32_t* As0 = usm;                     // [2][128*36]
    uint32_t* Bs0 = usm + 2 * GBM * GSTR;    // [2][64*36]

    const int tid  = threadIdx.x;
    const int lane = tid & 31;
    const int warp = tid >> 5;
    const int wm = warp >> 1;
    const int wn = warp & 1;
    const int group = lane >> 2;
    const int tig   = lane & 3;

    const int bm = blockIdx.y * GBM;
    const int bn = blockIdx.x * GBN;

    const int ra = tid >> 3;          // 0..31
    const int ca = (tid & 7) << 2;    // 0,4,...,28

    const float* Ag = A + (size_t)(bm + ra) * K + ca;
    const float* Wg = W + (size_t)(bn + ra) * K + ca;

    float acc[2][4][4];
    #pragma unroll
    for (int mt = 0; mt < 2; mt++)
        #pragma unroll
        for (int nt = 0; nt < 4; nt++)
            #pragma unroll
            for (int r = 0; r < 4; r++) acc[mt][nt][r] = 0.f;

    const int NS = K >> 5;

    float4 a_st[4], b_st[2];

    // prologue: load + convert + store stage 0
    #pragma unroll
    for (int p = 0; p < 4; p++) a_st[p] = *reinterpret_cast<const float4*>(Ag + (size_t)p * 32 * K);
    #pragma unroll
    for (int p = 0; p < 2; p++) b_st[p] = *reinterpret_cast<const float4*>(Wg + (size_t)p * 32 * K);
    #pragma unroll
    for (int p = 0; p < 4; p++)
        *reinterpret_cast<uint4*>(&As0[(ra + p*32)*GSTR + ca]) =
            make_uint4(f2tf(a_st[p].x), f2tf(a_st[p].y), f2tf(a_st[p].z), f2tf(a_st[p].w));
    #pragma unroll
    for (int p = 0; p < 2; p++)
        *reinterpret_cast<uint4*>(&Bs0[(ra + p*32)*GSTR + ca]) =
            make_uint4(f2tf(b_st[p].x), f2tf(b_st[p].y), f2tf(b_st[p].z), f2tf(b_st[p].w));
    __syncthreads();

    for (int s = 0; s < NS; s++) {
        const bool more = (s + 1 < NS);
        if (more) {
            const int k0 = (s + 1) << 5;
            #pragma unroll
            for (int p = 0; p < 4; p++) a_st[p] = *reinterpret_cast<const float4*>(Ag + k0 + (size_t)p * 32 * K);
            #pragma unroll
            for (int p = 0; p < 2; p++) b_st[p] = *reinterpret_cast<const float4*>(Wg + k0 + (size_t)p * 32 * K);
        }

        const uint32_t* as = As0 + (s & 1) * GBM * GSTR;
        const uint32_t* bs = Bs0 + (s & 1) * GBN * GSTR;

        #pragma unroll
        for (int kk = 0; kk < 4; kk++) {
            const int k8 = kk * 8;
            uint32_t af[2][4], bf[4][2];
            #pragma unroll
            for (int mt = 0; mt < 2; mt++) {
                const uint32_t* p = as + (wm*32 + mt*16 + group) * GSTR + k8;
                af[mt][0] = p[tig];
                af[mt][1] = p[8*GSTR + tig];
                af[mt][2] = p[tig + 4];
                af[mt][3] = p[8*GSTR + tig + 4];
            }
            #pragma unroll
            for (int nt = 0; nt < 4; nt++) {
                const uint32_t* p = bs + (wn*32 + nt*8 + group) * GSTR + k8;
                bf[nt][0] = p[tig];
                bf[nt][1] = p[tig + 4];
            }
            #pragma unroll
            for (int mt = 0; mt < 2; mt++)
                #pragma unroll
                for (int nt = 0; nt < 4; nt++)
                    mma_tf32(acc[mt][nt], af[mt], bf[nt]);
        }

        if (more) {
            const int nb = (s + 1) & 1;
            uint32_t* an = As0 + nb * GBM * GSTR;
            uint32_t* bn2 = Bs0 + nb * GBN * GSTR;
            #pragma unroll
            for (int p = 0; p < 4; p++)
                *reinterpret_cast<uint4*>(&an[(ra + p*32)*GSTR + ca]) =
                    make_uint4(f2tf(a_st[p].x), f2tf(a_st[p].y), f2tf(a_st[p].z), f2tf(a_st[p].w));
            #pragma unroll
            for (int p = 0; p < 2; p++)
                *reinterpret_cast<uint4*>(&bn2[(ra + p*32)*GSTR + ca]) =
                    make_uint4(f2tf(b_st[p].x), f2tf(b_st[p].y), f2tf(b_st[p].z), f2tf(b_st[p].w));
        }
        __syncthreads();
    }

    #pragma unroll
    for (int mt = 0; mt < 2; mt++) {
        const int r = bm + wm*32 + mt*16 + group;
        #pragma unroll
        for (int nt = 0; nt < 4; nt++) {
            const int c = bn + wn*32 + nt*8 + tig*2;
            const float bx = bias[c], by = bias[c + 1];
            float2 v0 = make_float2(acc[mt][nt][0] + bx, acc[mt][nt][1] + by);
            float2 v1 = make_float2(acc[mt][nt][2] + bx, acc[mt][nt][3] + by);
            *reinterpret_cast<float2*>(&C[(size_t)r * N + c]) = v0;
            *reinterpret_cast<float2*>(&C[(size_t)(r + 8) * N + c]) = v1;
        }
    }
}

// ---------------------------------------------------------------------------
// Tensor-core attention: one block per (window b, head h), 4 warps.
// QK^T split-tf32 (fp32-grade), register softmax, AV single tf32.
// ---------------------------------------------------------------------------
#define QR 36   // stride for q/k tf32 tiles
#define PR 60   // stride for vt / P tiles
// smem (uint32 words): qh[64*36] ql[64*36] kh[56*36] kl[56*36] vt[32*60] pbs[64*60]
#define ATTN_SMEM_WORDS (2*64*QR + 2*56*QR + 32*PR + 64*PR)
#define ATTN_SMEM_BYTES (ATTN_SMEM_WORDS * 4)   // 57600

__global__ __launch_bounds__(128) void attn_mma(
    const float* __restrict__ qkv,
    const float* __restrict__ biasAll,
    float* __restrict__ out)
{
    extern __shared__ uint32_t sm[];
    uint32_t* qh  = sm;
    uint32_t* ql  = qh + 64*QR;
    uint32_t* kh  = ql + 64*QR;
    uint32_t* kl  = kh + 56*QR;
    uint32_t* vt  = kl + 56*QR;      // [32][60] (transposed V, tf32)
    uint32_t* pbs = vt + 32*PR;      // [64][60] bias(float bits) then P(tf32)

    const int b = blockIdx.x >> 3;
    const int h = blockIdx.x & 7;
    const int tid = threadIdx.x;
    const float scale = 0.17677669529663687f;

    // ---- load q,k,v; split-tf32 for q,k; tf32 transposed v ----
    const float* base = qkv + (size_t)b * NTOK * QKV_COLS + h * DH;
    for (int idx = tid; idx < NTOK * 8; idx += 128) {
        const int n = idx >> 3, d4 = (idx & 7) << 2;
        const float* r = base + (size_t)n * QKV_COLS + d4;
        float4 q = *reinterpret_cast<const float4*>(r);
        float4 k = *reinterpret_cast<const float4*>(r + DIM);
        float4 v = *reinterpret_cast<const float4*>(r + 2 * DIM);
        q.x *= scale; q.y *= scale; q.z *= scale; q.w *= scale;
        const float* qp = &q.x; const float* kp = &k.x; const float* vp = &v.x;
        #pragma unroll
        for (int i = 0; i < 4; i++) {
            const int c = d4 + i;
            uint32_t hi = f2tf(qp[i]);
            qh[n*QR + c] = hi;
            ql[n*QR + c] = f2tf(qp[i] - __uint_as_float(hi));
            hi = f2tf(kp[i]);
            kh[n*QR + c] = hi;
            kl[n*QR + c] = f2tf(kp[i] - __uint_as_float(hi));
            vt[c*PR + n] = f2tf(vp[i]);
        }
    }
    // zero pads: q rows 49..63, k rows 49..55, v token-cols 49..55
    for (int idx = tid; idx < 15 * 32; idx += 128) {
        const int r = 49 + (idx >> 5), c = idx & 31;
        qh[r*QR + c] = 0; ql[r*QR + c] = 0;
    }
    for (int idx = tid; idx < 7 * 32; idx += 128) {
        const int r = 49 + (idx >> 5), c = idx & 31;
        kh[r*QR + c] = 0; kl[r*QR + c] = 0;
    }
    for (int idx = tid; idx < 32 * 7; idx += 128) {
        const int d = idx / 7, n = 49 + idx - (idx / 7) * 7;
        vt[d*PR + n] = 0;
    }
    // bias tile (float bits) into pbs
    const float* bp = biasAll + (size_t)(((b & (NW-1)) << 3) + h) * (NTOK * NTOK);
    for (int idx = tid; idx < NTOK * NTOK; idx += 128) {
        const int i = idx / NTOK, j = idx - i * NTOK;
        pbs[i*PR + j] = __float_as_uint(bp[idx]);
    }
    __syncthreads();

    const int warp = tid >> 5, lane = tid & 31;
    const int group = lane >> 2, tig = lane & 3;
    const int r0 = warp * 16 + group;          // row; also r0+8

    // ---- scores: split-tf32 QK^T ----
    float acc[7][4];
    #pragma unroll
    for (int t = 0; t < 7; t++)
        #pragma unroll
        for (int r = 0; r < 4; r++) acc[t][r] = 0.f;

    #pragma unroll
    for (int kk = 0; kk < 4; kk++) {
        const int c = kk * 8 + tig;
        uint32_t ah[4], al[4];
        ah[0] = qh[r0*QR + c];      al[0] = ql[r0*QR + c];
        ah[1] = qh[(r0+8)*QR + c];  al[1] = ql[(r0+8)*QR + c];
        ah[2] = qh[r0*QR + c + 4];  al[2] = ql[r0*QR + c + 4];
        ah[3] = qh[(r0+8)*QR + c+4];al[3] = ql[(r0+8)*QR + c + 4];
        #pragma unroll
        for (int t = 0; t < 7; t++) {
            const int rk = t * 8 + group;
            uint32_t bh[2] = { kh[rk*QR + c], kh[rk*QR + c + 4] };
            uint32_t bl[2] = { kl[rk*QR + c], kl[rk*QR + c + 4] };
            mma_tf32(acc[t], ah, bh);
            mma_tf32(acc[t], ah, bl);
            mma_tf32(acc[t], al, bh);
        }
    }

    // ---- bias add + masked softmax over register tiles ----
    float mx0 = -1e30f, mx1 = -1e30f;
    #pragma unroll
    for (int t = 0; t < 7; t++) {
        const int c0 = t * 8 + tig * 2;
        if (c0 < NTOK) {
            acc[t][0] += __uint_as_float(pbs[r0*PR + c0]);
            acc[t][2] += __uint_as_float(pbs[(r0+8)*PR + c0]);
            mx0 = fmaxf(mx0, acc[t][0]);
            mx1 = fmaxf(mx1, acc[t][2]);
        }
        if (c0 + 1 < NTOK) {
            acc[t][1] += __uint_as_float(pbs[r0*PR + c0 + 1]);
            acc[t][3] += __uint_as_float(pbs[(r0+8)*PR + c0 + 1]);
            mx0 = fmaxf(mx0, acc[t][1]);
            mx1 = fmaxf(mx1, acc[t][3]);
        }
    }
    mx0 = fmaxf(mx0, __shfl_xor_sync(0xffffffffu, mx0, 1));
    mx0 = fmaxf(mx0, __shfl_xor_sync(0xffffffffu, mx0, 2));
    mx1 = fmaxf(mx1, __shfl_xor_sync(0xffffffffu, mx1, 1));
    mx1 = fmaxf(mx1, __shfl_xor_sync(0xffffffffu, mx1, 2));

    float s0 = 0.f, s1 = 0.f;
    #pragma unroll
    for (int t = 0; t < 7; t++) {
        const int c0 = t * 8 + tig * 2;
        acc[t][0] = (c0     < NTOK) ? __expf(acc[t][0] - mx0) : 0.f;
        acc[t][1] = (c0 + 1 < NTOK) ? __expf(acc[t][1] - mx0) : 0.f;
        acc[t][2] = (c0     < NTOK) ? __expf(acc[t][2] - mx1) : 0.f;
        acc[t][3] = (c0 + 1 < NTOK) ? __expf(acc[t][3] - mx1) : 0.f;
        s0 += acc[t][0] + acc[t][1];
        s1 += acc[t][2] + acc[t][3];
    }
    s0 += __shfl_xor_sync(0xffffffffu, s0, 1);
    s0 += __shfl_xor_sync(0xffffffffu, s0, 2);
    s1 += __shfl_xor_sync(0xffffffffu, s1, 1);
    s1 += __shfl_xor_sync(0xffffffffu, s1, 2);
    const float inv0 = 1.f / s0;
    const float inv1 = 1.f / s1;

    // write normalized P (tf32) back into pbs (same thread owns same coords)
    #pragma unroll
    for (int t = 0; t < 7; t++) {
        const int c0 = t * 8 + tig * 2;
        pbs[r0*PR + c0]         = f2tf(acc[t][0] * inv0);
        pbs[r0*PR + c0 + 1]     = f2tf(acc[t][1] * inv0);
        pbs[(r0+8)*PR + c0]     = f2tf(acc[t][2] * inv1);
        pbs[(r0+8)*PR + c0 + 1] = f2tf(acc[t][3] * inv1);
    }
    __syncwarp();

    // ---- AV: P(64x56) @ V(56x32), tf32 ----
    float av[4][4];
    #pragma unroll
    for (int nt = 0; nt < 4; nt++)
        #pragma unroll
        for (int r = 0; r < 4; r++) av[nt][r] = 0.f;

    #pragma unroll
    for (int kv = 0; kv < 7; kv++) {
        const int c = kv * 8 + tig;
        uint32_t af[4];
        af[0] = pbs[r0*PR + c];
        af[1] = pbs[(r0+8)*PR + c];
        af[2] = pbs[r0*PR + c + 4];
        af[3] = pbs[(r0+8)*PR + c + 4];
        #pragma unroll
        for (int nt = 0; nt < 4; nt++) {
            const int dd = nt * 8 + group;
            uint32_t bf[2] = { vt[dd*PR + c], vt[dd*PR + c + 4] };
            mma_tf32(av[nt], af, bf);
        }
    }

    // ---- store ----
    float* ob = out + (size_t)b * NTOK * DIM + h * DH;
    if (r0 < NTOK) {
        #pragma unroll
        for (int nt = 0; nt < 4; nt++) {
            const int d = nt * 8 + tig * 2;
            *reinterpret_cast<float2*>(&ob[(size_t)r0 * DIM + d]) =
                make_float2(av[nt][0], av[nt][1]);
        }
    }
    if (r0 + 8 < NTOK) {
        #pragma unroll
        for (int nt = 0; nt < 4; nt++) {
            const int d = nt * 8 + tig * 2;
            *reinterpret_cast<float2*>(&ob[(size_t)(r0 + 8) * DIM + d]) =
                make_float2(av[nt][2], av[nt][3]);
        }
    }
}

// ---------------------------------------------------------------------------
// Launch
// ---------------------------------------------------------------------------
extern "C" void kernel_launch(void* const* d_in, const int* in_sizes, int n_in,
                              void* d_out, int out_size) {
    const float* x         = (const float*)d_in[0];
    const float* mask      = (const float*)d_in[1];
    const float* qkv_w     = (const float*)d_in[2];
    const float* qkv_b     = (const float*)d_in[3];
    const float* proj_w    = (const float*)d_in[4];
    const float* proj_b    = (const float*)d_in[5];
    const float* rpb_table = (const float*)d_in[6];
    const int*   rel_index = (const int*)d_in[7];
    float* out = (float*)d_out;

    float* qkv;      cudaGetSymbolAddress((void**)&qkv, g_qkv);
    float* attn_out; cudaGetSymbolAddress((void**)&attn_out, g_attn_out);
    float* biasAll;  cudaGetSymbolAddress((void**)&biasAll, g_bias);

    cudaFuncSetAttribute(gemm_tf32_nt_bias,
                         cudaFuncAttributeMaxDynamicSharedMemorySize, GEMM_SMEM_BYTES);
    cudaFuncSetAttribute(attn_mma,
                         cudaFuncAttributeMaxDynamicSharedMemorySize, ATTN_SMEM_BYTES);

    // 0) precombine mask + rpb
    bias_pre<<<NW * H, 256>>>(mask, rpb_table, rel_index, biasAll);
    // 1) QKV projection
    {
        dim3 grid(QKV_COLS / GBN, MROWS / GBM);
        gemm_tf32_nt_bias<<<grid, 256, GEMM_SMEM_BYTES>>>(
            x, qkv_w, qkv_b, qkv, MROWS, QKV_COLS, DIM);
    }
    // 2) attention
    attn_mma<<<BWIN * H, 128, ATTN_SMEM_BYTES>>>(qkv, biasAll, attn_out);
    // 3) output projection
    {
        dim3 grid(DIM / GBN, MROWS / GBM);
        gemm_tf32_nt_bias<<<grid, 256, GEMM_SMEM_BYTES>>>(
            attn_out, proj_w, proj_b, out, MROWS, DIM, DIM);
    }
}

// round 4
// speedup vs baseline: 3.9540x; 1.3504x over previous
#include <cuda_runtime.h>
#include <cuda_bf16.h>
#include <cstdint>

// Problem constants
#define NTOK 49
#define DIM 256
#define H 8
#define DH 32
#define BWIN 2048
#define NW 64
#define QKV_COLS 768
#define MROWS (BWIN * NTOK)  // 100352

// Scratch (allocation-free rule: device globals)
__device__ float g_qkv[(size_t)MROWS * QKV_COLS];
__device__ float g_attn_out[(size_t)MROWS * DIM];
__device__ float g_bias[(size_t)NW * H * NTOK * NTOK];  // mask + rpb precombined

// ---------------------------------------------------------------------------
// Helpers
// ---------------------------------------------------------------------------
__device__ __forceinline__ void cp_async16(void* s, const void* g) {
    uint32_t sa = (uint32_t)__cvta_generic_to_shared(s);
    asm volatile("cp.async.cg.shared.global [%0], [%1], 16;" :: "r"(sa), "l"(g));
}
__device__ __forceinline__ void cp_commit() {
    asm volatile("cp.async.commit_group;");
}
template<int Nw> __device__ __forceinline__ void cp_wait() {
    asm volatile("cp.async.wait_group %0;" :: "n"(Nw));
}
__device__ __forceinline__ uint32_t f2tf(float x) {
    uint32_t r;
    asm("cvt.rna.tf32.f32 %0, %1;" : "=r"(r) : "f"(x));
    return r;
}
__device__ __forceinline__ void mma_tf32(float c[4], const uint32_t a[4], const uint32_t b[2]) {
    asm volatile(
        "mma.sync.aligned.m16n8k8.row.col.f32.tf32.tf32.f32 "
        "{%0,%1,%2,%3}, {%4,%5,%6,%7}, {%8,%9}, {%0,%1,%2,%3};"
        : "+f"(c[0]), "+f"(c[1]), "+f"(c[2]), "+f"(c[3])
        : "r"(a[0]), "r"(a[1]), "r"(a[2]), "r"(a[3]), "r"(b[0]), "r"(b[1]));
}

// ---------------------------------------------------------------------------
// Bias precompute: g_bias[w][h][i][j] = mask[w][i][j] + rpb[rel_index[i][j]][h]
// ---------------------------------------------------------------------------
__global__ __launch_bounds__(256) void bias_pre(
    const float* __restrict__ mask, const float* __restrict__ rpb,
    const int* __restrict__ ridx, float* __restrict__ biasAll)
{
    const int wh = blockIdx.x;
    const int w = wh >> 3, h = wh & 7;
    const float* m = mask + (size_t)w * (NTOK * NTOK);
    float* o = biasAll + (size_t)wh * (NTOK * NTOK);
    for (int ij = threadIdx.x; ij < NTOK * NTOK; ij += 256)
        o[ij] = m[ij] + rpb[ridx[ij] * H + h];
}

// ---------------------------------------------------------------------------
// TF32 tensor-core NT GEMM + bias. Block 128x128, BK=32, 8 warps (2m x 4n).
// Warp tile 64x32. cp.async double-buffered, f32 in smem, cvt at use.
// Requires M%128==0, N%128==0, K%32==0.
// ---------------------------------------------------------------------------
#define GBM 128
#define GBN 128
#define GSTR 36
#define GEMM_SMEM_BYTES ((2 * GBM * GSTR + 2 * GBN * GSTR) * 4)  // 73728

__global__ __launch_bounds__(256, 2) void gemm_tf32_nt_bias(
    const float* __restrict__ A, const float* __restrict__ W,
    const float* __restrict__ bias, float* __restrict__ C,
    int M, int N, int K)
{
    extern __shared__ float smem[];
    float* As0 = smem;                       // [2][128*36]
    float* Bs0 = smem + 2 * GBM * GSTR;      // [2][128*36]

    const int tid  = threadIdx.x;
    const int lane = tid & 31;
    const int warp = tid >> 5;
    const int wm = warp >> 2;        // 0..1  (64 rows each)
    const int wn = warp & 3;         // 0..3  (32 cols each)
    const int group = lane >> 2;     // 0..7
    const int tig   = lane & 3;      // 0..3

    const int bm = blockIdx.y * GBM;
    const int bn = blockIdx.x * GBN;

    const int ra = tid >> 3;          // 0..31
    const int ca = (tid & 7) << 2;    // 0,4,...,28

    const float* Ag = A + (size_t)(bm + ra) * K + ca;
    const float* Wg = W + (size_t)(bn + ra) * K + ca;

    float acc[4][4][4];
    #pragma unroll
    for (int mt = 0; mt < 4; mt++)
        #pragma unroll
        for (int nt = 0; nt < 4; nt++)
            #pragma unroll
            for (int r = 0; r < 4; r++) acc[mt][nt][r] = 0.f;

    const int NS = K >> 5;

    // prefetch stage 0
    #pragma unroll
    for (int p = 0; p < 4; p++)
        cp_async16(&As0[(ra + p*32)*GSTR + ca], Ag + (size_t)p*32*K);
    #pragma unroll
    for (int p = 0; p < 4; p++)
        cp_async16(&Bs0[(ra + p*32)*GSTR + ca], Wg + (size_t)p*32*K);
    cp_commit();

    for (int s = 0; s < NS; s++) {
        if (s + 1 < NS) {
            const int nb = (s + 1) & 1;
            const int k0 = (s + 1) << 5;
            float* as = As0 + nb * GBM * GSTR;
            float* bs = Bs0 + nb * GBN * GSTR;
            #pragma unroll
            for (int p = 0; p < 4; p++)
                cp_async16(&as[(ra + p*32)*GSTR + ca], Ag + k0 + (size_t)p*32*K);
            #pragma unroll
            for (int p = 0; p < 4; p++)
                cp_async16(&bs[(ra + p*32)*GSTR + ca], Wg + k0 + (size_t)p*32*K);
            cp_commit();
            cp_wait<1>();
        } else {
            cp_wait<0>();
        }
        __syncthreads();

        const float* as = As0 + (s & 1) * GBM * GSTR;
        const float* bs = Bs0 + (s & 1) * GBN * GSTR;

        #pragma unroll
        for (int kk = 0; kk < 4; kk++) {
            const int k8 = kk * 8;
            uint32_t af[4][4], bf[4][2];
            #pragma unroll
            for (int mt = 0; mt < 4; mt++) {
                const float* p = as + (wm*64 + mt*16 + group) * GSTR + k8;
                af[mt][0] = f2tf(p[tig]);
                af[mt][1] = f2tf(p[8*GSTR + tig]);
                af[mt][2] = f2tf(p[tig + 4]);
                af[mt][3] = f2tf(p[8*GSTR + tig + 4]);
            }
            #pragma unroll
            for (int nt = 0; nt < 4; nt++) {
                const float* p = bs + (wn*32 + nt*8 + group) * GSTR + k8;
                bf[nt][0] = f2tf(p[tig]);
                bf[nt][1] = f2tf(p[tig + 4]);
            }
            #pragma unroll
            for (int mt = 0; mt < 4; mt++)
                #pragma unroll
                for (int nt = 0; nt < 4; nt++)
                    mma_tf32(acc[mt][nt], af[mt], bf[nt]);
        }
        __syncthreads();
    }

    #pragma unroll
    for (int mt = 0; mt < 4; mt++) {
        const int r = bm + wm*64 + mt*16 + group;
        #pragma unroll
        for (int nt = 0; nt < 4; nt++) {
            const int c = bn + wn*32 + nt*8 + tig*2;
            const float bx = bias[c], by = bias[c + 1];
            float2 v0 = make_float2(acc[mt][nt][0] + bx, acc[mt][nt][1] + by);
            float2 v1 = make_float2(acc[mt][nt][2] + bx, acc[mt][nt][3] + by);
            *reinterpret_cast<float2*>(&C[(size_t)r * N + c]) = v0;
            *reinterpret_cast<float2*>(&C[(size_t)(r + 8) * N + c]) = v1;
        }
    }
}

// ---------------------------------------------------------------------------
// Tensor-core attention: one block per (window b, head h), 4 warps.
// QK^T split-tf32, bias from gmem, register softmax, P overlaid on kh/kl.
// ---------------------------------------------------------------------------
#define QR 36   // stride for q/k tf32 tiles
#define PR 60   // stride for vt / P tiles
// smem words: qh[64*36] ql[64*36] kh[56*36] kl[56*36] vt[32*60]; P overlays kh/kl
#define ATTN_SMEM_WORDS (2*64*QR + 2*56*QR + 32*PR)
#define ATTN_SMEM_BYTES (ATTN_SMEM_WORDS * 4)   // 42240

__global__ __launch_bounds__(128) void attn_mma(
    const float* __restrict__ qkv,
    const float* __restrict__ biasAll,
    float* __restrict__ out)
{
    extern __shared__ uint32_t sm[];
    uint32_t* qh  = sm;
    uint32_t* ql  = qh + 64*QR;
    uint32_t* kh  = ql + 64*QR;
    uint32_t* kl  = kh + 56*QR;
    uint32_t* vt  = kl + 56*QR;      // [32][60] transposed V (tf32)
    uint32_t* Ps  = kh;              // P overlay [64][60], after sync

    const int b = blockIdx.x >> 3;
    const int h = blockIdx.x & 7;
    const int tid = threadIdx.x;
    const float scale = 0.17677669529663687f;

    // ---- load q,k,v; split-tf32 for q,k; tf32 transposed v ----
    const float* base = qkv + (size_t)b * NTOK * QKV_COLS + h * DH;
    for (int idx = tid; idx < NTOK * 8; idx += 128) {
        const int n = idx >> 3, d4 = (idx & 7) << 2;
        const float* r = base + (size_t)n * QKV_COLS + d4;
        float4 q = *reinterpret_cast<const float4*>(r);
        float4 k = *reinterpret_cast<const float4*>(r + DIM);
        float4 v = *reinterpret_cast<const float4*>(r + 2 * DIM);
        q.x *= scale; q.y *= scale; q.z *= scale; q.w *= scale;
        const float* qp = &q.x; const float* kp = &k.x; const float* vp = &v.x;
        #pragma unroll
        for (int i = 0; i < 4; i++) {
            const int c = d4 + i;
            uint32_t hi = f2tf(qp[i]);
            qh[n*QR + c] = hi;
            ql[n*QR + c] = f2tf(qp[i] - __uint_as_float(hi));
            hi = f2tf(kp[i]);
            kh[n*QR + c] = hi;
            kl[n*QR + c] = f2tf(kp[i] - __uint_as_float(hi));
            vt[c*PR + n] = f2tf(vp[i]);
        }
    }
    // zero pads
    for (int idx = tid; idx < 15 * 32; idx += 128) {
        const int r = 49 + (idx >> 5), c = idx & 31;
        qh[r*QR + c] = 0; ql[r*QR + c] = 0;
    }
    for (int idx = tid; idx < 7 * 32; idx += 128) {
        const int r = 49 + (idx >> 5), c = idx & 31;
        kh[r*QR + c] = 0; kl[r*QR + c] = 0;
    }
    for (int idx = tid; idx < 32 * 7; idx += 128) {
        const int d = idx / 7, n = 49 + idx - (idx / 7) * 7;
        vt[d*PR + n] = 0;
    }
    __syncthreads();

    const int warp = tid >> 5, lane = tid & 31;
    const int group = lane >> 2, tig = lane & 3;
    const int r0 = warp * 16 + group;          // rows r0 and r0+8

    // ---- scores: split-tf32 QK^T ----
    float acc[7][4];
    #pragma unroll
    for (int t = 0; t < 7; t++)
        #pragma unroll
        for (int r = 0; r < 4; r++) acc[t][r] = 0.f;

    #pragma unroll
    for (int kk = 0; kk < 4; kk++) {
        const int c = kk * 8 + tig;
        uint32_t ah[4], al[4];
        ah[0] = qh[r0*QR + c];       al[0] = ql[r0*QR + c];
        ah[1] = qh[(r0+8)*QR + c];   al[1] = ql[(r0+8)*QR + c];
        ah[2] = qh[r0*QR + c + 4];   al[2] = ql[r0*QR + c + 4];
        ah[3] = qh[(r0+8)*QR + c+4]; al[3] = ql[(r0+8)*QR + c + 4];
        #pragma unroll
        for (int t = 0; t < 7; t++) {
            const int rk = t * 8 + group;
            uint32_t bh[2] = { kh[rk*QR + c], kh[rk*QR + c + 4] };
            uint32_t bl[2] = { kl[rk*QR + c], kl[rk*QR + c + 4] };
            mma_tf32(acc[t], ah, bh);
            mma_tf32(acc[t], ah, bl);
            mma_tf32(acc[t], al, bh);
        }
    }
    __syncthreads();   // all QK reads of kh/kl done; kh/kl now reusable as P

    // ---- bias (direct from gmem/L2) + masked softmax in registers ----
    const float* bp = biasAll + (size_t)(((b & (NW-1)) << 3) + h) * (NTOK * NTOK);
    const bool row0 = (r0 < NTOK);
    const bool row1 = (r0 + 8 < NTOK);
    float mx0 = -1e30f, mx1 = -1e30f;
    #pragma unroll
    for (int t = 0; t < 7; t++) {
        const int c0 = t * 8 + tig * 2;
        if (c0 < NTOK) {
            if (row0) { acc[t][0] += __ldg(&bp[r0*NTOK + c0]);      mx0 = fmaxf(mx0, acc[t][0]); }
            if (row1) { acc[t][2] += __ldg(&bp[(r0+8)*NTOK + c0]);  mx1 = fmaxf(mx1, acc[t][2]); }
        }
        if (c0 + 1 < NTOK) {
            if (row0) { acc[t][1] += __ldg(&bp[r0*NTOK + c0 + 1]);      mx0 = fmaxf(mx0, acc[t][1]); }
            if (row1) { acc[t][3] += __ldg(&bp[(r0+8)*NTOK + c0 + 1]);  mx1 = fmaxf(mx1, acc[t][3]); }
        }
    }
    mx0 = fmaxf(mx0, __shfl_xor_sync(0xffffffffu, mx0, 1));
    mx0 = fmaxf(mx0, __shfl_xor_sync(0xffffffffu, mx0, 2));
    mx1 = fmaxf(mx1, __shfl_xor_sync(0xffffffffu, mx1, 1));
    mx1 = fmaxf(mx1, __shfl_xor_sync(0xffffffffu, mx1, 2));
    // padded rows: acc all zero, no bias -> mx = 0, benign

    if (mx0 < -1e29f) mx0 = 0.f;
    if (mx1 < -1e29f) mx1 = 0.f;

    float s0 = 0.f, s1 = 0.f;
    #pragma unroll
    for (int t = 0; t < 7; t++) {
        const int c0 = t * 8 + tig * 2;
        acc[t][0] = (c0     < NTOK) ? __expf(acc[t][0] - mx0) : 0.f;
        acc[t][1] = (c0 + 1 < NTOK) ? __expf(acc[t][1] - mx0) : 0.f;
        acc[t][2] = (c0     < NTOK) ? __expf(acc[t][2] - mx1) : 0.f;
        acc[t][3] = (c0 + 1 < NTOK) ? __expf(acc[t][3] - mx1) : 0.f;
        s0 += acc[t][0] + acc[t][1];
        s1 += acc[t][2] + acc[t][3];
    }
    s0 += __shfl_xor_sync(0xffffffffu, s0, 1);
    s0 += __shfl_xor_sync(0xffffffffu, s0, 2);
    s1 += __shfl_xor_sync(0xffffffffu, s1, 1);
    s1 += __shfl_xor_sync(0xffffffffu, s1, 2);
    const float inv0 = 1.f / s0;
    const float inv1 = 1.f / s1;

    // write normalized P (tf32) into overlay; AV reads only this warp's rows
    #pragma unroll
    for (int t = 0; t < 7; t++) {
        const int c0 = t * 8 + tig * 2;
        Ps[r0*PR + c0]         = f2tf(acc[t][0] * inv0);
        Ps[r0*PR + c0 + 1]     = f2tf(acc[t][1] * inv0);
        Ps[(r0+8)*PR + c0]     = f2tf(acc[t][2] * inv1);
        Ps[(r0+8)*PR + c0 + 1] = f2tf(acc[t][3] * inv1);
    }
    __syncwarp();

    // ---- AV: P(64x56) @ V(56x32), tf32 ----
    float av[4][4];
    #pragma unroll
    for (int nt = 0; nt < 4; nt++)
        #pragma unroll
        for (int r = 0; r < 4; r++) av[nt][r] = 0.f;

    #pragma unroll
    for (int kv = 0; kv < 7; kv++) {
        const int c = kv * 8 + tig;
        uint32_t af[4];
        af[0] = Ps[r0*PR + c];
        af[1] = Ps[(r0+8)*PR + c];
        af[2] = Ps[r0*PR + c + 4];
        af[3] = Ps[(r0+8)*PR + c + 4];
        #pragma unroll
        for (int nt = 0; nt < 4; nt++) {
            const int dd = nt * 8 + group;
            uint32_t bf[2] = { vt[dd*PR + c], vt[dd*PR + c + 4] };
            mma_tf32(av[nt], af, bf);
        }
    }

    // ---- store ----
    float* ob = out + (size_t)b * NTOK * DIM + h * DH;
    if (row0) {
        #pragma unroll
        for (int nt = 0; nt < 4; nt++) {
            const int d = nt * 8 + tig * 2;
            *reinterpret_cast<float2*>(&ob[(size_t)r0 * DIM + d]) =
                make_float2(av[nt][0], av[nt][1]);
        }
    }
    if (row1) {
        #pragma unroll
        for (int nt = 0; nt < 4; nt++) {
            const int d = nt * 8 + tig * 2;
            *reinterpret_cast<float2*>(&ob[(size_t)(r0 + 8) * DIM + d]) =
                make_float2(av[nt][2], av[nt][3]);
        }
    }
}

// ---------------------------------------------------------------------------
// Launch
// ---------------------------------------------------------------------------
extern "C" void kernel_launch(void* const* d_in, const int* in_sizes, int n_in,
                              void* d_out, int out_size) {
    const float* x         = (const float*)d_in[0];
    const float* mask      = (const float*)d_in[1];
    const float* qkv_w     = (const float*)d_in[2];
    const float* qkv_b     = (const float*)d_in[3];
    const float* proj_w    = (const float*)d_in[4];
    const float* proj_b    = (const float*)d_in[5];
    const float* rpb_table = (const float*)d_in[6];
    const int*   rel_index = (const int*)d_in[7];
    float* out = (float*)d_out;

    float* qkv;      cudaGetSymbolAddress((void**)&qkv, g_qkv);
    float* attn_out; cudaGetSymbolAddress((void**)&attn_out, g_attn_out);
    float* biasAll;  cudaGetSymbolAddress((void**)&biasAll, g_bias);

    cudaFuncSetAttribute(gemm_tf32_nt_bias,
                         cudaFuncAttributeMaxDynamicSharedMemorySize, GEMM_SMEM_BYTES);
    cudaFuncSetAttribute(attn_mma,
                         cudaFuncAttributeMaxDynamicSharedMemorySize, ATTN_SMEM_BYTES);

    // 0) precombine mask + rpb
    bias_pre<<<NW * H, 256>>>(mask, rpb_table, rel_index, biasAll);
    // 1) QKV projection: [100352,256] x [768,256]^T
    {
        dim3 grid(QKV_COLS / GBN, MROWS / GBM);
        gemm_tf32_nt_bias<<<grid, 256, GEMM_SMEM_BYTES>>>(
            x, qkv_w, qkv_b, qkv, MROWS, QKV_COLS, DIM);
    }
    // 2) attention
    attn_mma<<<BWIN * H, 128, ATTN_SMEM_BYTES>>>(qkv, biasAll, attn_out);
    // 3) output projection: [100352,256] x [256,256]^T
    {
        dim3 grid(DIM / GBN, MROWS / GBM);
        gemm_tf32_nt_bias<<<grid, 256, GEMM_SMEM_BYTES>>>(
            attn_out, proj_w, proj_b, out, MROWS, DIM, DIM);
    }
}

// round 6
// speedup vs baseline: 5.3177x; 1.3449x over previous
#include <cuda_runtime.h>
#include <cuda_fp16.h>
#include <cstdint>

// Problem constants
#define NTOK 49
#define DIM 256
#define H 8
#define DH 32
#define BWIN 2048
#define NW 64
#define QKV_COLS 768
#define MROWS (BWIN * NTOK)  // 100352

// Scratch (allocation-free rule: device globals)
__device__ float  g_qkv[(size_t)MROWS * QKV_COLS];
__device__ __half g_xh[(size_t)MROWS * DIM];
__device__ __half g_attn_outh[(size_t)MROWS * DIM];
__device__ __half g_wh[QKV_COLS * DIM];
__device__ __half g_pwh[DIM * DIM];
__device__ float  g_bias[(size_t)NW * H * NTOK * NTOK];

// ---------------------------------------------------------------------------
// Helpers
// ---------------------------------------------------------------------------
__device__ __forceinline__ void cp_async16(uint32_t s, const void* g) {
    asm volatile("cp.async.cg.shared.global [%0], [%1], 16;" :: "r"(s), "l"(g));
}
__device__ __forceinline__ void cp_commit() {
    asm volatile("cp.async.commit_group;");
}
template<int Nw> __device__ __forceinline__ void cp_wait() {
    asm volatile("cp.async.wait_group %0;" :: "n"(Nw));
}
__device__ __forceinline__ uint32_t f2tf(float x) {
    uint32_t r;
    asm("cvt.rna.tf32.f32 %0, %1;" : "=r"(r) : "f"(x));
    return r;
}
__device__ __forceinline__ void mma_tf32(float c[4], const uint32_t a[4], const uint32_t b[2]) {
    asm volatile(
        "mma.sync.aligned.m16n8k8.row.col.f32.tf32.tf32.f32 "
        "{%0,%1,%2,%3}, {%4,%5,%6,%7}, {%8,%9}, {%0,%1,%2,%3};"
        : "+f"(c[0]), "+f"(c[1]), "+f"(c[2]), "+f"(c[3])
        : "r"(a[0]), "r"(a[1]), "r"(a[2]), "r"(a[3]), "r"(b[0]), "r"(b[1]));
}
__device__ __forceinline__ void mma_f16(float c[4], const uint32_t a[4], const uint32_t b[2]) {
    asm volatile(
        "mma.sync.aligned.m16n8k16.row.col.f32.f16.f16.f32 "
        "{%0,%1,%2,%3}, {%4,%5,%6,%7}, {%8,%9}, {%0,%1,%2,%3};"
        : "+f"(c[0]), "+f"(c[1]), "+f"(c[2]), "+f"(c[3])
        : "r"(a[0]), "r"(a[1]), "r"(a[2]), "r"(a[3]), "r"(b[0]), "r"(b[1]));
}
__device__ __forceinline__ void ldm_x4(uint32_t& r0, uint32_t& r1, uint32_t& r2, uint32_t& r3,
                                       uint32_t addr) {
    asm volatile("ldmatrix.sync.aligned.m8n8.x4.shared.b16 {%0,%1,%2,%3}, [%4];"
                 : "=r"(r0), "=r"(r1), "=r"(r2), "=r"(r3) : "r"(addr));
}
__device__ __forceinline__ uint32_t smem_u32(const void* p) {
    uint32_t a;
    asm("{ .reg .u64 t; cvta.to.shared.u64 t, %1; cvt.u32.u64 %0, t; }" : "=r"(a) : "l"(p));
    return a;
}

// ---------------------------------------------------------------------------
// fp32 -> fp16 conversion (vectorized)
// ---------------------------------------------------------------------------
__global__ __launch_bounds__(256) void cvt_f16(
    const float4* __restrict__ src, uint2* __restrict__ dst, int n4)
{
    int i = blockIdx.x * blockDim.x + threadIdx.x;
    if (i < n4) {
        float4 v = src[i];
        __half2 a = __floats2half2_rn(v.x, v.y);
        __half2 b = __floats2half2_rn(v.z, v.w);
        dst[i] = make_uint2(*reinterpret_cast<uint32_t*>(&a),
                            *reinterpret_cast<uint32_t*>(&b));
    }
}

// ---------------------------------------------------------------------------
// Bias precompute
// ---------------------------------------------------------------------------
__global__ __launch_bounds__(256) void bias_pre(
    const float* __restrict__ mask, const float* __restrict__ rpb,
    const int* __restrict__ ridx, float* __restrict__ biasAll)
{
    const int wh = blockIdx.x;
    const int w = wh >> 3, h = wh & 7;
    const float* m = mask + (size_t)w * (NTOK * NTOK);
    float* o = biasAll + (size_t)wh * (NTOK * NTOK);
    for (int ij = threadIdx.x; ij < NTOK * NTOK; ij += 256)
        o[ij] = m[ij] + rpb[ridx[ij] * H + h];
}

// ---------------------------------------------------------------------------
// FP16 tensor-core NT GEMM + bias: C[m][n] = sum_k A[m][k]*W[n][k] + bias[n]
// Block 128x128, BK=32, 8 warps (2m x 4n), warp tile 64x32.
// smem: half tiles, row=64B, chunk swizzle kc ^ ((row>>1)&3). ldmatrix frags.
// Requires M%128==0, N%128==0, K%32==0.
// ---------------------------------------------------------------------------
__global__ __launch_bounds__(256, 2) void gemm_f16_nt_bias(
    const __half* __restrict__ A, const __half* __restrict__ W,
    const float* __restrict__ bias, float* __restrict__ C,
    int M, int N, int K)
{
    __shared__ __align__(16) char smem[2 * 16384];   // [buf][A 8KB | B 8KB]

    const int tid  = threadIdx.x;
    const int lane = tid & 31;
    const int warp = tid >> 5;
    const int wm = warp >> 2;        // 0..1 -> 64 rows
    const int wn = warp & 3;         // 0..3 -> 32 cols
    const int bm = blockIdx.y * 128;
    const int bn = blockIdx.x * 128;

    const uint32_t sb = smem_u32(smem);

    // fill mapping: thread handles A chunks {tid, tid+256} and B chunks same.
    // chunk c: row = c>>2 (0..127), kc = c&3 (16B each)
    const int r0f = tid >> 2, kcf = tid & 3;
    const int r1f = r0f + 64;
    const uint32_t dA0 = (uint32_t)(r0f * 64 + ((kcf ^ ((r0f >> 1) & 3)) << 4));
    const uint32_t dA1 = (uint32_t)(r1f * 64 + ((kcf ^ ((r1f >> 1) & 3)) << 4));
    const __half* gA0 = A + (size_t)(bm + r0f) * K + kcf * 8;
    const __half* gA1 = A + (size_t)(bm + r1f) * K + kcf * 8;
    const __half* gB0 = W + (size_t)(bn + r0f) * K + kcf * 8;
    const __half* gB1 = W + (size_t)(bn + r1f) * K + kcf * 8;

    float acc[4][4][4];
    #pragma unroll
    for (int mt = 0; mt < 4; mt++)
        #pragma unroll
        for (int nt = 0; nt < 4; nt++)
            #pragma unroll
            for (int r = 0; r < 4; r++) acc[mt][nt][r] = 0.f;

    const int NS = K >> 5;

    // prefetch stage 0
    {
        const uint32_t ab = sb, bb = sb + 8192;
        cp_async16(ab + dA0, gA0);
        cp_async16(ab + dA1, gA1);
        cp_async16(bb + dA0, gB0);
        cp_async16(bb + dA1, gB1);
        cp_commit();
    }

    const int mat  = lane >> 3;      // 0..3
    const int lrow = lane & 7;

    for (int s = 0; s < NS; s++) {
        if (s + 1 < NS) {
            const int k0 = (s + 1) << 5;
            const uint32_t base = sb + ((s + 1) & 1) * 16384;
            cp_async16(base + dA0, gA0 + k0);
            cp_async16(base + dA1, gA1 + k0);
            cp_async16(base + 8192 + dA0, gB0 + k0);
            cp_async16(base + 8192 + dA1, gB1 + k0);
            cp_commit();
            cp_wait<1>();
        } else {
            cp_wait<0>();
        }
        __syncthreads();

        const uint32_t sA = sb + (s & 1) * 16384;
        const uint32_t sB = sA + 8192;

        #pragma unroll
        for (int ks = 0; ks < 2; ks++) {
            uint32_t af[4][4], bf[4][2];
            #pragma unroll
            for (int mt = 0; mt < 4; mt++) {
                const int arow = wm * 64 + mt * 16 + ((mat & 1) << 3) + lrow;
                const int akc  = (ks << 1) + (mat >> 1);
                const uint32_t aaddr = sA + (uint32_t)(arow * 64 + ((akc ^ ((arow >> 1) & 3)) << 4));
                ldm_x4(af[mt][0], af[mt][1], af[mt][2], af[mt][3], aaddr);
            }
            #pragma unroll
            for (int nt2 = 0; nt2 < 2; nt2++) {
                const int brow = wn * 32 + (nt2 << 4) + ((mat >> 1) << 3) + lrow;
                const int bkc  = (ks << 1) + (mat & 1);
                const uint32_t baddr = sB + (uint32_t)(brow * 64 + ((bkc ^ ((brow >> 1) & 3)) << 4));
                ldm_x4(bf[nt2*2][0], bf[nt2*2][1], bf[nt2*2+1][0], bf[nt2*2+1][1], baddr);
            }
            #pragma unroll
            for (int mt = 0; mt < 4; mt++)
                #pragma unroll
                for (int nt = 0; nt < 4; nt++)
                    mma_f16(acc[mt][nt], af[mt], bf[nt]);
        }
        __syncthreads();
    }

    // epilogue
    const int group = lane >> 2, tig = lane & 3;
    #pragma unroll
    for (int mt = 0; mt < 4; mt++) {
        const int r = bm + wm * 64 + mt * 16 + group;
        #pragma unroll
        for (int nt = 0; nt < 4; nt++) {
            const int c = bn + wn * 32 + nt * 8 + tig * 2;
            const float bx = bias[c], by = bias[c + 1];
            float2 v0 = make_float2(acc[mt][nt][0] + bx, acc[mt][nt][1] + by);
            float2 v1 = make_float2(acc[mt][nt][2] + bx, acc[mt][nt][3] + by);
            *reinterpret_cast<float2*>(&C[(size_t)r * N + c]) = v0;
            *reinterpret_cast<float2*>(&C[(size_t)(r + 8) * N + c]) = v1;
        }
    }
}

// ---------------------------------------------------------------------------
// Tensor-core attention (R4-proven), fp16 output stores.
// ---------------------------------------------------------------------------
#define QR 36
#define PR 60
#define ATTN_SMEM_WORDS (2*64*QR + 2*56*QR + 32*PR)
#define ATTN_SMEM_BYTES (ATTN_SMEM_WORDS * 4)   // 42240

__global__ __launch_bounds__(128) void attn_mma(
    const float* __restrict__ qkv,
    const float* __restrict__ biasAll,
    __half* __restrict__ out)
{
    extern __shared__ uint32_t smw[];
    uint32_t* qh  = smw;
    uint32_t* ql  = qh + 64*QR;
    uint32_t* kh  = ql + 64*QR;
    uint32_t* kl  = kh + 56*QR;
    uint32_t* vt  = kl + 56*QR;
    uint32_t* Ps  = kh;              // P overlay after sync

    const int b = blockIdx.x >> 3;
    const int h = blockIdx.x & 7;
    const int tid = threadIdx.x;
    const float scale = 0.17677669529663687f;

    const float* base = qkv + (size_t)b * NTOK * QKV_COLS + h * DH;
    for (int idx = tid; idx < NTOK * 8; idx += 128) {
        const int n = idx >> 3, d4 = (idx & 7) << 2;
        const float* r = base + (size_t)n * QKV_COLS + d4;
        float4 q = *reinterpret_cast<const float4*>(r);
        float4 k = *reinterpret_cast<const float4*>(r + DIM);
        float4 v = *reinterpret_cast<const float4*>(r + 2 * DIM);
        q.x *= scale; q.y *= scale; q.z *= scale; q.w *= scale;
        const float* qp = &q.x; const float* kp = &k.x; const float* vp = &v.x;
        #pragma unroll
        for (int i = 0; i < 4; i++) {
            const int c = d4 + i;
            uint32_t hi = f2tf(qp[i]);
            qh[n*QR + c] = hi;
            ql[n*QR + c] = f2tf(qp[i] - __uint_as_float(hi));
            hi = f2tf(kp[i]);
            kh[n*QR + c] = hi;
            kl[n*QR + c] = f2tf(kp[i] - __uint_as_float(hi));
            vt[c*PR + n] = f2tf(vp[i]);
        }
    }
    for (int idx = tid; idx < 15 * 32; idx += 128) {
        const int r = 49 + (idx >> 5), c = idx & 31;
        qh[r*QR + c] = 0; ql[r*QR + c] = 0;
    }
    for (int idx = tid; idx < 7 * 32; idx += 128) {
        const int r = 49 + (idx >> 5), c = idx & 31;
        kh[r*QR + c] = 0; kl[r*QR + c] = 0;
    }
    for (int idx = tid; idx < 32 * 7; idx += 128) {
        const int d = idx / 7, n = 49 + idx - (idx / 7) * 7;
        vt[d*PR + n] = 0;
    }
    __syncthreads();

    const int warp = tid >> 5, lane = tid & 31;
    const int group = lane >> 2, tig = lane & 3;
    const int r0 = warp * 16 + group;

    float acc[7][4];
    #pragma unroll
    for (int t = 0; t < 7; t++)
        #pragma unroll
        for (int r = 0; r < 4; r++) acc[t][r] = 0.f;

    #pragma unroll
    for (int kk = 0; kk < 4; kk++) {
        const int c = kk * 8 + tig;
        uint32_t ah[4], al[4];
        ah[0] = qh[r0*QR + c];       al[0] = ql[r0*QR + c];
        ah[1] = qh[(r0+8)*QR + c];   al[1] = ql[(r0+8)*QR + c];
        ah[2] = qh[r0*QR + c + 4];   al[2] = ql[r0*QR + c + 4];
        ah[3] = qh[(r0+8)*QR + c+4]; al[3] = ql[(r0+8)*QR + c + 4];
        #pragma unroll
        for (int t = 0; t < 7; t++) {
            const int rk = t * 8 + group;
            uint32_t bh[2] = { kh[rk*QR + c], kh[rk*QR + c + 4] };
            uint32_t bl[2] = { kl[rk*QR + c], kl[rk*QR + c + 4] };
            mma_tf32(acc[t], ah, bh);
            mma_tf32(acc[t], ah, bl);
            mma_tf32(acc[t], al, bh);
        }
    }
    __syncthreads();

    const float* bp = biasAll + (size_t)(((b & (NW-1)) << 3) + h) * (NTOK * NTOK);
    const bool row0 = (r0 < NTOK);
    const bool row1 = (r0 + 8 < NTOK);
    float mx0 = -1e30f, mx1 = -1e30f;
    #pragma unroll
    for (int t = 0; t < 7; t++) {
        const int c0 = t * 8 + tig * 2;
        if (c0 < NTOK) {
            if (row0) { acc[t][0] += __ldg(&bp[r0*NTOK + c0]);      mx0 = fmaxf(mx0, acc[t][0]); }
            if (row1) { acc[t][2] += __ldg(&bp[(r0+8)*NTOK + c0]);  mx1 = fmaxf(mx1, acc[t][2]); }
        }
        if (c0 + 1 < NTOK) {
            if (row0) { acc[t][1] += __ldg(&bp[r0*NTOK + c0 + 1]);      mx0 = fmaxf(mx0, acc[t][1]); }
            if (row1) { acc[t][3] += __ldg(&bp[(r0+8)*NTOK + c0 + 1]);  mx1 = fmaxf(mx1, acc[t][3]); }
        }
    }
    mx0 = fmaxf(mx0, __shfl_xor_sync(0xffffffffu, mx0, 1));
    mx0 = fmaxf(mx0, __shfl_xor_sync(0xffffffffu, mx0, 2));
    mx1 = fmaxf(mx1, __shfl_xor_sync(0xffffffffu, mx1, 1));
    mx1 = fmaxf(mx1, __shfl_xor_sync(0xffffffffu, mx1, 2));
    if (mx0 < -1e29f) mx0 = 0.f;
    if (mx1 < -1e29f) mx1 = 0.f;

    float s0 = 0.f, s1 = 0.f;
    #pragma unroll
    for (int t = 0; t < 7; t++) {
        const int c0 = t * 8 + tig * 2;
        acc[t][0] = (c0     < NTOK) ? __expf(acc[t][0] - mx0) : 0.f;
        acc[t][1] = (c0 + 1 < NTOK) ? __expf(acc[t][1] - mx0) : 0.f;
        acc[t][2] = (c0     < NTOK) ? __expf(acc[t][2] - mx1) : 0.f;
        acc[t][3] = (c0 + 1 < NTOK) ? __expf(acc[t][3] - mx1) : 0.f;
        s0 += acc[t][0] + acc[t][1];
        s1 += acc[t][2] + acc[t][3];
    }
    s0 += __shfl_xor_sync(0xffffffffu, s0, 1);
    s0 += __shfl_xor_sync(0xffffffffu, s0, 2);
    s1 += __shfl_xor_sync(0xffffffffu, s1, 1);
    s1 += __shfl_xor_sync(0xffffffffu, s1, 2);
    const float inv0 = 1.f / s0;
    const float inv1 = 1.f / s1;

    #pragma unroll
    for (int t = 0; t < 7; t++) {
        const int c0 = t * 8 + tig * 2;
        Ps[r0*PR + c0]         = f2tf(acc[t][0] * inv0);
        Ps[r0*PR + c0 + 1]     = f2tf(acc[t][1] * inv0);
        Ps[(r0+8)*PR + c0]     = f2tf(acc[t][2] * inv1);
        Ps[(r0+8)*PR + c0 + 1] = f2tf(acc[t][3] * inv1);
    }
    __syncwarp();

    float av[4][4];
    #pragma unroll
    for (int nt = 0; nt < 4; nt++)
        #pragma unroll
        for (int r = 0; r < 4; r++) av[nt][r] = 0.f;

    #pragma unroll
    for (int kv = 0; kv < 7; kv++) {
        const int c = kv * 8 + tig;
        uint32_t af[4];
        af[0] = Ps[r0*PR + c];
        af[1] = Ps[(r0+8)*PR + c];
        af[2] = Ps[r0*PR + c + 4];
        af[3] = Ps[(r0+8)*PR + c + 4];
        #pragma unroll
        for (int nt = 0; nt < 4; nt++) {
            const int dd = nt * 8 + group;
            uint32_t bf[2] = { vt[dd*PR + c], vt[dd*PR + c + 4] };
            mma_tf32(av[nt], af, bf);
        }
    }

    __half* ob = out + (size_t)b * NTOK * DIM + h * DH;
    if (row0) {
        #pragma unroll
        for (int nt = 0; nt < 4; nt++) {
            const int d = nt * 8 + tig * 2;
            __half2 hv = __floats2half2_rn(av[nt][0], av[nt][1]);
            *reinterpret_cast<__half2*>(&ob[(size_t)r0 * DIM + d]) = hv;
        }
    }
    if (row1) {
        #pragma unroll
        for (int nt = 0; nt < 4; nt++) {
            const int d = nt * 8 + tig * 2;
            __half2 hv = __floats2half2_rn(av[nt][2], av[nt][3]);
            *reinterpret_cast<__half2*>(&ob[(size_t)(r0 + 8) * DIM + d]) = hv;
        }
    }
}

// ---------------------------------------------------------------------------
// Launch
// ---------------------------------------------------------------------------
extern "C" void kernel_launch(void* const* d_in, const int* in_sizes, int n_in,
                              void* d_out, int out_size) {
    const float* x         = (const float*)d_in[0];
    const float* mask      = (const float*)d_in[1];
    const float* qkv_w     = (const float*)d_in[2];
    const float* qkv_b     = (const float*)d_in[3];
    const float* proj_w    = (const float*)d_in[4];
    const float* proj_b    = (const float*)d_in[5];
    const float* rpb_table = (const float*)d_in[6];
    const int*   rel_index = (const int*)d_in[7];
    float* out = (float*)d_out;

    float*  qkv;   cudaGetSymbolAddress((void**)&qkv,   g_qkv);
    __half* xh;    cudaGetSymbolAddress((void**)&xh,    g_xh);
    __half* aoh;   cudaGetSymbolAddress((void**)&aoh,   g_attn_outh);
    __half* wh;    cudaGetSymbolAddress((void**)&wh,    g_wh);
    __half* pwh;   cudaGetSymbolAddress((void**)&pwh,   g_pwh);
    float*  biasAll; cudaGetSymbolAddress((void**)&biasAll, g_bias);

    cudaFuncSetAttribute(attn_mma,
                         cudaFuncAttributeMaxDynamicSharedMemorySize, ATTN_SMEM_BYTES);

    // 0) precompute bias; convert x and weights to fp16
    bias_pre<<<NW * H, 256>>>(mask, rpb_table, rel_index, biasAll);
    {
        int n4 = MROWS * DIM / 4;
        cvt_f16<<<(n4 + 255) / 256, 256>>>((const float4*)x, (uint2*)xh, n4);
        n4 = QKV_COLS * DIM / 4;
        cvt_f16<<<(n4 + 255) / 256, 256>>>((const float4*)qkv_w, (uint2*)wh, n4);
        n4 = DIM * DIM / 4;
        cvt_f16<<<(n4 + 255) / 256, 256>>>((const float4*)proj_w, (uint2*)pwh, n4);
    }
    // 1) QKV projection (fp16 tensor cores, f32 out)
    {
        dim3 grid(QKV_COLS / 128, MROWS / 128);
        gemm_f16_nt_bias<<<grid, 256>>>(xh, wh, qkv_b, qkv, MROWS, QKV_COLS, DIM);
    }
    // 2) attention (fp32 compute, fp16 output)
    attn_mma<<<BWIN * H, 128, ATTN_SMEM_BYTES>>>(qkv, biasAll, aoh);
    // 3) output projection
    {
        dim3 grid(DIM / 128, MROWS / 128);
        gemm_f16_nt_bias<<<grid, 256>>>(aoh, pwh, proj_b, out, MROWS, DIM, DIM);
    }
}

// round 7
// speedup vs baseline: 6.9512x; 1.3072x over previous
#include <cuda_runtime.h>
#include <cuda_fp16.h>
#include <cstdint>

// Problem constants
#define NTOK 49
#define DIM 256
#define H 8
#define DH 32
#define BWIN 2048
#define NW 64
#define QKV_COLS 768
#define MROWS (BWIN * NTOK)  // 100352
#define NBH (BWIN * H)       // 16384

// Scratch (device globals; no allocation allowed)
__device__ __half g_xh[(size_t)MROWS * DIM];
__device__ __half g_attn_outh[(size_t)MROWS * DIM];
__device__ __half g_wh[QKV_COLS * DIM];
__device__ __half g_pwh[DIM * DIM];
__device__ float  g_bias[(size_t)NW * H * NTOK * NTOK];
// per-(window,head) fp16 q/k/v: [bh][49][32]
__device__ __half g_qhi[(size_t)NBH * NTOK * DH];
__device__ __half g_qlo[(size_t)NBH * NTOK * DH];
__device__ __half g_khi[(size_t)NBH * NTOK * DH];
__device__ __half g_klo[(size_t)NBH * NTOK * DH];
__device__ __half g_v  [(size_t)NBH * NTOK * DH];

#define ATT_SCALE 0.17677669529663687f

// ---------------------------------------------------------------------------
// Helpers
// ---------------------------------------------------------------------------
__device__ __forceinline__ void cp_async16(uint32_t s, const void* g) {
    asm volatile("cp.async.cg.shared.global [%0], [%1], 16;" :: "r"(s), "l"(g));
}
__device__ __forceinline__ void cp_commit() {
    asm volatile("cp.async.commit_group;");
}
template<int Nw> __device__ __forceinline__ void cp_wait() {
    asm volatile("cp.async.wait_group %0;" :: "n"(Nw));
}
__device__ __forceinline__ void mma_f16(float c[4], const uint32_t a[4], const uint32_t b[2]) {
    asm volatile(
        "mma.sync.aligned.m16n8k16.row.col.f32.f16.f16.f32 "
        "{%0,%1,%2,%3}, {%4,%5,%6,%7}, {%8,%9}, {%0,%1,%2,%3};"
        : "+f"(c[0]), "+f"(c[1]), "+f"(c[2]), "+f"(c[3])
        : "r"(a[0]), "r"(a[1]), "r"(a[2]), "r"(a[3]), "r"(b[0]), "r"(b[1]));
}
__device__ __forceinline__ void ldm_x4(uint32_t& r0, uint32_t& r1, uint32_t& r2, uint32_t& r3,
                                       uint32_t addr) {
    asm volatile("ldmatrix.sync.aligned.m8n8.x4.shared.b16 {%0,%1,%2,%3}, [%4];"
                 : "=r"(r0), "=r"(r1), "=r"(r2), "=r"(r3) : "r"(addr));
}
__device__ __forceinline__ void ldm_x4_t(uint32_t& r0, uint32_t& r1, uint32_t& r2, uint32_t& r3,
                                         uint32_t addr) {
    asm volatile("ldmatrix.sync.aligned.m8n8.x4.trans.shared.b16 {%0,%1,%2,%3}, [%4];"
                 : "=r"(r0), "=r"(r1), "=r"(r2), "=r"(r3) : "r"(addr));
}
__device__ __forceinline__ uint32_t smem_u32(const void* p) {
    uint32_t a;
    asm("{ .reg .u64 t; cvta.to.shared.u64 t, %1; cvt.u32.u64 %0, t; }" : "=r"(a) : "l"(p));
    return a;
}
__device__ __forceinline__ uint32_t pack_h2(float a, float b) {
    __half2 h = __floats2half2_rn(a, b);
    return *reinterpret_cast<uint32_t*>(&h);
}
// 64B-row tile XOR swizzle (16B granular), conflict-free for ldmatrix patterns
#define SWZ(row, kc) ((uint32_t)(((row) << 6) + ((((kc) ^ (((row) >> 1) & 3))) << 4)))

// ---------------------------------------------------------------------------
// fp32 -> fp16 conversion
// ---------------------------------------------------------------------------
__global__ __launch_bounds__(256) void cvt_f16(
    const float4* __restrict__ src, uint2* __restrict__ dst, int n4)
{
    int i = blockIdx.x * blockDim.x + threadIdx.x;
    if (i < n4) {
        float4 v = src[i];
        dst[i] = make_uint2(pack_h2(v.x, v.y), pack_h2(v.z, v.w));
    }
}

// ---------------------------------------------------------------------------
// Bias precompute
// ---------------------------------------------------------------------------
__global__ __launch_bounds__(256) void bias_pre(
    const float* __restrict__ mask, const float* __restrict__ rpb,
    const int* __restrict__ ridx, float* __restrict__ biasAll)
{
    const int wh = blockIdx.x;
    const int w = wh >> 3, h = wh & 7;
    const float* m = mask + (size_t)w * (NTOK * NTOK);
    float* o = biasAll + (size_t)wh * (NTOK * NTOK);
    for (int ij = threadIdx.x; ij < NTOK * NTOK; ij += 256)
        o[ij] = m[ij] + rpb[ridx[ij] * H + h];
}

// ---------------------------------------------------------------------------
// FP16 tensor-core NT GEMM. Block 128x128, BK=32, 8 warps (2m x 4n).
// MODE 0: C(fp32) = A*W^T + bias.  MODE 1: qkv epilogue -> split q/k/v halves.
// ---------------------------------------------------------------------------
template<int MODE>
__global__ __launch_bounds__(256, 2) void gemm_f16(
    const __half* __restrict__ A, const __half* __restrict__ W,
    const float* __restrict__ bias, float* __restrict__ C,
    __half* __restrict__ qhi, __half* __restrict__ qlo,
    __half* __restrict__ khi, __half* __restrict__ klo,
    __half* __restrict__ vh,
    int M, int N, int K)
{
    __shared__ __align__(16) char smem[2 * 16384];

    const int tid  = threadIdx.x;
    const int lane = tid & 31;
    const int warp = tid >> 5;
    const int wm = warp >> 2;
    const int wn = warp & 3;
    const int bm = blockIdx.y * 128;
    const int bn = blockIdx.x * 128;

    const uint32_t sb = smem_u32(smem);

    const int r0f = tid >> 2, kcf = tid & 3;
    const int r1f = r0f + 64;
    const uint32_t dA0 = SWZ(r0f, kcf);
    const uint32_t dA1 = SWZ(r1f, kcf);
    const __half* gA0 = A + (size_t)(bm + r0f) * K + kcf * 8;
    const __half* gA1 = A + (size_t)(bm + r1f) * K + kcf * 8;
    const __half* gB0 = W + (size_t)(bn + r0f) * K + kcf * 8;
    const __half* gB1 = W + (size_t)(bn + r1f) * K + kcf * 8;

    float acc[4][4][4];
    #pragma unroll
    for (int mt = 0; mt < 4; mt++)
        #pragma unroll
        for (int nt = 0; nt < 4; nt++)
            #pragma unroll
            for (int r = 0; r < 4; r++) acc[mt][nt][r] = 0.f;

    const int NS = K >> 5;

    {
        cp_async16(sb + dA0, gA0);
        cp_async16(sb + dA1, gA1);
        cp_async16(sb + 8192 + dA0, gB0);
        cp_async16(sb + 8192 + dA1, gB1);
        cp_commit();
    }

    const int mat  = lane >> 3;
    const int lrow = lane & 7;

    for (int s = 0; s < NS; s++) {
        if (s + 1 < NS) {
            const int k0 = (s + 1) << 5;
            const uint32_t base = sb + ((s + 1) & 1) * 16384;
            cp_async16(base + dA0, gA0 + k0);
            cp_async16(base + dA1, gA1 + k0);
            cp_async16(base + 8192 + dA0, gB0 + k0);
            cp_async16(base + 8192 + dA1, gB1 + k0);
            cp_commit();
            cp_wait<1>();
        } else {
            cp_wait<0>();
        }
        __syncthreads();

        const uint32_t sA = sb + (s & 1) * 16384;
        const uint32_t sB = sA + 8192;

        #pragma unroll
        for (int ks = 0; ks < 2; ks++) {
            uint32_t af[4][4], bf[4][2];
            #pragma unroll
            for (int mt = 0; mt < 4; mt++) {
                const int arow = wm * 64 + mt * 16 + ((mat & 1) << 3) + lrow;
                const int akc  = (ks << 1) + (mat >> 1);
                ldm_x4(af[mt][0], af[mt][1], af[mt][2], af[mt][3], sA + SWZ(arow, akc));
            }
            #pragma unroll
            for (int nt2 = 0; nt2 < 2; nt2++) {
                const int brow = wn * 32 + (nt2 << 4) + ((mat >> 1) << 3) + lrow;
                const int bkc  = (ks << 1) + (mat & 1);
                ldm_x4(bf[nt2*2][0], bf[nt2*2][1], bf[nt2*2+1][0], bf[nt2*2+1][1],
                       sB + SWZ(brow, bkc));
            }
            #pragma unroll
            for (int mt = 0; mt < 4; mt++)
                #pragma unroll
                for (int nt = 0; nt < 4; nt++)
                    mma_f16(acc[mt][nt], af[mt], bf[nt]);
        }
        __syncthreads();
    }

    const int group = lane >> 2, tig = lane & 3;
    if (MODE == 0) {
        #pragma unroll
        for (int mt = 0; mt < 4; mt++) {
            const int r = bm + wm * 64 + mt * 16 + group;
            #pragma unroll
            for (int nt = 0; nt < 4; nt++) {
                const int c = bn + wn * 32 + nt * 8 + tig * 2;
                const float bx = bias[c], by = bias[c + 1];
                *reinterpret_cast<float2*>(&C[(size_t)r * N + c]) =
                    make_float2(acc[mt][nt][0] + bx, acc[mt][nt][1] + by);
                *reinterpret_cast<float2*>(&C[(size_t)(r + 8) * N + c]) =
                    make_float2(acc[mt][nt][2] + bx, acc[mt][nt][3] + by);
            }
        }
    } else {
        #pragma unroll
        for (int mt = 0; mt < 4; mt++) {
            const int r = bm + wm * 64 + mt * 16 + group;
            const uint32_t bA = (uint32_t)r / 49u;
            const int tA = r - (int)bA * 49;
            const uint32_t bB = (uint32_t)(r + 8) / 49u;
            const int tB = (r + 8) - (int)bB * 49;
            #pragma unroll
            for (int nt = 0; nt < 4; nt++) {
                const int cc = bn + wn * 32 + nt * 8 + tig * 2;
                const int sidx = cc >> 8;
                const int hh = (cc >> 5) & 7;
                const int dd = cc & 31;
                float v0 = acc[mt][nt][0] + bias[cc];
                float v1 = acc[mt][nt][1] + bias[cc + 1];
                float v2 = acc[mt][nt][2] + bias[cc];
                float v3 = acc[mt][nt][3] + bias[cc + 1];
                const size_t iA = ((size_t)(bA * 8 + hh) * NTOK + tA) * DH + dd;
                const size_t iB = ((size_t)(bB * 8 + hh) * NTOK + tB) * DH + dd;
                if (sidx == 0) {
                    v0 *= ATT_SCALE; v1 *= ATT_SCALE; v2 *= ATT_SCALE; v3 *= ATT_SCALE;
                    __half2 hA = __floats2half2_rn(v0, v1);
                    float2 fA = __half22float2(hA);
                    __half2 lA = __floats2half2_rn(v0 - fA.x, v1 - fA.y);
                    __half2 hB = __floats2half2_rn(v2, v3);
                    float2 fB = __half22float2(hB);
                    __half2 lB = __floats2half2_rn(v2 - fB.x, v3 - fB.y);
                    *reinterpret_cast<__half2*>(&qhi[iA]) = hA;
                    *reinterpret_cast<__half2*>(&qlo[iA]) = lA;
                    *reinterpret_cast<__half2*>(&qhi[iB]) = hB;
                    *reinterpret_cast<__half2*>(&qlo[iB]) = lB;
                } else if (sidx == 1) {
                    __half2 hA = __floats2half2_rn(v0, v1);
                    float2 fA = __half22float2(hA);
                    __half2 lA = __floats2half2_rn(v0 - fA.x, v1 - fA.y);
                    __half2 hB = __floats2half2_rn(v2, v3);
                    float2 fB = __half22float2(hB);
                    __half2 lB = __floats2half2_rn(v2 - fB.x, v3 - fB.y);
                    *reinterpret_cast<__half2*>(&khi[iA]) = hA;
                    *reinterpret_cast<__half2*>(&klo[iA]) = lA;
                    *reinterpret_cast<__half2*>(&khi[iB]) = hB;
                    *reinterpret_cast<__half2*>(&klo[iB]) = lB;
                } else {
                    *reinterpret_cast<__half2*>(&vh[iA]) = __floats2half2_rn(v0, v1);
                    *reinterpret_cast<__half2*>(&vh[iB]) = __floats2half2_rn(v2, v3);
                }
            }
        }
    }
}

// ---------------------------------------------------------------------------
// Attention v2: fp16 fragments end-to-end. One block per (window, head).
// smem: 5 tiles [64 rows x 64B] (qhi, qlo, khi, klo, v) = 20 KB.
// ---------------------------------------------------------------------------
__global__ __launch_bounds__(128) void attn_f16(
    const __half* __restrict__ qhi, const __half* __restrict__ qlo,
    const __half* __restrict__ khi, const __half* __restrict__ klo,
    const __half* __restrict__ vh,
    const float* __restrict__ biasAll,
    __half* __restrict__ out)
{
    __shared__ __align__(16) char smem[5 * 4096];
    const uint32_t sb = smem_u32(smem);
    const uint32_t tQh = sb, tQl = sb + 4096, tKh = sb + 8192,
                   tKl = sb + 12288, tV = sb + 16384;

    const int bh = blockIdx.x;
    const int b = bh >> 3, h = bh & 7;
    const int tid = threadIdx.x;

    const size_t gbase = (size_t)bh * NTOK * DH;
    const __half* gp[5] = { qhi + gbase, qlo + gbase, khi + gbase, klo + gbase, vh + gbase };

    // fill: 49 rows x 4 chunks of 16B per buffer
    #pragma unroll
    for (int buf = 0; buf < 5; buf++) {
        for (int i = tid; i < 196; i += 128) {
            const int row = i >> 2, kc = i & 3;
            cp_async16(sb + buf * 4096 + SWZ(row, kc), gp[buf] + row * DH + kc * 8);
        }
    }
    cp_commit();
    // zero pad rows 49..63 (independent addresses; safe alongside cp.async)
    for (int i = tid; i < 300; i += 128) {
        const int buf = i / 60, rem = i - buf * 60;
        const int row = 49 + (rem >> 2), kc = rem & 3;
        *reinterpret_cast<uint4*>(smem + buf * 4096 + SWZ(row, kc)) = make_uint4(0, 0, 0, 0);
    }
    cp_wait<0>();
    __syncthreads();

    const int warp = tid >> 5, lane = tid & 31;
    const int group = lane >> 2, tig = lane & 3;
    const int mat = lane >> 3, lrow = lane & 7;
    const int r0 = warp * 16 + group;

    // ---- QK^T: split-fp16, 2 k16 chunks over d=32 ----
    float acc[7][4];
    #pragma unroll
    for (int t = 0; t < 7; t++)
        #pragma unroll
        for (int r = 0; r < 4; r++) acc[t][r] = 0.f;

    #pragma unroll
    for (int kc16 = 0; kc16 < 2; kc16++) {
        const int arow = warp * 16 + ((mat & 1) << 3) + lrow;
        const int akc  = kc16 * 2 + (mat >> 1);
        uint32_t ah[4], al[4];
        ldm_x4(ah[0], ah[1], ah[2], ah[3], tQh + SWZ(arow, akc));
        ldm_x4(al[0], al[1], al[2], al[3], tQl + SWZ(arow, akc));
        #pragma unroll
        for (int g4 = 0; g4 < 4; g4++) {
            const int brow = g4 * 16 + ((mat >> 1) << 3) + lrow;
            const int bkc  = kc16 * 2 + (mat & 1);
            uint32_t bh2[2][2], bl2[2][2];
            ldm_x4(bh2[0][0], bh2[0][1], bh2[1][0], bh2[1][1], tKh + SWZ(brow, bkc));
            ldm_x4(bl2[0][0], bl2[0][1], bl2[1][0], bl2[1][1], tKl + SWZ(brow, bkc));
            #pragma unroll
            for (int u = 0; u < 2; u++) {
                const int t = g4 * 2 + u;
                if (t < 7) {
                    mma_f16(acc[t], ah, bh2[u]);
                    mma_f16(acc[t], ah, bl2[u]);
                    mma_f16(acc[t], al, bh2[u]);
                }
            }
        }
    }

    // ---- bias + masked softmax in registers ----
    const float* bp = biasAll + (size_t)(((b & (NW - 1)) << 3) + h) * (NTOK * NTOK);
    const bool row0 = (r0 < NTOK);
    const bool row1 = (r0 + 8 < NTOK);
    float mx0 = -1e30f, mx1 = -1e30f;
    #pragma unroll
    for (int t = 0; t < 7; t++) {
        const int c0 = t * 8 + tig * 2;
        if (c0 < NTOK) {
            if (row0) { acc[t][0] += __ldg(&bp[r0 * NTOK + c0]);       mx0 = fmaxf(mx0, acc[t][0]); }
            if (row1) { acc[t][2] += __ldg(&bp[(r0 + 8) * NTOK + c0]); mx1 = fmaxf(mx1, acc[t][2]); }
        }
        if (c0 + 1 < NTOK) {
            if (row0) { acc[t][1] += __ldg(&bp[r0 * NTOK + c0 + 1]);       mx0 = fmaxf(mx0, acc[t][1]); }
            if (row1) { acc[t][3] += __ldg(&bp[(r0 + 8) * NTOK + c0 + 1]); mx1 = fmaxf(mx1, acc[t][3]); }
        }
    }
    mx0 = fmaxf(mx0, __shfl_xor_sync(0xffffffffu, mx0, 1));
    mx0 = fmaxf(mx0, __shfl_xor_sync(0xffffffffu, mx0, 2));
    mx1 = fmaxf(mx1, __shfl_xor_sync(0xffffffffu, mx1, 1));
    mx1 = fmaxf(mx1, __shfl_xor_sync(0xffffffffu, mx1, 2));
    if (mx0 < -1e29f) mx0 = 0.f;
    if (mx1 < -1e29f) mx1 = 0.f;

    float s0 = 0.f, s1 = 0.f;
    #pragma unroll
    for (int t = 0; t < 7; t++) {
        const int c0 = t * 8 + tig * 2;
        acc[t][0] = (c0     < NTOK) ? __expf(acc[t][0] - mx0) : 0.f;
        acc[t][1] = (c0 + 1 < NTOK) ? __expf(acc[t][1] - mx0) : 0.f;
        acc[t][2] = (c0     < NTOK) ? __expf(acc[t][2] - mx1) : 0.f;
        acc[t][3] = (c0 + 1 < NTOK) ? __expf(acc[t][3] - mx1) : 0.f;
        s0 += acc[t][0] + acc[t][1];
        s1 += acc[t][2] + acc[t][3];
    }
    s0 += __shfl_xor_sync(0xffffffffu, s0, 1);
    s0 += __shfl_xor_sync(0xffffffffu, s0, 2);
    s1 += __shfl_xor_sync(0xffffffffu, s1, 1);
    s1 += __shfl_xor_sync(0xffffffffu, s1, 2);
    const float inv0 = 1.f / s0;
    const float inv1 = 1.f / s1;

    // ---- AV: P packed in registers as fp16 A-frags; V via ldmatrix.trans ----
    uint32_t pa[4][4];
    #pragma unroll
    for (int kc = 0; kc < 4; kc++) {
        const int t0 = kc * 2, t1 = kc * 2 + 1;
        pa[kc][0] = pack_h2(acc[t0][0] * inv0, acc[t0][1] * inv0);
        pa[kc][1] = pack_h2(acc[t0][2] * inv1, acc[t0][3] * inv1);
        if (t1 < 7) {
            pa[kc][2] = pack_h2(acc[t1][0] * inv0, acc[t1][1] * inv0);
            pa[kc][3] = pack_h2(acc[t1][2] * inv1, acc[t1][3] * inv1);
        } else {
            pa[kc][2] = 0u;
            pa[kc][3] = 0u;
        }
    }

    float av[4][4];
    #pragma unroll
    for (int nt = 0; nt < 4; nt++)
        #pragma unroll
        for (int r = 0; r < 4; r++) av[nt][r] = 0.f;

    #pragma unroll
    for (int kc = 0; kc < 4; kc++) {
        #pragma unroll
        for (int d16 = 0; d16 < 2; d16++) {
            const int vrow = kc * 16 + ((mat & 1) << 3) + lrow;
            const int vkc  = d16 * 2 + (mat >> 1);
            uint32_t bf[2][2];
            ldm_x4_t(bf[0][0], bf[0][1], bf[1][0], bf[1][1], tV + SWZ(vrow, vkc));
            mma_f16(av[d16 * 2],     pa[kc], bf[0]);
            mma_f16(av[d16 * 2 + 1], pa[kc], bf[1]);
        }
    }

    // ---- store (fp16 for proj input) ----
    __half* ob = out + (size_t)b * NTOK * DIM + h * DH;
    if (row0) {
        #pragma unroll
        for (int nt = 0; nt < 4; nt++) {
            const int d = nt * 8 + tig * 2;
            *reinterpret_cast<__half2*>(&ob[(size_t)r0 * DIM + d]) =
                __floats2half2_rn(av[nt][0], av[nt][1]);
        }
    }
    if (row1) {
        #pragma unroll
        for (int nt = 0; nt < 4; nt++) {
            const int d = nt * 8 + tig * 2;
            *reinterpret_cast<__half2*>(&ob[(size_t)(r0 + 8) * DIM + d]) =
                __floats2half2_rn(av[nt][2], av[nt][3]);
        }
    }
}

// ---------------------------------------------------------------------------
// Launch
// ---------------------------------------------------------------------------
extern "C" void kernel_launch(void* const* d_in, const int* in_sizes, int n_in,
                              void* d_out, int out_size) {
    const float* x         = (const float*)d_in[0];
    const float* mask      = (const float*)d_in[1];
    const float* qkv_w     = (const float*)d_in[2];
    const float* qkv_b     = (const float*)d_in[3];
    const float* proj_w    = (const float*)d_in[4];
    const float* proj_b    = (const float*)d_in[5];
    const float* rpb_table = (const float*)d_in[6];
    const int*   rel_index = (const int*)d_in[7];
    float* out = (float*)d_out;

    __half *xh, *aoh, *wh, *pwh, *qhi, *qlo, *khi, *klo, *vh;
    float *biasAll;
    cudaGetSymbolAddress((void**)&xh,  g_xh);
    cudaGetSymbolAddress((void**)&aoh, g_attn_outh);
    cudaGetSymbolAddress((void**)&wh,  g_wh);
    cudaGetSymbolAddress((void**)&pwh, g_pwh);
    cudaGetSymbolAddress((void**)&qhi, g_qhi);
    cudaGetSymbolAddress((void**)&qlo, g_qlo);
    cudaGetSymbolAddress((void**)&khi, g_khi);
    cudaGetSymbolAddress((void**)&klo, g_klo);
    cudaGetSymbolAddress((void**)&vh,  g_v);
    cudaGetSymbolAddress((void**)&biasAll, g_bias);

    // 0) bias precompute + fp16 conversions
    bias_pre<<<NW * H, 256>>>(mask, rpb_table, rel_index, biasAll);
    {
        int n4 = MROWS * DIM / 4;
        cvt_f16<<<(n4 + 255) / 256, 256>>>((const float4*)x, (uint2*)xh, n4);
        n4 = QKV_COLS * DIM / 4;
        cvt_f16<<<(n4 + 255) / 256, 256>>>((const float4*)qkv_w, (uint2*)wh, n4);
        n4 = DIM * DIM / 4;
        cvt_f16<<<(n4 + 255) / 256, 256>>>((const float4*)proj_w, (uint2*)pwh, n4);
    }
    // 1) QKV projection with fused split-q/k/v epilogue
    {
        dim3 grid(QKV_COLS / 128, MROWS / 128);
        gemm_f16<1><<<grid, 256>>>(xh, wh, qkv_b, nullptr,
                                   qhi, qlo, khi, klo, vh,
                                   MROWS, QKV_COLS, DIM);
    }
    // 2) attention
    attn_f16<<<NBH, 128>>>(qhi, qlo, khi, klo, vh, biasAll, aoh);
    // 3) output projection
    {
        dim3 grid(DIM / 128, MROWS / 128);
        gemm_f16<0><<<grid, 256>>>(aoh, pwh, proj_b, out,
                                   nullptr, nullptr, nullptr, nullptr, nullptr,
                                   MROWS, DIM, DIM);
    }
}

// round 8
// speedup vs baseline: 7.4519x; 1.0720x over previous
#include <cuda_runtime.h>
#include <cuda_fp16.h>
#include <cstdint>

// Problem constants
#define NTOK 49
#define DIM 256
#define H 8
#define DH 32
#define BWIN 2048
#define NW 64
#define QKV_COLS 768
#define MROWS (BWIN * NTOK)  // 100352
#define NBH (BWIN * H)       // 16384

// Scratch (device globals; no allocation allowed)
__device__ __half g_xh[(size_t)MROWS * DIM];
__device__ __half g_attn_outh[(size_t)MROWS * DIM];
__device__ __half g_wh[QKV_COLS * DIM];
__device__ __half g_pwh[DIM * DIM];
__device__ float  g_bias[(size_t)NW * H * NTOK * NTOK];
// per-(window,head) fp16 q/k/v: [bh][49][32]
__device__ __half g_qhi[(size_t)NBH * NTOK * DH];
__device__ __half g_qlo[(size_t)NBH * NTOK * DH];
__device__ __half g_khi[(size_t)NBH * NTOK * DH];
__device__ __half g_klo[(size_t)NBH * NTOK * DH];
__device__ __half g_v  [(size_t)NBH * NTOK * DH];

#define ATT_SCALE 0.17677669529663687f

// ---------------------------------------------------------------------------
// Helpers
// ---------------------------------------------------------------------------
__device__ __forceinline__ void cp_async16(uint32_t s, const void* g) {
    asm volatile("cp.async.cg.shared.global [%0], [%1], 16;" :: "r"(s), "l"(g));
}
__device__ __forceinline__ void cp_commit() {
    asm volatile("cp.async.commit_group;");
}
template<int Nw> __device__ __forceinline__ void cp_wait() {
    asm volatile("cp.async.wait_group %0;" :: "n"(Nw));
}
__device__ __forceinline__ void mma_f16(float c[4], const uint32_t a[4], const uint32_t b[2]) {
    asm volatile(
        "mma.sync.aligned.m16n8k16.row.col.f32.f16.f16.f32 "
        "{%0,%1,%2,%3}, {%4,%5,%6,%7}, {%8,%9}, {%0,%1,%2,%3};"
        : "+f"(c[0]), "+f"(c[1]), "+f"(c[2]), "+f"(c[3])
        : "r"(a[0]), "r"(a[1]), "r"(a[2]), "r"(a[3]), "r"(b[0]), "r"(b[1]));
}
__device__ __forceinline__ void ldm_x4(uint32_t& r0, uint32_t& r1, uint32_t& r2, uint32_t& r3,
                                       uint32_t addr) {
    asm volatile("ldmatrix.sync.aligned.m8n8.x4.shared.b16 {%0,%1,%2,%3}, [%4];"
                 : "=r"(r0), "=r"(r1), "=r"(r2), "=r"(r3) : "r"(addr));
}
__device__ __forceinline__ void ldm_x4_t(uint32_t& r0, uint32_t& r1, uint32_t& r2, uint32_t& r3,
                                         uint32_t addr) {
    asm volatile("ldmatrix.sync.aligned.m8n8.x4.trans.shared.b16 {%0,%1,%2,%3}, [%4];"
                 : "=r"(r0), "=r"(r1), "=r"(r2), "=r"(r3) : "r"(addr));
}
__device__ __forceinline__ uint32_t smem_u32(const void* p) {
    uint32_t a;
    asm("{ .reg .u64 t; cvta.to.shared.u64 t, %1; cvt.u32.u64 %0, t; }" : "=r"(a) : "l"(p));
    return a;
}
__device__ __forceinline__ uint32_t pack_h2(float a, float b) {
    __half2 h = __floats2half2_rn(a, b);
    return *reinterpret_cast<uint32_t*>(&h);
}
// 64B-row tile swizzle (attention tiles)
#define SWZ(row, kc) ((uint32_t)(((row) << 6) + ((((kc) ^ (((row) >> 1) & 3))) << 4)))
// 128B-row tile swizzle (GEMM BK=64 tiles): 8 chunks of 16B per row
#define SWZ64(row, kc) ((uint32_t)(((row) << 7) + ((((kc) ^ ((row) & 7))) << 4)))

// ---------------------------------------------------------------------------
// fp32 -> fp16 conversion
// ---------------------------------------------------------------------------
__global__ __launch_bounds__(256) void cvt_f16(
    const float4* __restrict__ src, uint2* __restrict__ dst, int n4)
{
    int i = blockIdx.x * blockDim.x + threadIdx.x;
    if (i < n4) {
        float4 v = src[i];
        dst[i] = make_uint2(pack_h2(v.x, v.y), pack_h2(v.z, v.w));
    }
}

// ---------------------------------------------------------------------------
// Bias precompute
// ---------------------------------------------------------------------------
__global__ __launch_bounds__(256) void bias_pre(
    const float* __restrict__ mask, const float* __restrict__ rpb,
    const int* __restrict__ ridx, float* __restrict__ biasAll)
{
    const int wh = blockIdx.x;
    const int w = wh >> 3, h = wh & 7;
    const float* m = mask + (size_t)w * (NTOK * NTOK);
    float* o = biasAll + (size_t)wh * (NTOK * NTOK);
    for (int ij = threadIdx.x; ij < NTOK * NTOK; ij += 256)
        o[ij] = m[ij] + rpb[ridx[ij] * H + h];
}

// ---------------------------------------------------------------------------
// FP16 tensor-core NT GEMM. Block 128x128, BK=64, 8 warps (2m x 4n).
// MODE 0: C(fp32) = A*W^T + bias.  MODE 1: qkv epilogue -> split q/k/v halves.
// Requires M%128==0, N%128==0, K%64==0.
// ---------------------------------------------------------------------------
#define G_STAGE 32768                     // A 16KB + B 16KB per stage
#define GEMM_SMEM_BYTES (2 * G_STAGE)     // 65536 (dynamic)

template<int MODE>
__global__ __launch_bounds__(256, 2) void gemm_f16(
    const __half* __restrict__ A, const __half* __restrict__ W,
    const float* __restrict__ bias, float* __restrict__ C,
    __half* __restrict__ qhi, __half* __restrict__ qlo,
    __half* __restrict__ khi, __half* __restrict__ klo,
    __half* __restrict__ vh,
    int M, int N, int K)
{
    extern __shared__ __align__(16) char smem[];

    const int tid  = threadIdx.x;
    const int lane = tid & 31;
    const int warp = tid >> 5;
    const int wm = warp >> 2;
    const int wn = warp & 3;
    const int bm = blockIdx.y * 128;
    const int bn = blockIdx.x * 128;

    const uint32_t sb = smem_u32(smem);

    // fill mapping: 1024 16B-chunks per tile, 4 per thread (A) + 4 (B)
    uint32_t dstA[4];
    const __half* srcA[4];
    const __half* srcB[4];
    #pragma unroll
    for (int t = 0; t < 4; t++) {
        const int chunk = tid + t * 256;
        const int row = chunk >> 3, kc = chunk & 7;
        dstA[t] = SWZ64(row, kc);
        srcA[t] = A + (size_t)(bm + row) * K + kc * 8;
        srcB[t] = W + (size_t)(bn + row) * K + kc * 8;
    }

    float acc[4][4][4];
    #pragma unroll
    for (int mt = 0; mt < 4; mt++)
        #pragma unroll
        for (int nt = 0; nt < 4; nt++)
            #pragma unroll
            for (int r = 0; r < 4; r++) acc[mt][nt][r] = 0.f;

    const int NS = K >> 6;

    // prefetch stage 0
    #pragma unroll
    for (int t = 0; t < 4; t++) cp_async16(sb + dstA[t], srcA[t]);
    #pragma unroll
    for (int t = 0; t < 4; t++) cp_async16(sb + 16384 + dstA[t], srcB[t]);
    cp_commit();

    const int mat  = lane >> 3;
    const int lrow = lane & 7;

    for (int s = 0; s < NS; s++) {
        if (s + 1 < NS) {
            const int k0 = (s + 1) << 6;
            const uint32_t base = sb + ((s + 1) & 1) * G_STAGE;
            #pragma unroll
            for (int t = 0; t < 4; t++) cp_async16(base + dstA[t], srcA[t] + k0);
            #pragma unroll
            for (int t = 0; t < 4; t++) cp_async16(base + 16384 + dstA[t], srcB[t] + k0);
            cp_commit();
            cp_wait<1>();
        } else {
            cp_wait<0>();
        }
        __syncthreads();

        const uint32_t sA = sb + (s & 1) * G_STAGE;
        const uint32_t sB = sA + 16384;

        #pragma unroll
        for (int ks = 0; ks < 4; ks++) {
            uint32_t af[4][4], bf[4][2];
            #pragma unroll
            for (int mt = 0; mt < 4; mt++) {
                const int arow = wm * 64 + mt * 16 + ((mat & 1) << 3) + lrow;
                const int akc  = (ks << 1) + (mat >> 1);
                ldm_x4(af[mt][0], af[mt][1], af[mt][2], af[mt][3], sA + SWZ64(arow, akc));
            }
            #pragma unroll
            for (int nt2 = 0; nt2 < 2; nt2++) {
                const int brow = wn * 32 + (nt2 << 4) + ((mat >> 1) << 3) + lrow;
                const int bkc  = (ks << 1) + (mat & 1);
                ldm_x4(bf[nt2*2][0], bf[nt2*2][1], bf[nt2*2+1][0], bf[nt2*2+1][1],
                       sB + SWZ64(brow, bkc));
            }
            #pragma unroll
            for (int mt = 0; mt < 4; mt++)
                #pragma unroll
                for (int nt = 0; nt < 4; nt++)
                    mma_f16(acc[mt][nt], af[mt], bf[nt]);
        }
        __syncthreads();
    }

    const int group = lane >> 2, tig = lane & 3;
    if (MODE == 0) {
        #pragma unroll
        for (int mt = 0; mt < 4; mt++) {
            const int r = bm + wm * 64 + mt * 16 + group;
            #pragma unroll
            for (int nt = 0; nt < 4; nt++) {
                const int c = bn + wn * 32 + nt * 8 + tig * 2;
                const float bx = bias[c], by = bias[c + 1];
                *reinterpret_cast<float2*>(&C[(size_t)r * N + c]) =
                    make_float2(acc[mt][nt][0] + bx, acc[mt][nt][1] + by);
                *reinterpret_cast<float2*>(&C[(size_t)(r + 8) * N + c]) =
                    make_float2(acc[mt][nt][2] + bx, acc[mt][nt][3] + by);
            }
        }
    } else {
        #pragma unroll
        for (int mt = 0; mt < 4; mt++) {
            const int r = bm + wm * 64 + mt * 16 + group;
            const uint32_t bA = (uint32_t)r / 49u;
            const int tA = r - (int)bA * 49;
            const uint32_t bB = (uint32_t)(r + 8) / 49u;
            const int tB = (r + 8) - (int)bB * 49;
            #pragma unroll
            for (int nt = 0; nt < 4; nt++) {
                const int cc = bn + wn * 32 + nt * 8 + tig * 2;
                const int sidx = cc >> 8;
                const int hh = (cc >> 5) & 7;
                const int dd = cc & 31;
                float v0 = acc[mt][nt][0] + bias[cc];
                float v1 = acc[mt][nt][1] + bias[cc + 1];
                float v2 = acc[mt][nt][2] + bias[cc];
                float v3 = acc[mt][nt][3] + bias[cc + 1];
                const size_t iA = ((size_t)(bA * 8 + hh) * NTOK + tA) * DH + dd;
                const size_t iB = ((size_t)(bB * 8 + hh) * NTOK + tB) * DH + dd;
                if (sidx == 0) {
                    v0 *= ATT_SCALE; v1 *= ATT_SCALE; v2 *= ATT_SCALE; v3 *= ATT_SCALE;
                    __half2 hA = __floats2half2_rn(v0, v1);
                    float2 fA = __half22float2(hA);
                    __half2 lA = __floats2half2_rn(v0 - fA.x, v1 - fA.y);
                    __half2 hB = __floats2half2_rn(v2, v3);
                    float2 fB = __half22float2(hB);
                    __half2 lB = __floats2half2_rn(v2 - fB.x, v3 - fB.y);
                    *reinterpret_cast<__half2*>(&qhi[iA]) = hA;
                    *reinterpret_cast<__half2*>(&qlo[iA]) = lA;
                    *reinterpret_cast<__half2*>(&qhi[iB]) = hB;
                    *reinterpret_cast<__half2*>(&qlo[iB]) = lB;
                } else if (sidx == 1) {
                    __half2 hA = __floats2half2_rn(v0, v1);
                    float2 fA = __half22float2(hA);
                    __half2 lA = __floats2half2_rn(v0 - fA.x, v1 - fA.y);
                    __half2 hB = __floats2half2_rn(v2, v3);
                    float2 fB = __half22float2(hB);
                    __half2 lB = __floats2half2_rn(v2 - fB.x, v3 - fB.y);
                    *reinterpret_cast<__half2*>(&khi[iA]) = hA;
                    *reinterpret_cast<__half2*>(&klo[iA]) = lA;
                    *reinterpret_cast<__half2*>(&khi[iB]) = hB;
                    *reinterpret_cast<__half2*>(&klo[iB]) = lB;
                } else {
                    *reinterpret_cast<__half2*>(&vh[iA]) = __floats2half2_rn(v0, v1);
                    *reinterpret_cast<__half2*>(&vh[iB]) = __floats2half2_rn(v2, v3);
                }
            }
        }
    }
}

// ---------------------------------------------------------------------------
// Attention (R7-proven): fp16 fragments end-to-end. One block per (window, head).
// ---------------------------------------------------------------------------
__global__ __launch_bounds__(128) void attn_f16(
    const __half* __restrict__ qhi, const __half* __restrict__ qlo,
    const __half* __restrict__ khi, const __half* __restrict__ klo,
    const __half* __restrict__ vh,
    const float* __restrict__ biasAll,
    __half* __restrict__ out)
{
    __shared__ __align__(16) char smem[5 * 4096];
    const uint32_t sb = smem_u32(smem);
    const uint32_t tQh = sb, tQl = sb + 4096, tKh = sb + 8192,
                   tKl = sb + 12288, tV = sb + 16384;

    const int bh = blockIdx.x;
    const int b = bh >> 3, h = bh & 7;
    const int tid = threadIdx.x;

    const size_t gbase = (size_t)bh * NTOK * DH;
    const __half* gp[5] = { qhi + gbase, qlo + gbase, khi + gbase, klo + gbase, vh + gbase };

    #pragma unroll
    for (int buf = 0; buf < 5; buf++) {
        for (int i = tid; i < 196; i += 128) {
            const int row = i >> 2, kc = i & 3;
            cp_async16(sb + buf * 4096 + SWZ(row, kc), gp[buf] + row * DH + kc * 8);
        }
    }
    cp_commit();
    for (int i = tid; i < 300; i += 128) {
        const int buf = i / 60, rem = i - buf * 60;
        const int row = 49 + (rem >> 2), kc = rem & 3;
        *reinterpret_cast<uint4*>(smem + buf * 4096 + SWZ(row, kc)) = make_uint4(0, 0, 0, 0);
    }
    cp_wait<0>();
    __syncthreads();

    const int warp = tid >> 5, lane = tid & 31;
    const int group = lane >> 2, tig = lane & 3;
    const int mat = lane >> 3, lrow = lane & 7;
    const int r0 = warp * 16 + group;

    float acc[7][4];
    #pragma unroll
    for (int t = 0; t < 7; t++)
        #pragma unroll
        for (int r = 0; r < 4; r++) acc[t][r] = 0.f;

    #pragma unroll
    for (int kc16 = 0; kc16 < 2; kc16++) {
        const int arow = warp * 16 + ((mat & 1) << 3) + lrow;
        const int akc  = kc16 * 2 + (mat >> 1);
        uint32_t ah[4], al[4];
        ldm_x4(ah[0], ah[1], ah[2], ah[3], tQh + SWZ(arow, akc));
        ldm_x4(al[0], al[1], al[2], al[3], tQl + SWZ(arow, akc));
        #pragma unroll
        for (int g4 = 0; g4 < 4; g4++) {
            const int brow = g4 * 16 + ((mat >> 1) << 3) + lrow;
            const int bkc  = kc16 * 2 + (mat & 1);
            uint32_t bh2[2][2], bl2[2][2];
            ldm_x4(bh2[0][0], bh2[0][1], bh2[1][0], bh2[1][1], tKh + SWZ(brow, bkc));
            ldm_x4(bl2[0][0], bl2[0][1], bl2[1][0], bl2[1][1], tKl + SWZ(brow, bkc));
            #pragma unroll
            for (int u = 0; u < 2; u++) {
                const int t = g4 * 2 + u;
                if (t < 7) {
                    mma_f16(acc[t], ah, bh2[u]);
                    mma_f16(acc[t], ah, bl2[u]);
                    mma_f16(acc[t], al, bh2[u]);
                }
            }
        }
    }

    const float* bp = biasAll + (size_t)(((b & (NW - 1)) << 3) + h) * (NTOK * NTOK);
    const bool row0 = (r0 < NTOK);
    const bool row1 = (r0 + 8 < NTOK);
    float mx0 = -1e30f, mx1 = -1e30f;
    #pragma unroll
    for (int t = 0; t < 7; t++) {
        const int c0 = t * 8 + tig * 2;
        if (c0 < NTOK) {
            if (row0) { acc[t][0] += __ldg(&bp[r0 * NTOK + c0]);       mx0 = fmaxf(mx0, acc[t][0]); }
            if (row1) { acc[t][2] += __ldg(&bp[(r0 + 8) * NTOK + c0]); mx1 = fmaxf(mx1, acc[t][2]); }
        }
        if (c0 + 1 < NTOK) {
            if (row0) { acc[t][1] += __ldg(&bp[r0 * NTOK + c0 + 1]);       mx0 = fmaxf(mx0, acc[t][1]); }
            if (row1) { acc[t][3] += __ldg(&bp[(r0 + 8) * NTOK + c0 + 1]); mx1 = fmaxf(mx1, acc[t][3]); }
        }
    }
    mx0 = fmaxf(mx0, __shfl_xor_sync(0xffffffffu, mx0, 1));
    mx0 = fmaxf(mx0, __shfl_xor_sync(0xffffffffu, mx0, 2));
    mx1 = fmaxf(mx1, __shfl_xor_sync(0xffffffffu, mx1, 1));
    mx1 = fmaxf(mx1, __shfl_xor_sync(0xffffffffu, mx1, 2));
    if (mx0 < -1e29f) mx0 = 0.f;
    if (mx1 < -1e29f) mx1 = 0.f;

    float s0 = 0.f, s1 = 0.f;
    #pragma unroll
    for (int t = 0; t < 7; t++) {
        const int c0 = t * 8 + tig * 2;
        acc[t][0] = (c0     < NTOK) ? __expf(acc[t][0] - mx0) : 0.f;
        acc[t][1] = (c0 + 1 < NTOK) ? __expf(acc[t][1] - mx0) : 0.f;
        acc[t][2] = (c0     < NTOK) ? __expf(acc[t][2] - mx1) : 0.f;
        acc[t][3] = (c0 + 1 < NTOK) ? __expf(acc[t][3] - mx1) : 0.f;
        s0 += acc[t][0] + acc[t][1];
        s1 += acc[t][2] + acc[t][3];
    }
    s0 += __shfl_xor_sync(0xffffffffu, s0, 1);
    s0 += __shfl_xor_sync(0xffffffffu, s0, 2);
    s1 += __shfl_xor_sync(0xffffffffu, s1, 1);
    s1 += __shfl_xor_sync(0xffffffffu, s1, 2);
    const float inv0 = 1.f / s0;
    const float inv1 = 1.f / s1;

    uint32_t pa[4][4];
    #pragma unroll
    for (int kc = 0; kc < 4; kc++) {
        const int t0 = kc * 2, t1 = kc * 2 + 1;
        pa[kc][0] = pack_h2(acc[t0][0] * inv0, acc[t0][1] * inv0);
        pa[kc][1] = pack_h2(acc[t0][2] * inv1, acc[t0][3] * inv1);
        if (t1 < 7) {
            pa[kc][2] = pack_h2(acc[t1][0] * inv0, acc[t1][1] * inv0);
            pa[kc][3] = pack_h2(acc[t1][2] * inv1, acc[t1][3] * inv1);
        } else {
            pa[kc][2] = 0u;
            pa[kc][3] = 0u;
        }
    }

    float av[4][4];
    #pragma unroll
    for (int nt = 0; nt < 4; nt++)
        #pragma unroll
        for (int r = 0; r < 4; r++) av[nt][r] = 0.f;

    #pragma unroll
    for (int kc = 0; kc < 4; kc++) {
        #pragma unroll
        for (int d16 = 0; d16 < 2; d16++) {
            const int vrow = kc * 16 + ((mat & 1) << 3) + lrow;
            const int vkc  = d16 * 2 + (mat >> 1);
            uint32_t bf[2][2];
            ldm_x4_t(bf[0][0], bf[0][1], bf[1][0], bf[1][1], tV + SWZ(vrow, vkc));
            mma_f16(av[d16 * 2],     pa[kc], bf[0]);
            mma_f16(av[d16 * 2 + 1], pa[kc], bf[1]);
        }
    }

    __half* ob = out + (size_t)b * NTOK * DIM + h * DH;
    if (row0) {
        #pragma unroll
        for (int nt = 0; nt < 4; nt++) {
            const int d = nt * 8 + tig * 2;
            *reinterpret_cast<__half2*>(&ob[(size_t)r0 * DIM + d]) =
                __floats2half2_rn(av[nt][0], av[nt][1]);
        }
    }
    if (row1) {
        #pragma unroll
        for (int nt = 0; nt < 4; nt++) {
            const int d = nt * 8 + tig * 2;
            *reinterpret_cast<__half2*>(&ob[(size_t)(r0 + 8) * DIM + d]) =
                __floats2half2_rn(av[nt][2], av[nt][3]);
        }
    }
}

// ---------------------------------------------------------------------------
// Launch
// ---------------------------------------------------------------------------
extern "C" void kernel_launch(void* const* d_in, const int* in_sizes, int n_in,
                              void* d_out, int out_size) {
    const float* x         = (const float*)d_in[0];
    const float* mask      = (const float*)d_in[1];
    const float* qkv_w     = (const float*)d_in[2];
    const float* qkv_b     = (const float*)d_in[3];
    const float* proj_w    = (const float*)d_in[4];
    const float* proj_b    = (const float*)d_in[5];
    const float* rpb_table = (const float*)d_in[6];
    const int*   rel_index = (const int*)d_in[7];
    float* out = (float*)d_out;

    __half *xh, *aoh, *wh, *pwh, *qhi, *qlo, *khi, *klo, *vh;
    float *biasAll;
    cudaGetSymbolAddress((void**)&xh,  g_xh);
    cudaGetSymbolAddress((void**)&aoh, g_attn_outh);
    cudaGetSymbolAddress((void**)&wh,  g_wh);
    cudaGetSymbolAddress((void**)&pwh, g_pwh);
    cudaGetSymbolAddress((void**)&qhi, g_qhi);
    cudaGetSymbolAddress((void**)&qlo, g_qlo);
    cudaGetSymbolAddress((void**)&khi, g_khi);
    cudaGetSymbolAddress((void**)&klo, g_klo);
    cudaGetSymbolAddress((void**)&vh,  g_v);
    cudaGetSymbolAddress((void**)&biasAll, g_bias);

    cudaFuncSetAttribute(gemm_f16<0>,
                         cudaFuncAttributeMaxDynamicSharedMemorySize, GEMM_SMEM_BYTES);
    cudaFuncSetAttribute(gemm_f16<1>,
                         cudaFuncAttributeMaxDynamicSharedMemorySize, GEMM_SMEM_BYTES);

    // 0) bias precompute + fp16 conversions
    bias_pre<<<NW * H, 256>>>(mask, rpb_table, rel_index, biasAll);
    {
        int n4 = MROWS * DIM / 4;
        cvt_f16<<<(n4 + 255) / 256, 256>>>((const float4*)x, (uint2*)xh, n4);
        n4 = QKV_COLS * DIM / 4;
        cvt_f16<<<(n4 + 255) / 256, 256>>>((const float4*)qkv_w, (uint2*)wh, n4);
        n4 = DIM * DIM / 4;
        cvt_f16<<<(n4 + 255) / 256, 256>>>((const float4*)proj_w, (uint2*)pwh, n4);
    }
    // 1) QKV projection with fused split-q/k/v epilogue
    {
        dim3 grid(QKV_COLS / 128, MROWS / 128);
        gemm_f16<1><<<grid, 256, GEMM_SMEM_BYTES>>>(xh, wh, qkv_b, nullptr,
                                                    qhi, qlo, khi, klo, vh,
                                                    MROWS, QKV_COLS, DIM);
    }
    // 2) attention
    attn_f16<<<NBH, 128>>>(qhi, qlo, khi, klo, vh, biasAll, aoh);
    // 3) output projection
    {
        dim3 grid(DIM / 128, MROWS / 128);
        gemm_f16<0><<<grid, 256, GEMM_SMEM_BYTES>>>(aoh, pwh, proj_b, out,
                                                    nullptr, nullptr, nullptr, nullptr, nullptr,
                                                    MROWS, DIM, DIM);
    }
}

// round 10
// speedup vs baseline: 7.9327x; 1.0645x over previous
#include <cuda_runtime.h>
#include <cuda_fp16.h>
#include <cstdint>

// Problem constants
#define NTOK 49
#define DIM 256
#define H 8
#define DH 32
#define BWIN 2048
#define NW 64
#define QKV_COLS 768
#define MROWS (BWIN * NTOK)  // 100352
#define NBH (BWIN * H)       // 16384
#define BPAD 2404            // padded bias tile stride (floats), 9616B = 16B-aligned

// Scratch (device globals; no allocation allowed)
__device__ __half g_xh[(size_t)MROWS * DIM];
__device__ __half g_attn_outh[(size_t)MROWS * DIM];
__device__ __half g_wh[QKV_COLS * DIM];
__device__ __half g_pwh[DIM * DIM];
__device__ float  g_bias[(size_t)NW * H * BPAD];
// per-(window,head) fp16 q/k/v: [bh][49][32]
__device__ __half g_qhi[(size_t)NBH * NTOK * DH];
__device__ __half g_qlo[(size_t)NBH * NTOK * DH];
__device__ __half g_khi[(size_t)NBH * NTOK * DH];
__device__ __half g_klo[(size_t)NBH * NTOK * DH];
__device__ __half g_v  [(size_t)NBH * NTOK * DH];

#define ATT_SCALE 0.17677669529663687f

// ---------------------------------------------------------------------------
// Helpers
// ---------------------------------------------------------------------------
__device__ __forceinline__ void cp_async16(uint32_t s, const void* g) {
    asm volatile("cp.async.cg.shared.global [%0], [%1], 16;" :: "r"(s), "l"(g));
}
__device__ __forceinline__ void cp_commit() {
    asm volatile("cp.async.commit_group;");
}
template<int Nw> __device__ __forceinline__ void cp_wait() {
    asm volatile("cp.async.wait_group %0;" :: "n"(Nw));
}
__device__ __forceinline__ void mma_f16(float c[4], const uint32_t a[4], const uint32_t b[2]) {
    asm volatile(
        "mma.sync.aligned.m16n8k16.row.col.f32.f16.f16.f32 "
        "{%0,%1,%2,%3}, {%4,%5,%6,%7}, {%8,%9}, {%0,%1,%2,%3};"
        : "+f"(c[0]), "+f"(c[1]), "+f"(c[2]), "+f"(c[3])
        : "r"(a[0]), "r"(a[1]), "r"(a[2]), "r"(a[3]), "r"(b[0]), "r"(b[1]));
}
__device__ __forceinline__ void ldm_x4(uint32_t& r0, uint32_t& r1, uint32_t& r2, uint32_t& r3,
                                       uint32_t addr) {
    asm volatile("ldmatrix.sync.aligned.m8n8.x4.shared.b16 {%0,%1,%2,%3}, [%4];"
                 : "=r"(r0), "=r"(r1), "=r"(r2), "=r"(r3) : "r"(addr));
}
__device__ __forceinline__ void ldm_x4_t(uint32_t& r0, uint32_t& r1, uint32_t& r2, uint32_t& r3,
                                         uint32_t addr) {
    asm volatile("ldmatrix.sync.aligned.m8n8.x4.trans.shared.b16 {%0,%1,%2,%3}, [%4];"
                 : "=r"(r0), "=r"(r1), "=r"(r2), "=r"(r3) : "r"(addr));
}
__device__ __forceinline__ uint32_t smem_u32(const void* p) {
    uint32_t a;
    asm("{ .reg .u64 t; cvta.to.shared.u64 t, %1; cvt.u32.u64 %0, t; }" : "=r"(a) : "l"(p));
    return a;
}
__device__ __forceinline__ uint32_t pack_h2(float a, float b) {
    __half2 h = __floats2half2_rn(a, b);
    return *reinterpret_cast<uint32_t*>(&h);
}
// 64B-row tile swizzle (attention tiles)
#define SWZ(row, kc) ((uint32_t)(((row) << 6) + ((((kc) ^ (((row) >> 1) & 3))) << 4)))
// 128B-row tile swizzle (GEMM BK=64 tiles)
#define SWZ64(row, kc) ((uint32_t)(((row) << 7) + ((((kc) ^ ((row) & 7))) << 4)))

// ---------------------------------------------------------------------------
// fused fp32 -> fp16 conversion for x, qkv_w, proj_w (single launch)
// ---------------------------------------------------------------------------
__global__ __launch_bounds__(256) void cvt_f16_all(
    const float4* __restrict__ sa, uint2* __restrict__ da, int na,
    const float4* __restrict__ sb2, uint2* __restrict__ db, int nb,
    const float4* __restrict__ sc, uint2* __restrict__ dc, int nc)
{
    const int total = na + nb + nc;
    for (int i = blockIdx.x * blockDim.x + threadIdx.x; i < total;
         i += gridDim.x * blockDim.x) {
        const float4* s;
        uint2* d;
        int j = i;
        if (j < na)            { s = sa;  d = da; }
        else if (j < na + nb)  { s = sb2; d = db; j -= na; }
        else                   { s = sc;  d = dc; j -= na + nb; }
        float4 v = s[j];
        d[j] = make_uint2(pack_h2(v.x, v.y), pack_h2(v.z, v.w));
    }
}

// ---------------------------------------------------------------------------
// Bias precompute (padded stride BPAD)
// ---------------------------------------------------------------------------
__global__ __launch_bounds__(256) void bias_pre(
    const float* __restrict__ mask, const float* __restrict__ rpb,
    const int* __restrict__ ridx, float* __restrict__ biasAll)
{
    const int wh = blockIdx.x;
    const int w = wh >> 3, h = wh & 7;
    const float* m = mask + (size_t)w * (NTOK * NTOK);
    float* o = biasAll + (size_t)wh * BPAD;
    for (int ij = threadIdx.x; ij < NTOK * NTOK; ij += 256)
        o[ij] = m[ij] + rpb[ridx[ij] * H + h];
}

// ---------------------------------------------------------------------------
// FP16 tensor-core NT GEMM. Block 128x128, BK=64, 8 warps (2m x 4n).
// MODE 0: C(fp32) = A*W^T + bias.  MODE 1: qkv epilogue -> split q/k/v halves.
// ---------------------------------------------------------------------------
#define G_STAGE 32768
#define GEMM_SMEM_BYTES (2 * G_STAGE)

template<int MODE>
__global__ __launch_bounds__(256, 2) void gemm_f16(
    const __half* __restrict__ A, const __half* __restrict__ W,
    const float* __restrict__ bias, float* __restrict__ C,
    __half* __restrict__ qhi, __half* __restrict__ qlo,
    __half* __restrict__ khi, __half* __restrict__ klo,
    __half* __restrict__ vh,
    int M, int N, int K)
{
    extern __shared__ __align__(16) char smem[];

    const int tid  = threadIdx.x;
    const int lane = tid & 31;
    const int warp = tid >> 5;
    const int wm = warp >> 2;
    const int wn = warp & 3;
    const int bm = blockIdx.y * 128;
    const int bn = blockIdx.x * 128;

    const uint32_t sb = smem_u32(smem);

    uint32_t dstA[4];
    const __half* srcA[4];
    const __half* srcB[4];
    #pragma unroll
    for (int t = 0; t < 4; t++) {
        const int chunk = tid + t * 256;
        const int row = chunk >> 3, kc = chunk & 7;
        dstA[t] = SWZ64(row, kc);
        srcA[t] = A + (size_t)(bm + row) * K + kc * 8;
        srcB[t] = W + (size_t)(bn + row) * K + kc * 8;
    }

    float acc[4][4][4];
    #pragma unroll
    for (int mt = 0; mt < 4; mt++)
        #pragma unroll
        for (int nt = 0; nt < 4; nt++)
            #pragma unroll
            for (int r = 0; r < 4; r++) acc[mt][nt][r] = 0.f;

    const int NS = K >> 6;

    #pragma unroll
    for (int t = 0; t < 4; t++) cp_async16(sb + dstA[t], srcA[t]);
    #pragma unroll
    for (int t = 0; t < 4; t++) cp_async16(sb + 16384 + dstA[t], srcB[t]);
    cp_commit();

    const int mat  = lane >> 3;
    const int lrow = lane & 7;

    for (int s = 0; s < NS; s++) {
        if (s + 1 < NS) {
            const int k0 = (s + 1) << 6;
            const uint32_t base = sb + ((s + 1) & 1) * G_STAGE;
            #pragma unroll
            for (int t = 0; t < 4; t++) cp_async16(base + dstA[t], srcA[t] + k0);
            #pragma unroll
            for (int t = 0; t < 4; t++) cp_async16(base + 16384 + dstA[t], srcB[t] + k0);
            cp_commit();
            cp_wait<1>();
        } else {
            cp_wait<0>();
        }
        __syncthreads();

        const uint32_t sA = sb + (s & 1) * G_STAGE;
        const uint32_t sB = sA + 16384;

        #pragma unroll
        for (int ks = 0; ks < 4; ks++) {
            uint32_t af[4][4], bf[4][2];
            #pragma unroll
            for (int mt = 0; mt < 4; mt++) {
                const int arow = wm * 64 + mt * 16 + ((mat & 1) << 3) + lrow;
                const int akc  = (ks << 1) + (mat >> 1);
                ldm_x4(af[mt][0], af[mt][1], af[mt][2], af[mt][3], sA + SWZ64(arow, akc));
            }
            #pragma unroll
            for (int nt2 = 0; nt2 < 2; nt2++) {
                const int brow = wn * 32 + (nt2 << 4) + ((mat >> 1) << 3) + lrow;
                const int bkc  = (ks << 1) + (mat & 1);
                ldm_x4(bf[nt2*2][0], bf[nt2*2][1], bf[nt2*2+1][0], bf[nt2*2+1][1],
                       sB + SWZ64(brow, bkc));
            }
            #pragma unroll
            for (int mt = 0; mt < 4; mt++)
                #pragma unroll
                for (int nt = 0; nt < 4; nt++)
                    mma_f16(acc[mt][nt], af[mt], bf[nt]);
        }
        __syncthreads();
    }

    const int group = lane >> 2, tig = lane & 3;
    if (MODE == 0) {
        #pragma unroll
        for (int mt = 0; mt < 4; mt++) {
            const int r = bm + wm * 64 + mt * 16 + group;
            #pragma unroll
            for (int nt = 0; nt < 4; nt++) {
                const int c = bn + wn * 32 + nt * 8 + tig * 2;
                const float bx = bias[c], by = bias[c + 1];
                *reinterpret_cast<float2*>(&C[(size_t)r * N + c]) =
                    make_float2(acc[mt][nt][0] + bx, acc[mt][nt][1] + by);
                *reinterpret_cast<float2*>(&C[(size_t)(r + 8) * N + c]) =
                    make_float2(acc[mt][nt][2] + bx, acc[mt][nt][3] + by);
            }
        }
    } else {
        #pragma unroll
        for (int mt = 0; mt < 4; mt++) {
            const int r = bm + wm * 64 + mt * 16 + group;
            const uint32_t bA = (uint32_t)r / 49u;
            const int tA = r - (int)bA * 49;
            const uint32_t bB = (uint32_t)(r + 8) / 49u;
            const int tB = (r + 8) - (int)bB * 49;
            #pragma unroll
            for (int nt = 0; nt < 4; nt++) {
                const int cc = bn + wn * 32 + nt * 8 + tig * 2;
                const int sidx = cc >> 8;
                const int hh = (cc >> 5) & 7;
                const int dd = cc & 31;
                float v0 = acc[mt][nt][0] + bias[cc];
                float v1 = acc[mt][nt][1] + bias[cc + 1];
                float v2 = acc[mt][nt][2] + bias[cc];
                float v3 = acc[mt][nt][3] + bias[cc + 1];
                const size_t iA = ((size_t)(bA * 8 + hh) * NTOK + tA) * DH + dd;
                const size_t iB = ((size_t)(bB * 8 + hh) * NTOK + tB) * DH + dd;
                if (sidx == 0) {
                    v0 *= ATT_SCALE; v1 *= ATT_SCALE; v2 *= ATT_SCALE; v3 *= ATT_SCALE;
                    __half2 hA = __floats2half2_rn(v0, v1);
                    float2 fA = __half22float2(hA);
                    __half2 lA = __floats2half2_rn(v0 - fA.x, v1 - fA.y);
                    __half2 hB = __floats2half2_rn(v2, v3);
                    float2 fB = __half22float2(hB);
                    __half2 lB = __floats2half2_rn(v2 - fB.x, v3 - fB.y);
                    *reinterpret_cast<__half2*>(&qhi[iA]) = hA;
                    *reinterpret_cast<__half2*>(&qlo[iA]) = lA;
                    *reinterpret_cast<__half2*>(&qhi[iB]) = hB;
                    *reinterpret_cast<__half2*>(&qlo[iB]) = lB;
                } else if (sidx == 1) {
                    __half2 hA = __floats2half2_rn(v0, v1);
                    float2 fA = __half22float2(hA);
                    __half2 lA = __floats2half2_rn(v0 - fA.x, v1 - fA.y);
                    __half2 hB = __floats2half2_rn(v2, v3);
                    float2 fB = __half22float2(hB);
                    __half2 lB = __floats2half2_rn(v2 - fB.x, v3 - fB.y);
                    *reinterpret_cast<__half2*>(&khi[iA]) = hA;
                    *reinterpret_cast<__half2*>(&klo[iA]) = lA;
                    *reinterpret_cast<__half2*>(&khi[iB]) = hB;
                    *reinterpret_cast<__half2*>(&klo[iB]) = lB;
                } else {
                    *reinterpret_cast<__half2*>(&vh[iA]) = __floats2half2_rn(v0, v1);
                    *reinterpret_cast<__half2*>(&vh[iB]) = __floats2half2_rn(v2, v3);
                }
            }
        }
    }
}

// ---------------------------------------------------------------------------
// Attention: fp16 fragments; bias staged to smem via cp.async.
// smem: 5 tiles (20KB) + bias tile (9.6KB).
// ---------------------------------------------------------------------------
#define BIAS_CHUNKS 601   // ceil(2401*4 / 16)

__global__ __launch_bounds__(128) void attn_f16(
    const __half* __restrict__ qhi, const __half* __restrict__ qlo,
    const __half* __restrict__ khi, const __half* __restrict__ klo,
    const __half* __restrict__ vh,
    const float* __restrict__ biasAll,
    __half* __restrict__ out)
{
    __shared__ __align__(16) char smem[5 * 4096 + BIAS_CHUNKS * 16];
    const uint32_t sb = smem_u32(smem);
    const uint32_t tQh = sb, tQl = sb + 4096, tKh = sb + 8192,
                   tKl = sb + 12288, tV = sb + 16384;
    const uint32_t tBias = sb + 5 * 4096;
    const float* bias_s = reinterpret_cast<const float*>(smem + 5 * 4096);

    const int bh = blockIdx.x;
    const int b = bh >> 3, h = bh & 7;
    const int tid = threadIdx.x;

    const size_t gbase = (size_t)bh * NTOK * DH;
    const __half* gp[5] = { qhi + gbase, qlo + gbase, khi + gbase, klo + gbase, vh + gbase };
    const float* bp = biasAll + (size_t)(((b & (NW - 1)) << 3) + h) * BPAD;

    // async fills: q/k/v tiles + bias tile
    #pragma unroll
    for (int buf = 0; buf < 5; buf++) {
        for (int i = tid; i < 196; i += 128) {
            const int row = i >> 2, kc = i & 3;
            cp_async16(sb + buf * 4096 + SWZ(row, kc), gp[buf] + row * DH + kc * 8);
        }
    }
    for (int i = tid; i < BIAS_CHUNKS; i += 128)
        cp_async16(tBias + i * 16, bp + i * 4);
    cp_commit();
    // zero pad rows 49..63 of q/k/v tiles
    for (int i = tid; i < 300; i += 128) {
        const int buf = i / 60, rem = i - buf * 60;
        const int row = 49 + (rem >> 2), kc = rem & 3;
        *reinterpret_cast<uint4*>(smem + buf * 4096 + SWZ(row, kc)) = make_uint4(0, 0, 0, 0);
    }
    cp_wait<0>();
    __syncthreads();

    const int warp = tid >> 5, lane = tid & 31;
    const int group = lane >> 2, tig = lane & 3;
    const int mat = lane >> 3, lrow = lane & 7;
    const int r0 = warp * 16 + group;

    // ---- QK^T: split-fp16 ----
    float acc[7][4];
    #pragma unroll
    for (int t = 0; t < 7; t++)
        #pragma unroll
        for (int r = 0; r < 4; r++) acc[t][r] = 0.f;

    #pragma unroll
    for (int kc16 = 0; kc16 < 2; kc16++) {
        const int arow = warp * 16 + ((mat & 1) << 3) + lrow;
        const int akc  = kc16 * 2 + (mat >> 1);
        uint32_t ah[4], al[4];
        ldm_x4(ah[0], ah[1], ah[2], ah[3], tQh + SWZ(arow, akc));
        ldm_x4(al[0], al[1], al[2], al[3], tQl + SWZ(arow, akc));
        #pragma unroll
        for (int g4 = 0; g4 < 4; g4++) {
            const int brow = g4 * 16 + ((mat >> 1) << 3) + lrow;
            const int bkc  = kc16 * 2 + (mat & 1);
            uint32_t bh2[2][2], bl2[2][2];
            ldm_x4(bh2[0][0], bh2[0][1], bh2[1][0], bh2[1][1], tKh + SWZ(brow, bkc));
            ldm_x4(bl2[0][0], bl2[0][1], bl2[1][0], bl2[1][1], tKl + SWZ(brow, bkc));
            #pragma unroll
            for (int u = 0; u < 2; u++) {
                const int t = g4 * 2 + u;
                if (t < 7) {
                    mma_f16(acc[t], ah, bh2[u]);
                    mma_f16(acc[t], ah, bl2[u]);
                    mma_f16(acc[t], al, bh2[u]);
                }
            }
        }
    }

    // ---- bias (from smem) + masked softmax in registers ----
    const bool row0 = (r0 < NTOK);
    const bool row1 = (r0 + 8 < NTOK);
    float mx0 = -1e30f, mx1 = -1e30f;
    #pragma unroll
    for (int t = 0; t < 7; t++) {
        const int c0 = t * 8 + tig * 2;
        if (c0 < NTOK) {
            if (row0) { acc[t][0] += bias_s[r0 * NTOK + c0];       mx0 = fmaxf(mx0, acc[t][0]); }
            if (row1) { acc[t][2] += bias_s[(r0 + 8) * NTOK + c0]; mx1 = fmaxf(mx1, acc[t][2]); }
        }
        if (c0 + 1 < NTOK) {
            if (row0) { acc[t][1] += bias_s[r0 * NTOK + c0 + 1];       mx0 = fmaxf(mx0, acc[t][1]); }
            if (row1) { acc[t][3] += bias_s[(r0 + 8) * NTOK + c0 + 1]; mx1 = fmaxf(mx1, acc[t][3]); }
        }
    }
    mx0 = fmaxf(mx0, __shfl_xor_sync(0xffffffffu, mx0, 1));
    mx0 = fmaxf(mx0, __shfl_xor_sync(0xffffffffu, mx0, 2));
    mx1 = fmaxf(mx1, __shfl_xor_sync(0xffffffffu, mx1, 1));
    mx1 = fmaxf(mx1, __shfl_xor_sync(0xffffffffu, mx1, 2));
    if (mx0 < -1e29f) mx0 = 0.f;
    if (mx1 < -1e29f) mx1 = 0.f;

    float s0 = 0.f, s1 = 0.f;
    #pragma unroll
    for (int t = 0; t < 7; t++) {
        const int c0 = t * 8 + tig * 2;
        acc[t][0] = (c0     < NTOK) ? __expf(acc[t][0] - mx0) : 0.f;
        acc[t][1] = (c0 + 1 < NTOK) ? __expf(acc[t][1] - mx0) : 0.f;
        acc[t][2] = (c0     < NTOK) ? __expf(acc[t][2] - mx1) : 0.f;
        acc[t][3] = (c0 + 1 < NTOK) ? __expf(acc[t][3] - mx1) : 0.f;
        s0 += acc[t][0] + acc[t][1];
        s1 += acc[t][2] + acc[t][3];
    }
    s0 += __shfl_xor_sync(0xffffffffu, s0, 1);
    s0 += __shfl_xor_sync(0xffffffffu, s0, 2);
    s1 += __shfl_xor_sync(0xffffffffu, s1, 1);
    s1 += __shfl_xor_sync(0xffffffffu, s1, 2);
    const float inv0 = 1.f / s0;
    const float inv1 = 1.f / s1;

    // ---- AV: P in registers as fp16 A-frags; V via ldmatrix.trans ----
    uint32_t pa[4][4];
    #pragma unroll
    for (int kc = 0; kc < 4; kc++) {
        const int t0 = kc * 2, t1 = kc * 2 + 1;
        pa[kc][0] = pack_h2(acc[t0][0] * inv0, acc[t0][1] * inv0);
        pa[kc][1] = pack_h2(acc[t0][2] * inv1, acc[t0][3] * inv1);
        if (t1 < 7) {
            pa[kc][2] = pack_h2(acc[t1][0] * inv0, acc[t1][1] * inv0);
            pa[kc][3] = pack_h2(acc[t1][2] * inv1, acc[t1][3] * inv1);
        } else {
            pa[kc][2] = 0u;
            pa[kc][3] = 0u;
        }
    }

    float av[4][4];
    #pragma unroll
    for (int nt = 0; nt < 4; nt++)
        #pragma unroll
        for (int r = 0; r < 4; r++) av[nt][r] = 0.f;

    #pragma unroll
    for (int kc = 0; kc < 4; kc++) {
        #pragma unroll
        for (int d16 = 0; d16 < 2; d16++) {
            const int vrow = kc * 16 + ((mat & 1) << 3) + lrow;
            const int vkc  = d16 * 2 + (mat >> 1);
            uint32_t bf[2][2];
            ldm_x4_t(bf[0][0], bf[0][1], bf[1][0], bf[1][1], tV + SWZ(vrow, vkc));
            mma_f16(av[d16 * 2],     pa[kc], bf[0]);
            mma_f16(av[d16 * 2 + 1], pa[kc], bf[1]);
        }
    }

    __half* ob = out + (size_t)b * NTOK * DIM + h * DH;
    if (row0) {
        #pragma unroll
        for (int nt = 0; nt < 4; nt++) {
            const int d = nt * 8 + tig * 2;
            *reinterpret_cast<__half2*>(&ob[(size_t)r0 * DIM + d]) =
                __floats2half2_rn(av[nt][0], av[nt][1]);
        }
    }
    if (row1) {
        #pragma unroll
        for (int nt = 0; nt < 4; nt++) {
            const int d = nt * 8 + tig * 2;
            *reinterpret_cast<__half2*>(&ob[(size_t)(r0 + 8) * DIM + d]) =
                __floats2half2_rn(av[nt][2], av[nt][3]);
        }
    }
}

// ---------------------------------------------------------------------------
// Launch
// ---------------------------------------------------------------------------
extern "C" void kernel_launch(void* const* d_in, const int* in_sizes, int n_in,
                              void* d_out, int out_size) {
    const float* x         = (const float*)d_in[0];
    const float* mask      = (const float*)d_in[1];
    const float* qkv_w     = (const float*)d_in[2];
    const float* qkv_b     = (const float*)d_in[3];
    const float* proj_w    = (const float*)d_in[4];
    const float* proj_b    = (const float*)d_in[5];
    const float* rpb_table = (const float*)d_in[6];
    const int*   rel_index = (const int*)d_in[7];
    float* out = (float*)d_out;

    __half *xh, *aoh, *wh, *pwh, *qhi, *qlo, *khi, *klo, *vh;
    float *biasAll;
    cudaGetSymbolAddress((void**)&xh,  g_xh);
    cudaGetSymbolAddress((void**)&aoh, g_attn_outh);
    cudaGetSymbolAddress((void**)&wh,  g_wh);
    cudaGetSymbolAddress((void**)&pwh, g_pwh);
    cudaGetSymbolAddress((void**)&qhi, g_qhi);
    cudaGetSymbolAddress((void**)&qlo, g_qlo);
    cudaGetSymbolAddress((void**)&khi, g_khi);
    cudaGetSymbolAddress((void**)&klo, g_klo);
    cudaGetSymbolAddress((void**)&vh,  g_v);
    cudaGetSymbolAddress((void**)&biasAll, g_bias);

    cudaFuncSetAttribute(gemm_f16<0>,
                         cudaFuncAttributeMaxDynamicSharedMemorySize, GEMM_SMEM_BYTES);
    cudaFuncSetAttribute(gemm_f16<1>,
                         cudaFuncAttributeMaxDynamicSharedMemorySize, GEMM_SMEM_BYTES);

    // 0) bias precompute + fused fp16 conversions
    bias_pre<<<NW * H, 256>>>(mask, rpb_table, rel_index, biasAll);
    {
        const int na = MROWS * DIM / 4;
        const int nb = QKV_COLS * DIM / 4;
        const int nc = DIM * DIM / 4;
        const int total = na + nb + nc;
        cvt_f16_all<<<(total + 255) / 256, 256>>>(
            (const float4*)x, (uint2*)xh, na,
            (const float4*)qkv_w, (uint2*)wh, nb,
            (const float4*)proj_w, (uint2*)pwh, nc);
    }
    // 1) QKV projection with fused split-q/k/v epilogue
    {
        dim3 grid(QKV_COLS / 128, MROWS / 128);
        gemm_f16<1><<<grid, 256, GEMM_SMEM_BYTES>>>(xh, wh, qkv_b, nullptr,
                                                    qhi, qlo, khi, klo, vh,
                                                    MROWS, QKV_COLS, DIM);
    }
    // 2) attention
    attn_f16<<<NBH, 128>>>(qhi, qlo, khi, klo, vh, biasAll, aoh);
    // 3) output projection
    {
        dim3 grid(DIM / 128, MROWS / 128);
        gemm_f16<0><<<grid, 256, GEMM_SMEM_BYTES>>>(aoh, pwh, proj_b, out,
                                                    nullptr, nullptr, nullptr, nullptr, nullptr,
                                                    MROWS, DIM, DIM);
    }
}

// round 11
// speedup vs baseline: 8.9292x; 1.1256x over previous
#include <cuda_runtime.h>
#include <cuda_fp16.h>
#include <cstdint>

// Problem constants
#define NTOK 49
#define DIM 256
#define H 8
#define DH 32
#define BWIN 2048
#define NW 64
#define QKV_COLS 768
#define MROWS (BWIN * NTOK)  // 100352
#define NBH (BWIN * H)       // 16384
#define BPAD 2404            // padded bias tile stride (floats)

// Scratch (device globals; no allocation allowed)
__device__ __half g_xh[(size_t)MROWS * DIM];
__device__ __half g_attn_outh[(size_t)MROWS * DIM];
__device__ __half g_wh[QKV_COLS * DIM];
__device__ __half g_pwh[DIM * DIM];
__device__ float  g_bias[(size_t)NW * H * BPAD];
// per-(window,head) fp16 q/k/v: [bh][49][32]
__device__ __half g_q[(size_t)NBH * NTOK * DH];
__device__ __half g_k[(size_t)NBH * NTOK * DH];
__device__ __half g_v[(size_t)NBH * NTOK * DH];

#define ATT_SCALE 0.17677669529663687f

// ---------------------------------------------------------------------------
// Helpers
// ---------------------------------------------------------------------------
__device__ __forceinline__ void cp_async16(uint32_t s, const void* g) {
    asm volatile("cp.async.cg.shared.global [%0], [%1], 16;" :: "r"(s), "l"(g));
}
__device__ __forceinline__ void cp_commit() {
    asm volatile("cp.async.commit_group;");
}
template<int Nw> __device__ __forceinline__ void cp_wait() {
    asm volatile("cp.async.wait_group %0;" :: "n"(Nw));
}
__device__ __forceinline__ void mma_f16(float c[4], const uint32_t a[4], const uint32_t b[2]) {
    asm volatile(
        "mma.sync.aligned.m16n8k16.row.col.f32.f16.f16.f32 "
        "{%0,%1,%2,%3}, {%4,%5,%6,%7}, {%8,%9}, {%0,%1,%2,%3};"
        : "+f"(c[0]), "+f"(c[1]), "+f"(c[2]), "+f"(c[3])
        : "r"(a[0]), "r"(a[1]), "r"(a[2]), "r"(a[3]), "r"(b[0]), "r"(b[1]));
}
__device__ __forceinline__ void ldm_x4(uint32_t& r0, uint32_t& r1, uint32_t& r2, uint32_t& r3,
                                       uint32_t addr) {
    asm volatile("ldmatrix.sync.aligned.m8n8.x4.shared.b16 {%0,%1,%2,%3}, [%4];"
                 : "=r"(r0), "=r"(r1), "=r"(r2), "=r"(r3) : "r"(addr));
}
__device__ __forceinline__ void ldm_x4_t(uint32_t& r0, uint32_t& r1, uint32_t& r2, uint32_t& r3,
                                         uint32_t addr) {
    asm volatile("ldmatrix.sync.aligned.m8n8.x4.trans.shared.b16 {%0,%1,%2,%3}, [%4];"
                 : "=r"(r0), "=r"(r1), "=r"(r2), "=r"(r3) : "r"(addr));
}
__device__ __forceinline__ uint32_t smem_u32(const void* p) {
    uint32_t a;
    asm("{ .reg .u64 t; cvta.to.shared.u64 t, %1; cvt.u32.u64 %0, t; }" : "=r"(a) : "l"(p));
    return a;
}
__device__ __forceinline__ uint32_t pack_h2(float a, float b) {
    __half2 h = __floats2half2_rn(a, b);
    return *reinterpret_cast<uint32_t*>(&h);
}
// 64B-row tile swizzle (attention tiles)
#define SWZ(row, kc) ((uint32_t)(((row) << 6) + ((((kc) ^ (((row) >> 1) & 3))) << 4)))
// 128B-row tile swizzle (GEMM BK=64 tiles)
#define SWZ64(row, kc) ((uint32_t)(((row) << 7) + ((((kc) ^ ((row) & 7))) << 4)))

// ---------------------------------------------------------------------------
// fused fp32 -> fp16 conversion for x, qkv_w, proj_w (single launch)
// ---------------------------------------------------------------------------
__global__ __launch_bounds__(256) void cvt_f16_all(
    const float4* __restrict__ sa, uint2* __restrict__ da, int na,
    const float4* __restrict__ sb2, uint2* __restrict__ db, int nb,
    const float4* __restrict__ sc, uint2* __restrict__ dc, int nc)
{
    const int total = na + nb + nc;
    for (int i = blockIdx.x * blockDim.x + threadIdx.x; i < total;
         i += gridDim.x * blockDim.x) {
        const float4* s;
        uint2* d;
        int j = i;
        if (j < na)            { s = sa;  d = da; }
        else if (j < na + nb)  { s = sb2; d = db; j -= na; }
        else                   { s = sc;  d = dc; j -= na + nb; }
        float4 v = s[j];
        d[j] = make_uint2(pack_h2(v.x, v.y), pack_h2(v.z, v.w));
    }
}

// ---------------------------------------------------------------------------
// Bias precompute (padded stride BPAD)
// ---------------------------------------------------------------------------
__global__ __launch_bounds__(256) void bias_pre(
    const float* __restrict__ mask, const float* __restrict__ rpb,
    const int* __restrict__ ridx, float* __restrict__ biasAll)
{
    const int wh = blockIdx.x;
    const int w = wh >> 3, h = wh & 7;
    const float* m = mask + (size_t)w * (NTOK * NTOK);
    float* o = biasAll + (size_t)wh * BPAD;
    for (int ij = threadIdx.x; ij < NTOK * NTOK; ij += 256)
        o[ij] = m[ij] + rpb[ridx[ij] * H + h];
}

// ---------------------------------------------------------------------------
// FP16 tensor-core NT GEMM. Block 128x128, BK=64, 8 warps (2m x 4n).
// MODE 0: C(fp32) = A*W^T + bias.  MODE 1: qkv epilogue -> q(scaled)/k/v fp16.
// ---------------------------------------------------------------------------
#define G_STAGE 32768
#define GEMM_SMEM_BYTES (2 * G_STAGE)

template<int MODE>
__global__ __launch_bounds__(256, 2) void gemm_f16(
    const __half* __restrict__ A, const __half* __restrict__ W,
    const float* __restrict__ bias, float* __restrict__ C,
    __half* __restrict__ qh, __half* __restrict__ kh, __half* __restrict__ vh,
    int M, int N, int K)
{
    extern __shared__ __align__(16) char smem[];

    const int tid  = threadIdx.x;
    const int lane = tid & 31;
    const int warp = tid >> 5;
    const int wm = warp >> 2;
    const int wn = warp & 3;
    const int bm = blockIdx.y * 128;
    const int bn = blockIdx.x * 128;

    const uint32_t sb = smem_u32(smem);

    uint32_t dstA[4];
    const __half* srcA[4];
    const __half* srcB[4];
    #pragma unroll
    for (int t = 0; t < 4; t++) {
        const int chunk = tid + t * 256;
        const int row = chunk >> 3, kc = chunk & 7;
        dstA[t] = SWZ64(row, kc);
        srcA[t] = A + (size_t)(bm + row) * K + kc * 8;
        srcB[t] = W + (size_t)(bn + row) * K + kc * 8;
    }

    float acc[4][4][4];
    #pragma unroll
    for (int mt = 0; mt < 4; mt++)
        #pragma unroll
        for (int nt = 0; nt < 4; nt++)
            #pragma unroll
            for (int r = 0; r < 4; r++) acc[mt][nt][r] = 0.f;

    const int NS = K >> 6;

    #pragma unroll
    for (int t = 0; t < 4; t++) cp_async16(sb + dstA[t], srcA[t]);
    #pragma unroll
    for (int t = 0; t < 4; t++) cp_async16(sb + 16384 + dstA[t], srcB[t]);
    cp_commit();

    const int mat  = lane >> 3;
    const int lrow = lane & 7;

    for (int s = 0; s < NS; s++) {
        if (s + 1 < NS) {
            const int k0 = (s + 1) << 6;
            const uint32_t base = sb + ((s + 1) & 1) * G_STAGE;
            #pragma unroll
            for (int t = 0; t < 4; t++) cp_async16(base + dstA[t], srcA[t] + k0);
            #pragma unroll
            for (int t = 0; t < 4; t++) cp_async16(base + 16384 + dstA[t], srcB[t] + k0);
            cp_commit();
            cp_wait<1>();
        } else {
            cp_wait<0>();
        }
        __syncthreads();

        const uint32_t sA = sb + (s & 1) * G_STAGE;
        const uint32_t sB = sA + 16384;

        #pragma unroll
        for (int ks = 0; ks < 4; ks++) {
            uint32_t af[4][4], bf[4][2];
            #pragma unroll
            for (int mt = 0; mt < 4; mt++) {
                const int arow = wm * 64 + mt * 16 + ((mat & 1) << 3) + lrow;
                const int akc  = (ks << 1) + (mat >> 1);
                ldm_x4(af[mt][0], af[mt][1], af[mt][2], af[mt][3], sA + SWZ64(arow, akc));
            }
            #pragma unroll
            for (int nt2 = 0; nt2 < 2; nt2++) {
                const int brow = wn * 32 + (nt2 << 4) + ((mat >> 1) << 3) + lrow;
                const int bkc  = (ks << 1) + (mat & 1);
                ldm_x4(bf[nt2*2][0], bf[nt2*2][1], bf[nt2*2+1][0], bf[nt2*2+1][1],
                       sB + SWZ64(brow, bkc));
            }
            #pragma unroll
            for (int mt = 0; mt < 4; mt++)
                #pragma unroll
                for (int nt = 0; nt < 4; nt++)
                    mma_f16(acc[mt][nt], af[mt], bf[nt]);
        }
        __syncthreads();
    }

    const int group = lane >> 2, tig = lane & 3;
    if (MODE == 0) {
        #pragma unroll
        for (int mt = 0; mt < 4; mt++) {
            const int r = bm + wm * 64 + mt * 16 + group;
            #pragma unroll
            for (int nt = 0; nt < 4; nt++) {
                const int c = bn + wn * 32 + nt * 8 + tig * 2;
                const float bx = bias[c], by = bias[c + 1];
                *reinterpret_cast<float2*>(&C[(size_t)r * N + c]) =
                    make_float2(acc[mt][nt][0] + bx, acc[mt][nt][1] + by);
                *reinterpret_cast<float2*>(&C[(size_t)(r + 8) * N + c]) =
                    make_float2(acc[mt][nt][2] + bx, acc[mt][nt][3] + by);
            }
        }
    } else {
        #pragma unroll
        for (int mt = 0; mt < 4; mt++) {
            const int r = bm + wm * 64 + mt * 16 + group;
            const uint32_t bA = (uint32_t)r / 49u;
            const int tA = r - (int)bA * 49;
            const uint32_t bB = (uint32_t)(r + 8) / 49u;
            const int tB = (r + 8) - (int)bB * 49;
            #pragma unroll
            for (int nt = 0; nt < 4; nt++) {
                const int cc = bn + wn * 32 + nt * 8 + tig * 2;
                const int sidx = cc >> 8;
                const int hh = (cc >> 5) & 7;
                const int dd = cc & 31;
                float v0 = acc[mt][nt][0] + bias[cc];
                float v1 = acc[mt][nt][1] + bias[cc + 1];
                float v2 = acc[mt][nt][2] + bias[cc];
                float v3 = acc[mt][nt][3] + bias[cc + 1];
                const size_t iA = ((size_t)(bA * 8 + hh) * NTOK + tA) * DH + dd;
                const size_t iB = ((size_t)(bB * 8 + hh) * NTOK + tB) * DH + dd;
                if (sidx == 0) {
                    v0 *= ATT_SCALE; v1 *= ATT_SCALE; v2 *= ATT_SCALE; v3 *= ATT_SCALE;
                    *reinterpret_cast<__half2*>(&qh[iA]) = __floats2half2_rn(v0, v1);
                    *reinterpret_cast<__half2*>(&qh[iB]) = __floats2half2_rn(v2, v3);
                } else if (sidx == 1) {
                    *reinterpret_cast<__half2*>(&kh[iA]) = __floats2half2_rn(v0, v1);
                    *reinterpret_cast<__half2*>(&kh[iB]) = __floats2half2_rn(v2, v3);
                } else {
                    *reinterpret_cast<__half2*>(&vh[iA]) = __floats2half2_rn(v0, v1);
                    *reinterpret_cast<__half2*>(&vh[iB]) = __floats2half2_rn(v2, v3);
                }
            }
        }
    }
}

// ---------------------------------------------------------------------------
// Attention: plain fp16 q/k/v; bias staged to smem via cp.async.
// smem: 3 tiles (12KB) + bias tile (9.6KB) = 21.9 KB.
// ---------------------------------------------------------------------------
#define BIAS_CHUNKS 601   // ceil(2401*4 / 16)

__global__ __launch_bounds__(128) void attn_f16(
    const __half* __restrict__ qh, const __half* __restrict__ kh,
    const __half* __restrict__ vh,
    const float* __restrict__ biasAll,
    __half* __restrict__ out)
{
    __shared__ __align__(16) char smem[3 * 4096 + BIAS_CHUNKS * 16];
    const uint32_t sb = smem_u32(smem);
    const uint32_t tQ = sb, tK = sb + 4096, tV = sb + 8192;
    const uint32_t tBias = sb + 3 * 4096;
    const float* bias_s = reinterpret_cast<const float*>(smem + 3 * 4096);

    const int bh = blockIdx.x;
    const int b = bh >> 3, h = bh & 7;
    const int tid = threadIdx.x;

    const size_t gbase = (size_t)bh * NTOK * DH;
    const __half* gp[3] = { qh + gbase, kh + gbase, vh + gbase };
    const float* bp = biasAll + (size_t)(((b & (NW - 1)) << 3) + h) * BPAD;

    // async fills: q/k/v tiles + bias tile
    #pragma unroll
    for (int buf = 0; buf < 3; buf++) {
        for (int i = tid; i < 196; i += 128) {
            const int row = i >> 2, kc = i & 3;
            cp_async16(sb + buf * 4096 + SWZ(row, kc), gp[buf] + row * DH + kc * 8);
        }
    }
    for (int i = tid; i < BIAS_CHUNKS; i += 128)
        cp_async16(tBias + i * 16, bp + i * 4);
    cp_commit();
    // zero pad rows 49..63 of q/k/v tiles
    for (int i = tid; i < 180; i += 128) {
        const int buf = i / 60, rem = i - buf * 60;
        const int row = 49 + (rem >> 2), kc = rem & 3;
        *reinterpret_cast<uint4*>(smem + buf * 4096 + SWZ(row, kc)) = make_uint4(0, 0, 0, 0);
    }
    cp_wait<0>();
    __syncthreads();

    const int warp = tid >> 5, lane = tid & 31;
    const int group = lane >> 2, tig = lane & 3;
    const int mat = lane >> 3, lrow = lane & 7;
    const int r0 = warp * 16 + group;

    // ---- QK^T: fp16 ----
    float acc[7][4];
    #pragma unroll
    for (int t = 0; t < 7; t++)
        #pragma unroll
        for (int r = 0; r < 4; r++) acc[t][r] = 0.f;

    #pragma unroll
    for (int kc16 = 0; kc16 < 2; kc16++) {
        const int arow = warp * 16 + ((mat & 1) << 3) + lrow;
        const int akc  = kc16 * 2 + (mat >> 1);
        uint32_t ah[4];
        ldm_x4(ah[0], ah[1], ah[2], ah[3], tQ + SWZ(arow, akc));
        #pragma unroll
        for (int g4 = 0; g4 < 4; g4++) {
            const int brow = g4 * 16 + ((mat >> 1) << 3) + lrow;
            const int bkc  = kc16 * 2 + (mat & 1);
            uint32_t bh2[2][2];
            ldm_x4(bh2[0][0], bh2[0][1], bh2[1][0], bh2[1][1], tK + SWZ(brow, bkc));
            #pragma unroll
            for (int u = 0; u < 2; u++) {
                const int t = g4 * 2 + u;
                if (t < 7) mma_f16(acc[t], ah, bh2[u]);
            }
        }
    }

    // ---- bias (from smem) + masked softmax in registers ----
    const bool row0 = (r0 < NTOK);
    const bool row1 = (r0 + 8 < NTOK);
    float mx0 = -1e30f, mx1 = -1e30f;
    #pragma unroll
    for (int t = 0; t < 7; t++) {
        const int c0 = t * 8 + tig * 2;
        if (c0 < NTOK) {
            if (row0) { acc[t][0] += bias_s[r0 * NTOK + c0];       mx0 = fmaxf(mx0, acc[t][0]); }
            if (row1) { acc[t][2] += bias_s[(r0 + 8) * NTOK + c0]; mx1 = fmaxf(mx1, acc[t][2]); }
        }
        if (c0 + 1 < NTOK) {
            if (row0) { acc[t][1] += bias_s[r0 * NTOK + c0 + 1];       mx0 = fmaxf(mx0, acc[t][1]); }
            if (row1) { acc[t][3] += bias_s[(r0 + 8) * NTOK + c0 + 1]; mx1 = fmaxf(mx1, acc[t][3]); }
        }
    }
    mx0 = fmaxf(mx0, __shfl_xor_sync(0xffffffffu, mx0, 1));
    mx0 = fmaxf(mx0, __shfl_xor_sync(0xffffffffu, mx0, 2));
    mx1 = fmaxf(mx1, __shfl_xor_sync(0xffffffffu, mx1, 1));
    mx1 = fmaxf(mx1, __shfl_xor_sync(0xffffffffu, mx1, 2));
    if (mx0 < -1e29f) mx0 = 0.f;
    if (mx1 < -1e29f) mx1 = 0.f;

    float s0 = 0.f, s1 = 0.f;
    #pragma unroll
    for (int t = 0; t < 7; t++) {
        const int c0 = t * 8 + tig * 2;
        acc[t][0] = (c0     < NTOK) ? __expf(acc[t][0] - mx0) : 0.f;
        acc[t][1] = (c0 + 1 < NTOK) ? __expf(acc[t][1] - mx0) : 0.f;
        acc[t][2] = (c0     < NTOK) ? __expf(acc[t][2] - mx1) : 0.f;
        acc[t][3] = (c0 + 1 < NTOK) ? __expf(acc[t][3] - mx1) : 0.f;
        s0 += acc[t][0] + acc[t][1];
        s1 += acc[t][2] + acc[t][3];
    }
    s0 += __shfl_xor_sync(0xffffffffu, s0, 1);
    s0 += __shfl_xor_sync(0xffffffffu, s0, 2);
    s1 += __shfl_xor_sync(0xffffffffu, s1, 1);
    s1 += __shfl_xor_sync(0xffffffffu, s1, 2);
    const float inv0 = 1.f / s0;
    const float inv1 = 1.f / s1;

    // ---- AV: P in registers as fp16 A-frags; V via ldmatrix.trans ----
    uint32_t pa[4][4];
    #pragma unroll
    for (int kc = 0; kc < 4; kc++) {
        const int t0 = kc * 2, t1 = kc * 2 + 1;
        pa[kc][0] = pack_h2(acc[t0][0] * inv0, acc[t0][1] * inv0);
        pa[kc][1] = pack_h2(acc[t0][2] * inv1, acc[t0][3] * inv1);
        if (t1 < 7) {
            pa[kc][2] = pack_h2(acc[t1][0] * inv0, acc[t1][1] * inv0);
            pa[kc][3] = pack_h2(acc[t1][2] * inv1, acc[t1][3] * inv1);
        } else {
            pa[kc][2] = 0u;
            pa[kc][3] = 0u;
        }
    }

    float av[4][4];
    #pragma unroll
    for (int nt = 0; nt < 4; nt++)
        #pragma unroll
        for (int r = 0; r < 4; r++) av[nt][r] = 0.f;

    #pragma unroll
    for (int kc = 0; kc < 4; kc++) {
        #pragma unroll
        for (int d16 = 0; d16 < 2; d16++) {
            const int vrow = kc * 16 + ((mat & 1) << 3) + lrow;
            const int vkc  = d16 * 2 + (mat >> 1);
            uint32_t bf[2][2];
            ldm_x4_t(bf[0][0], bf[0][1], bf[1][0], bf[1][1], tV + SWZ(vrow, vkc));
            mma_f16(av[d16 * 2],     pa[kc], bf[0]);
            mma_f16(av[d16 * 2 + 1], pa[kc], bf[1]);
        }
    }

    __half* ob = out + (size_t)b * NTOK * DIM + h * DH;
    if (row0) {
        #pragma unroll
        for (int nt = 0; nt < 4; nt++) {
            const int d = nt * 8 + tig * 2;
            *reinterpret_cast<__half2*>(&ob[(size_t)r0 * DIM + d]) =
                __floats2half2_rn(av[nt][0], av[nt][1]);
        }
    }
    if (row1) {
        #pragma unroll
        for (int nt = 0; nt < 4; nt++) {
            const int d = nt * 8 + tig * 2;
            *reinterpret_cast<__half2*>(&ob[(size_t)(r0 + 8) * DIM + d]) =
                __floats2half2_rn(av[nt][2], av[nt][3]);
        }
    }
}

// ---------------------------------------------------------------------------
// Launch
// ---------------------------------------------------------------------------
extern "C" void kernel_launch(void* const* d_in, const int* in_sizes, int n_in,
                              void* d_out, int out_size) {
    const float* x         = (const float*)d_in[0];
    const float* mask      = (const float*)d_in[1];
    const float* qkv_w     = (const float*)d_in[2];
    const float* qkv_b     = (const float*)d_in[3];
    const float* proj_w    = (const float*)d_in[4];
    const float* proj_b    = (const float*)d_in[5];
    const float* rpb_table = (const float*)d_in[6];
    const int*   rel_index = (const int*)d_in[7];
    float* out = (float*)d_out;

    __half *xh, *aoh, *wh, *pwh, *qh, *kh, *vh;
    float *biasAll;
    cudaGetSymbolAddress((void**)&xh,  g_xh);
    cudaGetSymbolAddress((void**)&aoh, g_attn_outh);
    cudaGetSymbolAddress((void**)&wh,  g_wh);
    cudaGetSymbolAddress((void**)&pwh, g_pwh);
    cudaGetSymbolAddress((void**)&qh,  g_q);
    cudaGetSymbolAddress((void**)&kh,  g_k);
    cudaGetSymbolAddress((void**)&vh,  g_v);
    cudaGetSymbolAddress((void**)&biasAll, g_bias);

    cudaFuncSetAttribute(gemm_f16<0>,
                         cudaFuncAttributeMaxDynamicSharedMemorySize, GEMM_SMEM_BYTES);
    cudaFuncSetAttribute(gemm_f16<1>,
                         cudaFuncAttributeMaxDynamicSharedMemorySize, GEMM_SMEM_BYTES);

    // 0) bias precompute + fused fp16 conversions
    bias_pre<<<NW * H, 256>>>(mask, rpb_table, rel_index, biasAll);
    {
        const int na = MROWS * DIM / 4;
        const int nb = QKV_COLS * DIM / 4;
        const int nc = DIM * DIM / 4;
        const int total = na + nb + nc;
        cvt_f16_all<<<(total + 255) / 256, 256>>>(
            (const float4*)x, (uint2*)xh, na,
            (const float4*)qkv_w, (uint2*)wh, nb,
            (const float4*)proj_w, (uint2*)pwh, nc);
    }
    // 1) QKV projection with fused q/k/v epilogue
    {
        dim3 grid(QKV_COLS / 128, MROWS / 128);
        gemm_f16<1><<<grid, 256, GEMM_SMEM_BYTES>>>(xh, wh, qkv_b, nullptr,
                                                    qh, kh, vh,
                                                    MROWS, QKV_COLS, DIM);
    }
    // 2) attention
    attn_f16<<<NBH, 128>>>(qh, kh, vh, biasAll, aoh);
    // 3) output projection
    {
        dim3 grid(DIM / 128, MROWS / 128);
        gemm_f16<0><<<grid, 256, GEMM_SMEM_BYTES>>>(aoh, pwh, proj_b, out,
                                                    nullptr, nullptr, nullptr,
                                                    MROWS, DIM, DIM);
    }
}

// round 12
// speedup vs baseline: 9.0096x; 1.0090x over previous
#include <cuda_runtime.h>
#include <cuda_fp16.h>
#include <cstdint>

// Problem constants
#define NTOK 49
#define DIM 256
#define H 8
#define DH 32
#define BWIN 2048
#define NW 64
#define QKV_COLS 768
#define MROWS (BWIN * NTOK)  // 100352
#define NBH (BWIN * H)       // 16384

// Scratch (device globals; no allocation allowed)
__device__ __half g_xh[(size_t)MROWS * DIM];
__device__ __half g_attn_outh[(size_t)MROWS * DIM];
__device__ __half g_wh[QKV_COLS * DIM];
__device__ __half g_pwh[DIM * DIM];
// bias in mma-fragment layout: [wh][warp(4)][t(7)][lane(32)] float4
__device__ float4 g_biasF[(size_t)NW * H * 4 * 7 * 32];
// per-(window,head) fp16 q/k/v: [bh][49][32]
__device__ __half g_q[(size_t)NBH * NTOK * DH];
__device__ __half g_k[(size_t)NBH * NTOK * DH];
__device__ __half g_v[(size_t)NBH * NTOK * DH];

#define ATT_SCALE 0.17677669529663687f

// ---------------------------------------------------------------------------
// Helpers
// ---------------------------------------------------------------------------
__device__ __forceinline__ void cp_async16(uint32_t s, const void* g) {
    asm volatile("cp.async.cg.shared.global [%0], [%1], 16;" :: "r"(s), "l"(g));
}
__device__ __forceinline__ void cp_commit() {
    asm volatile("cp.async.commit_group;");
}
template<int Nw> __device__ __forceinline__ void cp_wait() {
    asm volatile("cp.async.wait_group %0;" :: "n"(Nw));
}
__device__ __forceinline__ void mma_f16(float c[4], const uint32_t a[4], const uint32_t b[2]) {
    asm volatile(
        "mma.sync.aligned.m16n8k16.row.col.f32.f16.f16.f32 "
        "{%0,%1,%2,%3}, {%4,%5,%6,%7}, {%8,%9}, {%0,%1,%2,%3};"
        : "+f"(c[0]), "+f"(c[1]), "+f"(c[2]), "+f"(c[3])
        : "r"(a[0]), "r"(a[1]), "r"(a[2]), "r"(a[3]), "r"(b[0]), "r"(b[1]));
}
__device__ __forceinline__ void ldm_x4(uint32_t& r0, uint32_t& r1, uint32_t& r2, uint32_t& r3,
                                       uint32_t addr) {
    asm volatile("ldmatrix.sync.aligned.m8n8.x4.shared.b16 {%0,%1,%2,%3}, [%4];"
                 : "=r"(r0), "=r"(r1), "=r"(r2), "=r"(r3) : "r"(addr));
}
__device__ __forceinline__ void ldm_x4_t(uint32_t& r0, uint32_t& r1, uint32_t& r2, uint32_t& r3,
                                         uint32_t addr) {
    asm volatile("ldmatrix.sync.aligned.m8n8.x4.trans.shared.b16 {%0,%1,%2,%3}, [%4];"
                 : "=r"(r0), "=r"(r1), "=r"(r2), "=r"(r3) : "r"(addr));
}
__device__ __forceinline__ uint32_t smem_u32(const void* p) {
    uint32_t a;
    asm("{ .reg .u64 t; cvta.to.shared.u64 t, %1; cvt.u32.u64 %0, t; }" : "=r"(a) : "l"(p));
    return a;
}
__device__ __forceinline__ uint32_t pack_h2(float a, float b) {
    __half2 h = __floats2half2_rn(a, b);
    return *reinterpret_cast<uint32_t*>(&h);
}
// 64B-row tile swizzle (attention tiles)
#define SWZ(row, kc) ((uint32_t)(((row) << 6) + ((((kc) ^ (((row) >> 1) & 3))) << 4)))
// 128B-row tile swizzle (GEMM BK=64 tiles)
#define SWZ64(row, kc) ((uint32_t)(((row) << 7) + ((((kc) ^ ((row) & 7))) << 4)))

// ---------------------------------------------------------------------------
// fused fp32 -> fp16 conversion for x, qkv_w, proj_w (single launch)
// ---------------------------------------------------------------------------
__global__ __launch_bounds__(256) void cvt_f16_all(
    const float4* __restrict__ sa, uint2* __restrict__ da, int na,
    const float4* __restrict__ sb2, uint2* __restrict__ db, int nb,
    const float4* __restrict__ sc, uint2* __restrict__ dc, int nc)
{
    const int total = na + nb + nc;
    for (int i = blockIdx.x * blockDim.x + threadIdx.x; i < total;
         i += gridDim.x * blockDim.x) {
        const float4* s;
        uint2* d;
        int j = i;
        if (j < na)            { s = sa;  d = da; }
        else if (j < na + nb)  { s = sb2; d = db; j -= na; }
        else                   { s = sc;  d = dc; j -= na + nb; }
        float4 v = s[j];
        d[j] = make_uint2(pack_h2(v.x, v.y), pack_h2(v.z, v.w));
    }
}

// ---------------------------------------------------------------------------
// Bias precompute in mma fragment layout.
// One block per wh (=w*8+h), 128 threads = 4 warps x 32 lanes.
// biasF[((wh*4 + warp)*7 + t)*32 + lane] =
//   { bias(r0,c0), bias(r0,c0+1), bias(r0+8,c0), bias(r0+8,c0+1) }  (0 if OOB)
// where r0 = warp*16 + (lane>>2), c0 = t*8 + (lane&3)*2.
// ---------------------------------------------------------------------------
__global__ __launch_bounds__(128) void bias_pre_frag(
    const float* __restrict__ mask, const float* __restrict__ rpb,
    const int* __restrict__ ridx, float4* __restrict__ biasF)
{
    const int wh = blockIdx.x;
    const int w = wh >> 3, h = wh & 7;
    const float* m = mask + (size_t)w * (NTOK * NTOK);
    const int tid = threadIdx.x;
    const int warp = tid >> 5, lane = tid & 31;
    const int r0 = warp * 16 + (lane >> 2);
    const int r1 = r0 + 8;
    float4* o = biasF + ((size_t)wh * 4 + warp) * 7 * 32 + lane;

    #pragma unroll
    for (int t = 0; t < 7; t++) {
        const int c0 = t * 8 + (lane & 3) * 2;
        const int c1 = c0 + 1;
        float4 v = make_float4(0.f, 0.f, 0.f, 0.f);
        if (r0 < NTOK) {
            if (c0 < NTOK) v.x = m[r0 * NTOK + c0] + rpb[ridx[r0 * NTOK + c0] * H + h];
            if (c1 < NTOK) v.y = m[r0 * NTOK + c1] + rpb[ridx[r0 * NTOK + c1] * H + h];
        }
        if (r1 < NTOK) {
            if (c0 < NTOK) v.z = m[r1 * NTOK + c0] + rpb[ridx[r1 * NTOK + c0] * H + h];
            if (c1 < NTOK) v.w = m[r1 * NTOK + c1] + rpb[ridx[r1 * NTOK + c1] * H + h];
        }
        o[t * 32] = v;
    }
}

// ---------------------------------------------------------------------------
// FP16 tensor-core NT GEMM. Block 128x128, BK=64, 8 warps (2m x 4n).
// MODE 0: C(fp32) = A*W^T + bias.  MODE 1: qkv epilogue -> q(scaled)/k/v fp16.
// ---------------------------------------------------------------------------
#define G_STAGE 32768
#define GEMM_SMEM_BYTES (2 * G_STAGE)

template<int MODE>
__global__ __launch_bounds__(256, 2) void gemm_f16(
    const __half* __restrict__ A, const __half* __restrict__ W,
    const float* __restrict__ bias, float* __restrict__ C,
    __half* __restrict__ qh, __half* __restrict__ kh, __half* __restrict__ vh,
    int M, int N, int K)
{
    extern __shared__ __align__(16) char smem[];

    const int tid  = threadIdx.x;
    const int lane = tid & 31;
    const int warp = tid >> 5;
    const int wm = warp >> 2;
    const int wn = warp & 3;
    const int bm = blockIdx.y * 128;
    const int bn = blockIdx.x * 128;

    const uint32_t sb = smem_u32(smem);

    uint32_t dstA[4];
    const __half* srcA[4];
    const __half* srcB[4];
    #pragma unroll
    for (int t = 0; t < 4; t++) {
        const int chunk = tid + t * 256;
        const int row = chunk >> 3, kc = chunk & 7;
        dstA[t] = SWZ64(row, kc);
        srcA[t] = A + (size_t)(bm + row) * K + kc * 8;
        srcB[t] = W + (size_t)(bn + row) * K + kc * 8;
    }

    float acc[4][4][4];
    #pragma unroll
    for (int mt = 0; mt < 4; mt++)
        #pragma unroll
        for (int nt = 0; nt < 4; nt++)
            #pragma unroll
            for (int r = 0; r < 4; r++) acc[mt][nt][r] = 0.f;

    const int NS = K >> 6;

    #pragma unroll
    for (int t = 0; t < 4; t++) cp_async16(sb + dstA[t], srcA[t]);
    #pragma unroll
    for (int t = 0; t < 4; t++) cp_async16(sb + 16384 + dstA[t], srcB[t]);
    cp_commit();

    const int mat  = lane >> 3;
    const int lrow = lane & 7;

    for (int s = 0; s < NS; s++) {
        if (s + 1 < NS) {
            const int k0 = (s + 1) << 6;
            const uint32_t base = sb + ((s + 1) & 1) * G_STAGE;
            #pragma unroll
            for (int t = 0; t < 4; t++) cp_async16(base + dstA[t], srcA[t] + k0);
            #pragma unroll
            for (int t = 0; t < 4; t++) cp_async16(base + 16384 + dstA[t], srcB[t] + k0);
            cp_commit();
            cp_wait<1>();
        } else {
            cp_wait<0>();
        }
        __syncthreads();

        const uint32_t sA = sb + (s & 1) * G_STAGE;
        const uint32_t sB = sA + 16384;

        #pragma unroll
        for (int ks = 0; ks < 4; ks++) {
            uint32_t af[4][4], bf[4][2];
            #pragma unroll
            for (int mt = 0; mt < 4; mt++) {
                const int arow = wm * 64 + mt * 16 + ((mat & 1) << 3) + lrow;
                const int akc  = (ks << 1) + (mat >> 1);
                ldm_x4(af[mt][0], af[mt][1], af[mt][2], af[mt][3], sA + SWZ64(arow, akc));
            }
            #pragma unroll
            for (int nt2 = 0; nt2 < 2; nt2++) {
                const int brow = wn * 32 + (nt2 << 4) + ((mat >> 1) << 3) + lrow;
                const int bkc  = (ks << 1) + (mat & 1);
                ldm_x4(bf[nt2*2][0], bf[nt2*2][1], bf[nt2*2+1][0], bf[nt2*2+1][1],
                       sB + SWZ64(brow, bkc));
            }
            #pragma unroll
            for (int mt = 0; mt < 4; mt++)
                #pragma unroll
                for (int nt = 0; nt < 4; nt++)
                    mma_f16(acc[mt][nt], af[mt], bf[nt]);
        }
        __syncthreads();
    }

    const int group = lane >> 2, tig = lane & 3;
    if (MODE == 0) {
        #pragma unroll
        for (int mt = 0; mt < 4; mt++) {
            const int r = bm + wm * 64 + mt * 16 + group;
            #pragma unroll
            for (int nt = 0; nt < 4; nt++) {
                const int c = bn + wn * 32 + nt * 8 + tig * 2;
                const float bx = bias[c], by = bias[c + 1];
                *reinterpret_cast<float2*>(&C[(size_t)r * N + c]) =
                    make_float2(acc[mt][nt][0] + bx, acc[mt][nt][1] + by);
                *reinterpret_cast<float2*>(&C[(size_t)(r + 8) * N + c]) =
                    make_float2(acc[mt][nt][2] + bx, acc[mt][nt][3] + by);
            }
        }
    } else {
        #pragma unroll
        for (int mt = 0; mt < 4; mt++) {
            const int r = bm + wm * 64 + mt * 16 + group;
            const uint32_t bA = (uint32_t)r / 49u;
            const int tA = r - (int)bA * 49;
            const uint32_t bB = (uint32_t)(r + 8) / 49u;
            const int tB = (r + 8) - (int)bB * 49;
            #pragma unroll
            for (int nt = 0; nt < 4; nt++) {
                const int cc = bn + wn * 32 + nt * 8 + tig * 2;
                const int sidx = cc >> 8;
                const int hh = (cc >> 5) & 7;
                const int dd = cc & 31;
                float v0 = acc[mt][nt][0] + bias[cc];
                float v1 = acc[mt][nt][1] + bias[cc + 1];
                float v2 = acc[mt][nt][2] + bias[cc];
                float v3 = acc[mt][nt][3] + bias[cc + 1];
                const size_t iA = ((size_t)(bA * 8 + hh) * NTOK + tA) * DH + dd;
                const size_t iB = ((size_t)(bB * 8 + hh) * NTOK + tB) * DH + dd;
                if (sidx == 0) {
                    v0 *= ATT_SCALE; v1 *= ATT_SCALE; v2 *= ATT_SCALE; v3 *= ATT_SCALE;
                    *reinterpret_cast<__half2*>(&qh[iA]) = __floats2half2_rn(v0, v1);
                    *reinterpret_cast<__half2*>(&qh[iB]) = __floats2half2_rn(v2, v3);
                } else if (sidx == 1) {
                    *reinterpret_cast<__half2*>(&kh[iA]) = __floats2half2_rn(v0, v1);
                    *reinterpret_cast<__half2*>(&kh[iB]) = __floats2half2_rn(v2, v3);
                } else {
                    *reinterpret_cast<__half2*>(&vh[iA]) = __floats2half2_rn(v0, v1);
                    *reinterpret_cast<__half2*>(&vh[iB]) = __floats2half2_rn(v2, v3);
                }
            }
        }
    }
}

// ---------------------------------------------------------------------------
// Attention: plain fp16 q/k/v; bias read from L2 in fragment layout.
// smem: 3 tiles = 12 KB.
// ---------------------------------------------------------------------------
__global__ __launch_bounds__(128) void attn_f16(
    const __half* __restrict__ qh, const __half* __restrict__ kh,
    const __half* __restrict__ vh,
    const float4* __restrict__ biasF,
    __half* __restrict__ out)
{
    __shared__ __align__(16) char smem[3 * 4096];
    const uint32_t sb = smem_u32(smem);
    const uint32_t tQ = sb, tK = sb + 4096, tV = sb + 8192;

    const int bh = blockIdx.x;
    const int b = bh >> 3, h = bh & 7;
    const int tid = threadIdx.x;

    const size_t gbase = (size_t)bh * NTOK * DH;
    const __half* gp[3] = { qh + gbase, kh + gbase, vh + gbase };

    // async fills: q/k/v tiles
    #pragma unroll
    for (int buf = 0; buf < 3; buf++) {
        for (int i = tid; i < 196; i += 128) {
            const int row = i >> 2, kc = i & 3;
            cp_async16(sb + buf * 4096 + SWZ(row, kc), gp[buf] + row * DH + kc * 8);
        }
    }
    cp_commit();
    // zero pad rows 49..63
    for (int i = tid; i < 180; i += 128) {
        const int buf = i / 60, rem = i - buf * 60;
        const int row = 49 + (rem >> 2), kc = rem & 3;
        *reinterpret_cast<uint4*>(smem + buf * 4096 + SWZ(row, kc)) = make_uint4(0, 0, 0, 0);
    }
    cp_wait<0>();
    __syncthreads();

    const int warp = tid >> 5, lane = tid & 31;
    const int group = lane >> 2, tig = lane & 3;
    const int mat = lane >> 3, lrow = lane & 7;
    const int r0 = warp * 16 + group;

    // ---- QK^T: fp16 ----
    float acc[7][4];
    #pragma unroll
    for (int t = 0; t < 7; t++)
        #pragma unroll
        for (int r = 0; r < 4; r++) acc[t][r] = 0.f;

    #pragma unroll
    for (int kc16 = 0; kc16 < 2; kc16++) {
        const int arow = warp * 16 + ((mat & 1) << 3) + lrow;
        const int akc  = kc16 * 2 + (mat >> 1);
        uint32_t ah[4];
        ldm_x4(ah[0], ah[1], ah[2], ah[3], tQ + SWZ(arow, akc));
        #pragma unroll
        for (int g4 = 0; g4 < 4; g4++) {
            const int brow = g4 * 16 + ((mat >> 1) << 3) + lrow;
            const int bkc  = kc16 * 2 + (mat & 1);
            uint32_t bh2[2][2];
            ldm_x4(bh2[0][0], bh2[0][1], bh2[1][0], bh2[1][1], tK + SWZ(brow, bkc));
            #pragma unroll
            for (int u = 0; u < 2; u++) {
                const int t = g4 * 2 + u;
                if (t < 7) mma_f16(acc[t], ah, bh2[u]);
            }
        }
    }

    // ---- bias (fragment layout, coalesced from L2) + masked softmax ----
    const float4* bfp = biasF + ((size_t)(((b & (NW - 1)) << 3) + h) * 4 + warp) * 7 * 32 + lane;
    const bool row0 = (r0 < NTOK);
    const bool row1 = (r0 + 8 < NTOK);
    float mx0 = -1e30f, mx1 = -1e30f;
    #pragma unroll
    for (int t = 0; t < 7; t++) {
        const float4 bv = __ldg(&bfp[t * 32]);
        acc[t][0] += bv.x;
        acc[t][1] += bv.y;
        acc[t][2] += bv.z;
        acc[t][3] += bv.w;
        const int c0 = t * 8 + tig * 2;
        if (c0 < NTOK) {
            if (row0) mx0 = fmaxf(mx0, acc[t][0]);
            if (row1) mx1 = fmaxf(mx1, acc[t][2]);
        }
        if (c0 + 1 < NTOK) {
            if (row0) mx0 = fmaxf(mx0, acc[t][1]);
            if (row1) mx1 = fmaxf(mx1, acc[t][3]);
        }
    }
    mx0 = fmaxf(mx0, __shfl_xor_sync(0xffffffffu, mx0, 1));
    mx0 = fmaxf(mx0, __shfl_xor_sync(0xffffffffu, mx0, 2));
    mx1 = fmaxf(mx1, __shfl_xor_sync(0xffffffffu, mx1, 1));
    mx1 = fmaxf(mx1, __shfl_xor_sync(0xffffffffu, mx1, 2));
    if (mx0 < -1e29f) mx0 = 0.f;
    if (mx1 < -1e29f) mx1 = 0.f;

    float s0 = 0.f, s1 = 0.f;
    #pragma unroll
    for (int t = 0; t < 7; t++) {
        const int c0 = t * 8 + tig * 2;
        acc[t][0] = (c0     < NTOK) ? __expf(acc[t][0] - mx0) : 0.f;
        acc[t][1] = (c0 + 1 < NTOK) ? __expf(acc[t][1] - mx0) : 0.f;
        acc[t][2] = (c0     < NTOK) ? __expf(acc[t][2] - mx1) : 0.f;
        acc[t][3] = (c0 + 1 < NTOK) ? __expf(acc[t][3] - mx1) : 0.f;
        s0 += acc[t][0] + acc[t][1];
        s1 += acc[t][2] + acc[t][3];
    }
    s0 += __shfl_xor_sync(0xffffffffu, s0, 1);
    s0 += __shfl_xor_sync(0xffffffffu, s0, 2);
    s1 += __shfl_xor_sync(0xffffffffu, s1, 1);
    s1 += __shfl_xor_sync(0xffffffffu, s1, 2);
    const float inv0 = 1.f / s0;
    const float inv1 = 1.f / s1;

    // ---- AV: P in registers as fp16 A-frags; V via ldmatrix.trans ----
    uint32_t pa[4][4];
    #pragma unroll
    for (int kc = 0; kc < 4; kc++) {
        const int t0 = kc * 2, t1 = kc * 2 + 1;
        pa[kc][0] = pack_h2(acc[t0][0] * inv0, acc[t0][1] * inv0);
        pa[kc][1] = pack_h2(acc[t0][2] * inv1, acc[t0][3] * inv1);
        if (t1 < 7) {
            pa[kc][2] = pack_h2(acc[t1][0] * inv0, acc[t1][1] * inv0);
            pa[kc][3] = pack_h2(acc[t1][2] * inv1, acc[t1][3] * inv1);
        } else {
            pa[kc][2] = 0u;
            pa[kc][3] = 0u;
        }
    }

    float av[4][4];
    #pragma unroll
    for (int nt = 0; nt < 4; nt++)
        #pragma unroll
        for (int r = 0; r < 4; r++) av[nt][r] = 0.f;

    #pragma unroll
    for (int kc = 0; kc < 4; kc++) {
        #pragma unroll
        for (int d16 = 0; d16 < 2; d16++) {
            const int vrow = kc * 16 + ((mat & 1) << 3) + lrow;
            const int vkc  = d16 * 2 + (mat >> 1);
            uint32_t bf[2][2];
            ldm_x4_t(bf[0][0], bf[0][1], bf[1][0], bf[1][1], tV + SWZ(vrow, vkc));
            mma_f16(av[d16 * 2],     pa[kc], bf[0]);
            mma_f16(av[d16 * 2 + 1], pa[kc], bf[1]);
        }
    }

    __half* ob = out + (size_t)b * NTOK * DIM + h * DH;
    if (row0) {
        #pragma unroll
        for (int nt = 0; nt < 4; nt++) {
            const int d = nt * 8 + tig * 2;
            *reinterpret_cast<__half2*>(&ob[(size_t)r0 * DIM + d]) =
                __floats2half2_rn(av[nt][0], av[nt][1]);
        }
    }
    if (row1) {
        #pragma unroll
        for (int nt = 0; nt < 4; nt++) {
            const int d = nt * 8 + tig * 2;
            *reinterpret_cast<__half2*>(&ob[(size_t)(r0 + 8) * DIM + d]) =
                __floats2half2_rn(av[nt][2], av[nt][3]);
        }
    }
}

// ---------------------------------------------------------------------------
// Launch
// ---------------------------------------------------------------------------
extern "C" void kernel_launch(void* const* d_in, const int* in_sizes, int n_in,
                              void* d_out, int out_size) {
    const float* x         = (const float*)d_in[0];
    const float* mask      = (const float*)d_in[1];
    const float* qkv_w     = (const float*)d_in[2];
    const float* qkv_b     = (const float*)d_in[3];
    const float* proj_w    = (const float*)d_in[4];
    const float* proj_b    = (const float*)d_in[5];
    const float* rpb_table = (const float*)d_in[6];
    const int*   rel_index = (const int*)d_in[7];
    float* out = (float*)d_out;

    __half *xh, *aoh, *wh, *pwh, *qh, *kh, *vh;
    float4 *biasF;
    cudaGetSymbolAddress((void**)&xh,  g_xh);
    cudaGetSymbolAddress((void**)&aoh, g_attn_outh);
    cudaGetSymbolAddress((void**)&wh,  g_wh);
    cudaGetSymbolAddress((void**)&pwh, g_pwh);
    cudaGetSymbolAddress((void**)&qh,  g_q);
    cudaGetSymbolAddress((void**)&kh,  g_k);
    cudaGetSymbolAddress((void**)&vh,  g_v);
    cudaGetSymbolAddress((void**)&biasF, g_biasF);

    cudaFuncSetAttribute(gemm_f16<0>,
                         cudaFuncAttributeMaxDynamicSharedMemorySize, GEMM_SMEM_BYTES);
    cudaFuncSetAttribute(gemm_f16<1>,
                         cudaFuncAttributeMaxDynamicSharedMemorySize, GEMM_SMEM_BYTES);

    // 0) bias precompute (fragment layout) + fused fp16 conversions
    bias_pre_frag<<<NW * H, 128>>>(mask, rpb_table, rel_index, biasF);
    {
        const int na = MROWS * DIM / 4;
        const int nb = QKV_COLS * DIM / 4;
        const int nc = DIM * DIM / 4;
        const int total = na + nb + nc;
        cvt_f16_all<<<(total + 255) / 256, 256>>>(
            (const float4*)x, (uint2*)xh, na,
            (const float4*)qkv_w, (uint2*)wh, nb,
            (const float4*)proj_w, (uint2*)pwh, nc);
    }
    // 1) QKV projection with fused q/k/v epilogue
    {
        dim3 grid(QKV_COLS / 128, MROWS / 128);
        gemm_f16<1><<<grid, 256, GEMM_SMEM_BYTES>>>(xh, wh, qkv_b, nullptr,
                                                    qh, kh, vh,
                                                    MROWS, QKV_COLS, DIM);
    }
    // 2) attention
    attn_f16<<<NBH, 128>>>(qh, kh, vh, biasF, aoh);
    // 3) output projection
    {
        dim3 grid(DIM / 128, MROWS / 128);
        gemm_f16<0><<<grid, 256, GEMM_SMEM_BYTES>>>(aoh, pwh, proj_b, out,
                                                    nullptr, nullptr, nullptr,
                                                    MROWS, DIM, DIM);
    }
}

// round 13
// speedup vs baseline: 9.1447x; 1.0150x over previous
#include <cuda_runtime.h>
#include <cuda_fp16.h>
#include <cstdint>

// Problem constants
#define NTOK 49
#define DIM 256
#define H 8
#define DH 32
#define BWIN 2048
#define NW 64
#define QKV_COLS 768
#define MROWS (BWIN * NTOK)  // 100352
#define NBH (BWIN * H)       // 16384

// Scratch (device globals; no allocation allowed)
__device__ __half g_xh[(size_t)MROWS * DIM];
__device__ __half g_attn_outh[(size_t)MROWS * DIM];
__device__ __half g_wh[QKV_COLS * DIM];
__device__ __half g_pwh[DIM * DIM];
// bias in mma-fragment layout: [wh][warp(4)][t(7)][lane(32)] float4; -1e30 at masked coords
__device__ float4 g_biasF[(size_t)NW * H * 4 * 7 * 32];
// per-(window,head) fp16 q/k/v: [bh][49][32]
__device__ __half g_q[(size_t)NBH * NTOK * DH];
__device__ __half g_k[(size_t)NBH * NTOK * DH];
__device__ __half g_v[(size_t)NBH * NTOK * DH];

#define ATT_SCALE 0.17677669529663687f
#define NEG_BIG (-1e30f)

// ---------------------------------------------------------------------------
// Helpers
// ---------------------------------------------------------------------------
__device__ __forceinline__ void cp_async16(uint32_t s, const void* g) {
    asm volatile("cp.async.cg.shared.global [%0], [%1], 16;" :: "r"(s), "l"(g));
}
__device__ __forceinline__ void cp_commit() {
    asm volatile("cp.async.commit_group;");
}
template<int Nw> __device__ __forceinline__ void cp_wait() {
    asm volatile("cp.async.wait_group %0;" :: "n"(Nw));
}
__device__ __forceinline__ void mma_f16(float c[4], const uint32_t a[4], const uint32_t b[2]) {
    asm volatile(
        "mma.sync.aligned.m16n8k16.row.col.f32.f16.f16.f32 "
        "{%0,%1,%2,%3}, {%4,%5,%6,%7}, {%8,%9}, {%0,%1,%2,%3};"
        : "+f"(c[0]), "+f"(c[1]), "+f"(c[2]), "+f"(c[3])
        : "r"(a[0]), "r"(a[1]), "r"(a[2]), "r"(a[3]), "r"(b[0]), "r"(b[1]));
}
__device__ __forceinline__ void ldm_x4(uint32_t& r0, uint32_t& r1, uint32_t& r2, uint32_t& r3,
                                       uint32_t addr) {
    asm volatile("ldmatrix.sync.aligned.m8n8.x4.shared.b16 {%0,%1,%2,%3}, [%4];"
                 : "=r"(r0), "=r"(r1), "=r"(r2), "=r"(r3) : "r"(addr));
}
__device__ __forceinline__ void ldm_x4_t(uint32_t& r0, uint32_t& r1, uint32_t& r2, uint32_t& r3,
                                         uint32_t addr) {
    asm volatile("ldmatrix.sync.aligned.m8n8.x4.trans.shared.b16 {%0,%1,%2,%3}, [%4];"
                 : "=r"(r0), "=r"(r1), "=r"(r2), "=r"(r3) : "r"(addr));
}
__device__ __forceinline__ uint32_t smem_u32(const void* p) {
    uint32_t a;
    asm("{ .reg .u64 t; cvta.to.shared.u64 t, %1; cvt.u32.u64 %0, t; }" : "=r"(a) : "l"(p));
    return a;
}
__device__ __forceinline__ uint32_t pack_h2(float a, float b) {
    __half2 h = __floats2half2_rn(a, b);
    return *reinterpret_cast<uint32_t*>(&h);
}
// 64B-row tile swizzle (attention tiles)
#define SWZ(row, kc) ((uint32_t)(((row) << 6) + ((((kc) ^ (((row) >> 1) & 3))) << 4)))
// 128B-row tile swizzle (GEMM BK=64 tiles)
#define SWZ64(row, kc) ((uint32_t)(((row) << 7) + ((((kc) ^ ((row) & 7))) << 4)))

// ---------------------------------------------------------------------------
// fused fp32 -> fp16 conversion for x, qkv_w, proj_w (single launch)
// ---------------------------------------------------------------------------
__global__ __launch_bounds__(256) void cvt_f16_all(
    const float4* __restrict__ sa, uint2* __restrict__ da, int na,
    const float4* __restrict__ sb2, uint2* __restrict__ db, int nb,
    const float4* __restrict__ sc, uint2* __restrict__ dc, int nc)
{
    const int total = na + nb + nc;
    for (int i = blockIdx.x * blockDim.x + threadIdx.x; i < total;
         i += gridDim.x * blockDim.x) {
        const float4* s;
        uint2* d;
        int j = i;
        if (j < na)            { s = sa;  d = da; }
        else if (j < na + nb)  { s = sb2; d = db; j -= na; }
        else                   { s = sc;  d = dc; j -= na + nb; }
        float4 v = s[j];
        d[j] = make_uint2(pack_h2(v.x, v.y), pack_h2(v.z, v.w));
    }
}

// ---------------------------------------------------------------------------
// Bias precompute in mma fragment layout; masked/padded coords get -1e30
// so attention softmax needs NO guards.
// ---------------------------------------------------------------------------
__global__ __launch_bounds__(128) void bias_pre_frag(
    const float* __restrict__ mask, const float* __restrict__ rpb,
    const int* __restrict__ ridx, float4* __restrict__ biasF)
{
    const int wh = blockIdx.x;
    const int w = wh >> 3, h = wh & 7;
    const float* m = mask + (size_t)w * (NTOK * NTOK);
    const int tid = threadIdx.x;
    const int warp = tid >> 5, lane = tid & 31;
    const int r0 = warp * 16 + (lane >> 2);
    const int r1 = r0 + 8;
    float4* o = biasF + ((size_t)wh * 4 + warp) * 7 * 32 + lane;

    #pragma unroll
    for (int t = 0; t < 7; t++) {
        const int c0 = t * 8 + (lane & 3) * 2;
        const int c1 = c0 + 1;
        float4 v = make_float4(NEG_BIG, NEG_BIG, NEG_BIG, NEG_BIG);
        if (r0 < NTOK) {
            if (c0 < NTOK) v.x = m[r0 * NTOK + c0] + rpb[ridx[r0 * NTOK + c0] * H + h];
            if (c1 < NTOK) v.y = m[r0 * NTOK + c1] + rpb[ridx[r0 * NTOK + c1] * H + h];
        }
        if (r1 < NTOK) {
            if (c0 < NTOK) v.z = m[r1 * NTOK + c0] + rpb[ridx[r1 * NTOK + c0] * H + h];
            if (c1 < NTOK) v.w = m[r1 * NTOK + c1] + rpb[ridx[r1 * NTOK + c1] * H + h];
        }
        o[t * 32] = v;
    }
}

// ---------------------------------------------------------------------------
// FP16 tensor-core NT GEMM. Block 128x128, BK=64, 8 warps (2m x 4n).
// 3-stage cp.async pipeline. MODE 0: fp32 C + bias. MODE 1: qkv split epilogue.
// ---------------------------------------------------------------------------
#define G_STAGE 32768
#define GEMM_SMEM_BYTES (3 * G_STAGE)   // 98304

template<int MODE>
__global__ __launch_bounds__(256, 2) void gemm_f16(
    const __half* __restrict__ A, const __half* __restrict__ W,
    const float* __restrict__ bias, float* __restrict__ C,
    __half* __restrict__ qh, __half* __restrict__ kh, __half* __restrict__ vh,
    int M, int N, int K)
{
    extern __shared__ __align__(16) char smem[];

    const int tid  = threadIdx.x;
    const int lane = tid & 31;
    const int warp = tid >> 5;
    const int wm = warp >> 2;
    const int wn = warp & 3;
    const int bm = blockIdx.y * 128;
    const int bn = blockIdx.x * 128;

    const uint32_t sb = smem_u32(smem);

    uint32_t dstA[4];
    const __half* srcA[4];
    const __half* srcB[4];
    #pragma unroll
    for (int t = 0; t < 4; t++) {
        const int chunk = tid + t * 256;
        const int row = chunk >> 3, kc = chunk & 7;
        dstA[t] = SWZ64(row, kc);
        srcA[t] = A + (size_t)(bm + row) * K + kc * 8;
        srcB[t] = W + (size_t)(bn + row) * K + kc * 8;
    }

    float acc[4][4][4];
    #pragma unroll
    for (int mt = 0; mt < 4; mt++)
        #pragma unroll
        for (int nt = 0; nt < 4; nt++)
            #pragma unroll
            for (int r = 0; r < 4; r++) acc[mt][nt][r] = 0.f;

    const int NS = K >> 6;

    // prologue: prefetch stages 0 and 1
    {
        const uint32_t b0 = sb;
        #pragma unroll
        for (int t = 0; t < 4; t++) cp_async16(b0 + dstA[t], srcA[t]);
        #pragma unroll
        for (int t = 0; t < 4; t++) cp_async16(b0 + 16384 + dstA[t], srcB[t]);
        cp_commit();
        if (NS > 1) {
            const uint32_t b1 = sb + G_STAGE;
            #pragma unroll
            for (int t = 0; t < 4; t++) cp_async16(b1 + dstA[t], srcA[t] + 64);
            #pragma unroll
            for (int t = 0; t < 4; t++) cp_async16(b1 + 16384 + dstA[t], srcB[t] + 64);
        }
        cp_commit();
    }

    const int mat  = lane >> 3;
    const int lrow = lane & 7;

    int buf = 0;
    for (int s = 0; s < NS; s++) {
        if (s + 2 < NS) {
            const int k0 = (s + 2) << 6;
            int nb = buf + 2; if (nb >= 3) nb -= 3;
            const uint32_t base = sb + nb * G_STAGE;
            #pragma unroll
            for (int t = 0; t < 4; t++) cp_async16(base + dstA[t], srcA[t] + k0);
            #pragma unroll
            for (int t = 0; t < 4; t++) cp_async16(base + 16384 + dstA[t], srcB[t] + k0);
        }
        cp_commit();
        cp_wait<2>();
        __syncthreads();

        const uint32_t sA = sb + buf * G_STAGE;
        const uint32_t sB = sA + 16384;

        #pragma unroll
        for (int ks = 0; ks < 4; ks++) {
            uint32_t af[4][4], bf[4][2];
            #pragma unroll
            for (int mt = 0; mt < 4; mt++) {
                const int arow = wm * 64 + mt * 16 + ((mat & 1) << 3) + lrow;
                const int akc  = (ks << 1) + (mat >> 1);
                ldm_x4(af[mt][0], af[mt][1], af[mt][2], af[mt][3], sA + SWZ64(arow, akc));
            }
            #pragma unroll
            for (int nt2 = 0; nt2 < 2; nt2++) {
                const int brow = wn * 32 + (nt2 << 4) + ((mat >> 1) << 3) + lrow;
                const int bkc  = (ks << 1) + (mat & 1);
                ldm_x4(bf[nt2*2][0], bf[nt2*2][1], bf[nt2*2+1][0], bf[nt2*2+1][1],
                       sB + SWZ64(brow, bkc));
            }
            #pragma unroll
            for (int mt = 0; mt < 4; mt++)
                #pragma unroll
                for (int nt = 0; nt < 4; nt++)
                    mma_f16(acc[mt][nt], af[mt], bf[nt]);
        }
        __syncthreads();
        if (++buf == 3) buf = 0;
    }

    const int group = lane >> 2, tig = lane & 3;
    if (MODE == 0) {
        #pragma unroll
        for (int mt = 0; mt < 4; mt++) {
            const int r = bm + wm * 64 + mt * 16 + group;
            #pragma unroll
            for (int nt = 0; nt < 4; nt++) {
                const int c = bn + wn * 32 + nt * 8 + tig * 2;
                const float bx = bias[c], by = bias[c + 1];
                *reinterpret_cast<float2*>(&C[(size_t)r * N + c]) =
                    make_float2(acc[mt][nt][0] + bx, acc[mt][nt][1] + by);
                *reinterpret_cast<float2*>(&C[(size_t)(r + 8) * N + c]) =
                    make_float2(acc[mt][nt][2] + bx, acc[mt][nt][3] + by);
            }
        }
    } else {
        #pragma unroll
        for (int mt = 0; mt < 4; mt++) {
            const int r = bm + wm * 64 + mt * 16 + group;
            const uint32_t bA = (uint32_t)r / 49u;
            const int tA = r - (int)bA * 49;
            const uint32_t bB = (uint32_t)(r + 8) / 49u;
            const int tB = (r + 8) - (int)bB * 49;
            #pragma unroll
            for (int nt = 0; nt < 4; nt++) {
                const int cc = bn + wn * 32 + nt * 8 + tig * 2;
                const int sidx = cc >> 8;
                const int hh = (cc >> 5) & 7;
                const int dd = cc & 31;
                float v0 = acc[mt][nt][0] + bias[cc];
                float v1 = acc[mt][nt][1] + bias[cc + 1];
                float v2 = acc[mt][nt][2] + bias[cc];
                float v3 = acc[mt][nt][3] + bias[cc + 1];
                const size_t iA = ((size_t)(bA * 8 + hh) * NTOK + tA) * DH + dd;
                const size_t iB = ((size_t)(bB * 8 + hh) * NTOK + tB) * DH + dd;
                if (sidx == 0) {
                    v0 *= ATT_SCALE; v1 *= ATT_SCALE; v2 *= ATT_SCALE; v3 *= ATT_SCALE;
                    *reinterpret_cast<__half2*>(&qh[iA]) = __floats2half2_rn(v0, v1);
                    *reinterpret_cast<__half2*>(&qh[iB]) = __floats2half2_rn(v2, v3);
                } else if (sidx == 1) {
                    *reinterpret_cast<__half2*>(&kh[iA]) = __floats2half2_rn(v0, v1);
                    *reinterpret_cast<__half2*>(&kh[iB]) = __floats2half2_rn(v2, v3);
                } else {
                    *reinterpret_cast<__half2*>(&vh[iA]) = __floats2half2_rn(v0, v1);
                    *reinterpret_cast<__half2*>(&vh[iB]) = __floats2half2_rn(v2, v3);
                }
            }
        }
    }
}

// ---------------------------------------------------------------------------
// Attention: plain fp16 q/k/v; bias (with -1e30 masking) from L2 in fragment
// layout -> completely unconditional softmax. smem: 3 tiles = 12 KB.
// ---------------------------------------------------------------------------
__global__ __launch_bounds__(128) void attn_f16(
    const __half* __restrict__ qh, const __half* __restrict__ kh,
    const __half* __restrict__ vh,
    const float4* __restrict__ biasF,
    __half* __restrict__ out)
{
    __shared__ __align__(16) char smem[3 * 4096];
    const uint32_t sb = smem_u32(smem);
    const uint32_t tQ = sb, tK = sb + 4096, tV = sb + 8192;

    const int bh = blockIdx.x;
    const int b = bh >> 3, h = bh & 7;
    const int tid = threadIdx.x;

    const size_t gbase = (size_t)bh * NTOK * DH;
    const __half* gp[3] = { qh + gbase, kh + gbase, vh + gbase };

    #pragma unroll
    for (int buf = 0; buf < 3; buf++) {
        for (int i = tid; i < 196; i += 128) {
            const int row = i >> 2, kc = i & 3;
            cp_async16(sb + buf * 4096 + SWZ(row, kc), gp[buf] + row * DH + kc * 8);
        }
    }
    cp_commit();
    for (int i = tid; i < 180; i += 128) {
        const int buf = i / 60, rem = i - buf * 60;
        const int row = 49 + (rem >> 2), kc = rem & 3;
        *reinterpret_cast<uint4*>(smem + buf * 4096 + SWZ(row, kc)) = make_uint4(0, 0, 0, 0);
    }
    cp_wait<0>();
    __syncthreads();

    const int warp = tid >> 5, lane = tid & 31;
    const int group = lane >> 2, tig = lane & 3;
    const int mat = lane >> 3, lrow = lane & 7;
    const int r0 = warp * 16 + group;

    // ---- QK^T: fp16 ----
    float acc[7][4];
    #pragma unroll
    for (int t = 0; t < 7; t++)
        #pragma unroll
        for (int r = 0; r < 4; r++) acc[t][r] = 0.f;

    #pragma unroll
    for (int kc16 = 0; kc16 < 2; kc16++) {
        const int arow = warp * 16 + ((mat & 1) << 3) + lrow;
        const int akc  = kc16 * 2 + (mat >> 1);
        uint32_t ah[4];
        ldm_x4(ah[0], ah[1], ah[2], ah[3], tQ + SWZ(arow, akc));
        #pragma unroll
        for (int g4 = 0; g4 < 4; g4++) {
            const int brow = g4 * 16 + ((mat >> 1) << 3) + lrow;
            const int bkc  = kc16 * 2 + (mat & 1);
            uint32_t bh2[2][2];
            ldm_x4(bh2[0][0], bh2[0][1], bh2[1][0], bh2[1][1], tK + SWZ(brow, bkc));
            #pragma unroll
            for (int u = 0; u < 2; u++) {
                const int t = g4 * 2 + u;
                if (t < 7) mma_f16(acc[t], ah, bh2[u]);
            }
        }
    }

    // ---- bias add (includes -1e30 masking) + unconditional softmax ----
    const float4* bfp = biasF + ((size_t)(((b & (NW - 1)) << 3) + h) * 4 + warp) * 7 * 32 + lane;
    float mx0 = NEG_BIG, mx1 = NEG_BIG;
    #pragma unroll
    for (int t = 0; t < 7; t++) {
        const float4 bv = __ldg(&bfp[t * 32]);
        acc[t][0] += bv.x;
        acc[t][1] += bv.y;
        acc[t][2] += bv.z;
        acc[t][3] += bv.w;
        mx0 = fmaxf(mx0, fmaxf(acc[t][0], acc[t][1]));
        mx1 = fmaxf(mx1, fmaxf(acc[t][2], acc[t][3]));
    }
    mx0 = fmaxf(mx0, __shfl_xor_sync(0xffffffffu, mx0, 1));
    mx0 = fmaxf(mx0, __shfl_xor_sync(0xffffffffu, mx0, 2));
    mx1 = fmaxf(mx1, __shfl_xor_sync(0xffffffffu, mx1, 1));
    mx1 = fmaxf(mx1, __shfl_xor_sync(0xffffffffu, mx1, 2));

    float s0 = 0.f, s1 = 0.f;
    #pragma unroll
    for (int t = 0; t < 7; t++) {
        acc[t][0] = __expf(acc[t][0] - mx0);
        acc[t][1] = __expf(acc[t][1] - mx0);
        acc[t][2] = __expf(acc[t][2] - mx1);
        acc[t][3] = __expf(acc[t][3] - mx1);
        s0 += acc[t][0] + acc[t][1];
        s1 += acc[t][2] + acc[t][3];
    }
    s0 += __shfl_xor_sync(0xffffffffu, s0, 1);
    s0 += __shfl_xor_sync(0xffffffffu, s0, 2);
    s1 += __shfl_xor_sync(0xffffffffu, s1, 1);
    s1 += __shfl_xor_sync(0xffffffffu, s1, 2);
    const float inv0 = 1.f / s0;
    const float inv1 = 1.f / s1;

    // ---- AV: P in registers as fp16 A-frags; V via ldmatrix.trans ----
    uint32_t pa[4][4];
    #pragma unroll
    for (int kc = 0; kc < 4; kc++) {
        const int t0 = kc * 2, t1 = kc * 2 + 1;
        pa[kc][0] = pack_h2(acc[t0][0] * inv0, acc[t0][1] * inv0);
        pa[kc][1] = pack_h2(acc[t0][2] * inv1, acc[t0][3] * inv1);
        if (t1 < 7) {
            pa[kc][2] = pack_h2(acc[t1][0] * inv0, acc[t1][1] * inv0);
            pa[kc][3] = pack_h2(acc[t1][2] * inv1, acc[t1][3] * inv1);
        } else {
            pa[kc][2] = 0u;
            pa[kc][3] = 0u;
        }
    }

    float av[4][4];
    #pragma unroll
    for (int nt = 0; nt < 4; nt++)
        #pragma unroll
        for (int r = 0; r < 4; r++) av[nt][r] = 0.f;

    #pragma unroll
    for (int kc = 0; kc < 4; kc++) {
        #pragma unroll
        for (int d16 = 0; d16 < 2; d16++) {
            const int vrow = kc * 16 + ((mat & 1) << 3) + lrow;
            const int vkc  = d16 * 2 + (mat >> 1);
            uint32_t bf[2][2];
            ldm_x4_t(bf[0][0], bf[0][1], bf[1][0], bf[1][1], tV + SWZ(vrow, vkc));
            mma_f16(av[d16 * 2],     pa[kc], bf[0]);
            mma_f16(av[d16 * 2 + 1], pa[kc], bf[1]);
        }
    }

    __half* ob = out + (size_t)b * NTOK * DIM + h * DH;
    if (r0 < NTOK) {
        #pragma unroll
        for (int nt = 0; nt < 4; nt++) {
            const int d = nt * 8 + tig * 2;
            *reinterpret_cast<__half2*>(&ob[(size_t)r0 * DIM + d]) =
                __floats2half2_rn(av[nt][0], av[nt][1]);
        }
    }
    if (r0 + 8 < NTOK) {
        #pragma unroll
        for (int nt = 0; nt < 4; nt++) {
            const int d = nt * 8 + tig * 2;
            *reinterpret_cast<__half2*>(&ob[(size_t)(r0 + 8) * DIM + d]) =
                __floats2half2_rn(av[nt][2], av[nt][3]);
        }
    }
}

// ---------------------------------------------------------------------------
// Launch
// ---------------------------------------------------------------------------
extern "C" void kernel_launch(void* const* d_in, const int* in_sizes, int n_in,
                              void* d_out, int out_size) {
    const float* x         = (const float*)d_in[0];
    const float* mask      = (const float*)d_in[1];
    const float* qkv_w     = (const float*)d_in[2];
    const float* qkv_b     = (const float*)d_in[3];
    const float* proj_w    = (const float*)d_in[4];
    const float* proj_b    = (const float*)d_in[5];
    const float* rpb_table = (const float*)d_in[6];
    const int*   rel_index = (const int*)d_in[7];
    float* out = (float*)d_out;

    __half *xh, *aoh, *wh, *pwh, *qh, *kh, *vh;
    float4 *biasF;
    cudaGetSymbolAddress((void**)&xh,  g_xh);
    cudaGetSymbolAddress((void**)&aoh, g_attn_outh);
    cudaGetSymbolAddress((void**)&wh,  g_wh);
    cudaGetSymbolAddress((void**)&pwh, g_pwh);
    cudaGetSymbolAddress((void**)&qh,  g_q);
    cudaGetSymbolAddress((void**)&kh,  g_k);
    cudaGetSymbolAddress((void**)&vh,  g_v);
    cudaGetSymbolAddress((void**)&biasF, g_biasF);

    cudaFuncSetAttribute(gemm_f16<0>,
                         cudaFuncAttributeMaxDynamicSharedMemorySize, GEMM_SMEM_BYTES);
    cudaFuncSetAttribute(gemm_f16<1>,
                         cudaFuncAttributeMaxDynamicSharedMemorySize, GEMM_SMEM_BYTES);

    // 0) bias precompute (fragment layout, -1e30 masking) + fused conversions
    bias_pre_frag<<<NW * H, 128>>>(mask, rpb_table, rel_index, biasF);
    {
        const int na = MROWS * DIM / 4;
        const int nb = QKV_COLS * DIM / 4;
        const int nc = DIM * DIM / 4;
        const int total = na + nb + nc;
        cvt_f16_all<<<(total + 255) / 256, 256>>>(
            (const float4*)x, (uint2*)xh, na,
            (const float4*)qkv_w, (uint2*)wh, nb,
            (const float4*)proj_w, (uint2*)pwh, nc);
    }
    // 1) QKV projection with fused q/k/v epilogue
    {
        dim3 grid(QKV_COLS / 128, MROWS / 128);
        gemm_f16<1><<<grid, 256, GEMM_SMEM_BYTES>>>(xh, wh, qkv_b, nullptr,
                                                    qh, kh, vh,
                                                    MROWS, QKV_COLS, DIM);
    }
    // 2) attention
    attn_f16<<<NBH, 128>>>(qh, kh, vh, biasF, aoh);
    // 3) output projection
    {
        dim3 grid(DIM / 128, MROWS / 128);
        gemm_f16<0><<<grid, 256, GEMM_SMEM_BYTES>>>(aoh, pwh, proj_b, out,
                                                    nullptr, nullptr, nullptr,
                                                    MROWS, DIM, DIM);
    }
}

// round 14
// speedup vs baseline: 9.2531x; 1.0118x over previous
#include <cuda_runtime.h>
#include <cuda_fp16.h>
#include <cstdint>

// Problem constants
#define NTOK 49
#define DIM 256
#define H 8
#define DH 32
#define BWIN 2048
#define NW 64
#define QKV_COLS 768
#define MROWS (BWIN * NTOK)  // 100352
#define NBH (BWIN * H)       // 16384

// Scratch (device globals; no allocation allowed)
__device__ __half g_xh[(size_t)MROWS * DIM];
__device__ __half g_attn_outh[(size_t)MROWS * DIM];
__device__ __half g_wh[QKV_COLS * DIM];
__device__ __half g_pwh[DIM * DIM];
// bias in mma-fragment layout: [wh][warp(4)][t(7)][lane(32)] float4; -1e30 at masked coords
__device__ float4 g_biasF[(size_t)NW * H * 4 * 7 * 32];
// per-(window,head) fp16 q/k/v: [bh][49][32]
__device__ __half g_q[(size_t)NBH * NTOK * DH];
__device__ __half g_k[(size_t)NBH * NTOK * DH];
__device__ __half g_v[(size_t)NBH * NTOK * DH];

#define ATT_SCALE 0.17677669529663687f
#define NEG_BIG (-1e30f)

// ---------------------------------------------------------------------------
// Helpers
// ---------------------------------------------------------------------------
__device__ __forceinline__ void cp_async16(uint32_t s, const void* g) {
    asm volatile("cp.async.cg.shared.global [%0], [%1], 16;" :: "r"(s), "l"(g));
}
__device__ __forceinline__ void cp_commit() {
    asm volatile("cp.async.commit_group;");
}
template<int Nw> __device__ __forceinline__ void cp_wait() {
    asm volatile("cp.async.wait_group %0;" :: "n"(Nw));
}
__device__ __forceinline__ void mma_f16(float c[4], const uint32_t a[4], const uint32_t b[2]) {
    asm volatile(
        "mma.sync.aligned.m16n8k16.row.col.f32.f16.f16.f32 "
        "{%0,%1,%2,%3}, {%4,%5,%6,%7}, {%8,%9}, {%0,%1,%2,%3};"
        : "+f"(c[0]), "+f"(c[1]), "+f"(c[2]), "+f"(c[3])
        : "r"(a[0]), "r"(a[1]), "r"(a[2]), "r"(a[3]), "r"(b[0]), "r"(b[1]));
}
__device__ __forceinline__ void ldm_x4(uint32_t& r0, uint32_t& r1, uint32_t& r2, uint32_t& r3,
                                       uint32_t addr) {
    asm volatile("ldmatrix.sync.aligned.m8n8.x4.shared.b16 {%0,%1,%2,%3}, [%4];"
                 : "=r"(r0), "=r"(r1), "=r"(r2), "=r"(r3) : "r"(addr));
}
__device__ __forceinline__ void ldm_x4_t(uint32_t& r0, uint32_t& r1, uint32_t& r2, uint32_t& r3,
                                         uint32_t addr) {
    asm volatile("ldmatrix.sync.aligned.m8n8.x4.trans.shared.b16 {%0,%1,%2,%3}, [%4];"
                 : "=r"(r0), "=r"(r1), "=r"(r2), "=r"(r3) : "r"(addr));
}
__device__ __forceinline__ uint32_t smem_u32(const void* p) {
    uint32_t a;
    asm("{ .reg .u64 t; cvta.to.shared.u64 t, %1; cvt.u32.u64 %0, t; }" : "=r"(a) : "l"(p));
    return a;
}
__device__ __forceinline__ uint32_t pack_h2(float a, float b) {
    __half2 h = __floats2half2_rn(a, b);
    return *reinterpret_cast<uint32_t*>(&h);
}
// 64B-row tile swizzle (attention tiles)
#define SWZ(row, kc) ((uint32_t)(((row) << 6) + ((((kc) ^ (((row) >> 1) & 3))) << 4)))
// 128B-row tile swizzle (GEMM BK=64 tiles)
#define SWZ64(row, kc) ((uint32_t)(((row) << 7) + ((((kc) ^ ((row) & 7))) << 4)))

// ---------------------------------------------------------------------------
// Fused prep: blocks [0,512) build fragment-layout bias (with -1e30 masking);
// remaining blocks convert x / qkv_w / proj_w to fp16.
// ---------------------------------------------------------------------------
#define PREP_BIAS_BLOCKS (NW * H)   // 512

__global__ __launch_bounds__(256) void prep_all(
    const float* __restrict__ mask, const float* __restrict__ rpb,
    const int* __restrict__ ridx, float4* __restrict__ biasF,
    const float4* __restrict__ sa, uint2* __restrict__ da, int na,
    const float4* __restrict__ sb2, uint2* __restrict__ db, int nb,
    const float4* __restrict__ sc, uint2* __restrict__ dc, int nc)
{
    if (blockIdx.x < PREP_BIAS_BLOCKS) {
        const int tid = threadIdx.x;
        if (tid >= 128) return;
        const int wh = blockIdx.x;
        const int w = wh >> 3, h = wh & 7;
        const float* m = mask + (size_t)w * (NTOK * NTOK);
        const int warp = tid >> 5, lane = tid & 31;
        const int r0 = warp * 16 + (lane >> 2);
        const int r1 = r0 + 8;
        float4* o = biasF + ((size_t)wh * 4 + warp) * 7 * 32 + lane;
        #pragma unroll
        for (int t = 0; t < 7; t++) {
            const int c0 = t * 8 + (lane & 3) * 2;
            const int c1 = c0 + 1;
            float4 v = make_float4(NEG_BIG, NEG_BIG, NEG_BIG, NEG_BIG);
            if (r0 < NTOK) {
                if (c0 < NTOK) v.x = m[r0 * NTOK + c0] + rpb[ridx[r0 * NTOK + c0] * H + h];
                if (c1 < NTOK) v.y = m[r0 * NTOK + c1] + rpb[ridx[r0 * NTOK + c1] * H + h];
            }
            if (r1 < NTOK) {
                if (c0 < NTOK) v.z = m[r1 * NTOK + c0] + rpb[ridx[r1 * NTOK + c0] * H + h];
                if (c1 < NTOK) v.w = m[r1 * NTOK + c1] + rpb[ridx[r1 * NTOK + c1] * H + h];
            }
            o[t * 32] = v;
        }
    } else {
        const int total = na + nb + nc;
        const int base = (blockIdx.x - PREP_BIAS_BLOCKS) * blockDim.x + threadIdx.x;
        const int stride = (gridDim.x - PREP_BIAS_BLOCKS) * blockDim.x;
        for (int i = base; i < total; i += stride) {
            const float4* s;
            uint2* d;
            int j = i;
            if (j < na)            { s = sa;  d = da; }
            else if (j < na + nb)  { s = sb2; d = db; j -= na; }
            else                   { s = sc;  d = dc; j -= na + nb; }
            float4 v = s[j];
            d[j] = make_uint2(pack_h2(v.x, v.y), pack_h2(v.z, v.w));
        }
    }
}

// ---------------------------------------------------------------------------
// FP16 tensor-core NT GEMM. Block 128x128, BK=64, 8 warps (2m x 4n).
// 3-stage cp.async pipeline. MODE 0: fp32 C + bias. MODE 1: qkv split epilogue.
// ---------------------------------------------------------------------------
#define G_STAGE 32768
#define GEMM_SMEM_BYTES (3 * G_STAGE)   // 98304

template<int MODE>
__global__ __launch_bounds__(256, 2) void gemm_f16(
    const __half* __restrict__ A, const __half* __restrict__ W,
    const float* __restrict__ bias, float* __restrict__ C,
    __half* __restrict__ qh, __half* __restrict__ kh, __half* __restrict__ vh,
    int M, int N, int K)
{
    extern __shared__ __align__(16) char smem[];

    const int tid  = threadIdx.x;
    const int lane = tid & 31;
    const int warp = tid >> 5;
    const int wm = warp >> 2;
    const int wn = warp & 3;
    const int bm = blockIdx.y * 128;
    const int bn = blockIdx.x * 128;

    const uint32_t sb = smem_u32(smem);

    uint32_t dstA[4];
    const __half* srcA[4];
    const __half* srcB[4];
    #pragma unroll
    for (int t = 0; t < 4; t++) {
        const int chunk = tid + t * 256;
        const int row = chunk >> 3, kc = chunk & 7;
        dstA[t] = SWZ64(row, kc);
        srcA[t] = A + (size_t)(bm + row) * K + kc * 8;
        srcB[t] = W + (size_t)(bn + row) * K + kc * 8;
    }

    float acc[4][4][4];
    #pragma unroll
    for (int mt = 0; mt < 4; mt++)
        #pragma unroll
        for (int nt = 0; nt < 4; nt++)
            #pragma unroll
            for (int r = 0; r < 4; r++) acc[mt][nt][r] = 0.f;

    const int NS = K >> 6;

    // prologue: prefetch stages 0 and 1
    {
        const uint32_t b0 = sb;
        #pragma unroll
        for (int t = 0; t < 4; t++) cp_async16(b0 + dstA[t], srcA[t]);
        #pragma unroll
        for (int t = 0; t < 4; t++) cp_async16(b0 + 16384 + dstA[t], srcB[t]);
        cp_commit();
        if (NS > 1) {
            const uint32_t b1 = sb + G_STAGE;
            #pragma unroll
            for (int t = 0; t < 4; t++) cp_async16(b1 + dstA[t], srcA[t] + 64);
            #pragma unroll
            for (int t = 0; t < 4; t++) cp_async16(b1 + 16384 + dstA[t], srcB[t] + 64);
        }
        cp_commit();
    }

    const int mat  = lane >> 3;
    const int lrow = lane & 7;

    int buf = 0;
    for (int s = 0; s < NS; s++) {
        if (s + 2 < NS) {
            const int k0 = (s + 2) << 6;
            int nb = buf + 2; if (nb >= 3) nb -= 3;
            const uint32_t base = sb + nb * G_STAGE;
            #pragma unroll
            for (int t = 0; t < 4; t++) cp_async16(base + dstA[t], srcA[t] + k0);
            #pragma unroll
            for (int t = 0; t < 4; t++) cp_async16(base + 16384 + dstA[t], srcB[t] + k0);
        }
        cp_commit();
        cp_wait<2>();
        __syncthreads();

        const uint32_t sA = sb + buf * G_STAGE;
        const uint32_t sB = sA + 16384;

        #pragma unroll
        for (int ks = 0; ks < 4; ks++) {
            uint32_t af[4][4], bf[4][2];
            #pragma unroll
            for (int mt = 0; mt < 4; mt++) {
                const int arow = wm * 64 + mt * 16 + ((mat & 1) << 3) + lrow;
                const int akc  = (ks << 1) + (mat >> 1);
                ldm_x4(af[mt][0], af[mt][1], af[mt][2], af[mt][3], sA + SWZ64(arow, akc));
            }
            #pragma unroll
            for (int nt2 = 0; nt2 < 2; nt2++) {
                const int brow = wn * 32 + (nt2 << 4) + ((mat >> 1) << 3) + lrow;
                const int bkc  = (ks << 1) + (mat & 1);
                ldm_x4(bf[nt2*2][0], bf[nt2*2][1], bf[nt2*2+1][0], bf[nt2*2+1][1],
                       sB + SWZ64(brow, bkc));
            }
            #pragma unroll
            for (int mt = 0; mt < 4; mt++)
                #pragma unroll
                for (int nt = 0; nt < 4; nt++)
                    mma_f16(acc[mt][nt], af[mt], bf[nt]);
        }
        __syncthreads();
        if (++buf == 3) buf = 0;
    }

    const int group = lane >> 2, tig = lane & 3;
    if (MODE == 0) {
        #pragma unroll
        for (int mt = 0; mt < 4; mt++) {
            const int r = bm + wm * 64 + mt * 16 + group;
            #pragma unroll
            for (int nt = 0; nt < 4; nt++) {
                const int c = bn + wn * 32 + nt * 8 + tig * 2;
                const float bx = bias[c], by = bias[c + 1];
                *reinterpret_cast<float2*>(&C[(size_t)r * N + c]) =
                    make_float2(acc[mt][nt][0] + bx, acc[mt][nt][1] + by);
                *reinterpret_cast<float2*>(&C[(size_t)(r + 8) * N + c]) =
                    make_float2(acc[mt][nt][2] + bx, acc[mt][nt][3] + by);
            }
        }
    } else {
        #pragma unroll
        for (int mt = 0; mt < 4; mt++) {
            const int r = bm + wm * 64 + mt * 16 + group;
            const uint32_t bA = (uint32_t)r / 49u;
            const int tA = r - (int)bA * 49;
            const uint32_t bB = (uint32_t)(r + 8) / 49u;
            const int tB = (r + 8) - (int)bB * 49;
            #pragma unroll
            for (int nt = 0; nt < 4; nt++) {
                const int cc = bn + wn * 32 + nt * 8 + tig * 2;
                const int sidx = cc >> 8;
                const int hh = (cc >> 5) & 7;
                const int dd = cc & 31;
                float v0 = acc[mt][nt][0] + bias[cc];
                float v1 = acc[mt][nt][1] + bias[cc + 1];
                float v2 = acc[mt][nt][2] + bias[cc];
                float v3 = acc[mt][nt][3] + bias[cc + 1];
                const size_t iA = ((size_t)(bA * 8 + hh) * NTOK + tA) * DH + dd;
                const size_t iB = ((size_t)(bB * 8 + hh) * NTOK + tB) * DH + dd;
                if (sidx == 0) {
                    v0 *= ATT_SCALE; v1 *= ATT_SCALE; v2 *= ATT_SCALE; v3 *= ATT_SCALE;
                    *reinterpret_cast<__half2*>(&qh[iA]) = __floats2half2_rn(v0, v1);
                    *reinterpret_cast<__half2*>(&qh[iB]) = __floats2half2_rn(v2, v3);
                } else if (sidx == 1) {
                    *reinterpret_cast<__half2*>(&kh[iA]) = __floats2half2_rn(v0, v1);
                    *reinterpret_cast<__half2*>(&kh[iB]) = __floats2half2_rn(v2, v3);
                } else {
                    *reinterpret_cast<__half2*>(&vh[iA]) = __floats2half2_rn(v0, v1);
                    *reinterpret_cast<__half2*>(&vh[iB]) = __floats2half2_rn(v2, v3);
                }
            }
        }
    }
}

// ---------------------------------------------------------------------------
// Attention: 2 (window,head) pairs per 256-thread CTA. Warps 0-3 -> bh0,
// warps 4-7 -> bh1. Bias (-1e30 masked) from L2 in fragment layout.
// smem: 6 tiles = 24 KB.
// ---------------------------------------------------------------------------
__global__ __launch_bounds__(256) void attn_f16(
    const __half* __restrict__ qh, const __half* __restrict__ kh,
    const __half* __restrict__ vh,
    const float4* __restrict__ biasF,
    __half* __restrict__ out)
{
    __shared__ __align__(16) char smem[6 * 4096];
    const uint32_t sb = smem_u32(smem);

    const int bh0 = blockIdx.x * 2;
    const int tid = threadIdx.x;

    const size_t g0 = (size_t)bh0 * NTOK * DH;
    const size_t g1 = (size_t)(bh0 + 1) * NTOK * DH;
    const __half* gp[6] = { qh + g0, kh + g0, vh + g0,
                            qh + g1, kh + g1, vh + g1 };

    // async fills: 6 tiles x 196 16B chunks
    if (tid < 196) {
        const int row = tid >> 2, kc = tid & 3;
        const uint32_t off = SWZ(row, kc);
        #pragma unroll
        for (int buf = 0; buf < 6; buf++)
            cp_async16(sb + buf * 4096 + off, gp[buf] + row * DH + kc * 8);
    }
    cp_commit();
    // zero pad rows 49..63 of all tiles (6 * 60 = 360 chunks)
    for (int i = tid; i < 360; i += 256) {
        const int buf = i / 60, rem = i - buf * 60;
        const int row = 49 + (rem >> 2), kc = rem & 3;
        *reinterpret_cast<uint4*>(smem + buf * 4096 + SWZ(row, kc)) = make_uint4(0, 0, 0, 0);
    }
    cp_wait<0>();
    __syncthreads();

    const int warp = tid >> 5, lane = tid & 31;
    const int wl = warp & 3;            // warp-local index within its bh
    const int which = warp >> 2;        // 0 -> bh0, 1 -> bh0+1
    const int mybh = bh0 + which;
    const int b = mybh >> 3, h = mybh & 7;
    const uint32_t tQ = sb + which * 3 * 4096;
    const uint32_t tK = tQ + 4096;
    const uint32_t tV = tQ + 8192;

    const int group = lane >> 2, tig = lane & 3;
    const int mat = lane >> 3, lrow = lane & 7;
    const int r0 = wl * 16 + group;

    // ---- QK^T: fp16 ----
    float acc[7][4];
    #pragma unroll
    for (int t = 0; t < 7; t++)
        #pragma unroll
        for (int r = 0; r < 4; r++) acc[t][r] = 0.f;

    #pragma unroll
    for (int kc16 = 0; kc16 < 2; kc16++) {
        const int arow = wl * 16 + ((mat & 1) << 3) + lrow;
        const int akc  = kc16 * 2 + (mat >> 1);
        uint32_t ah[4];
        ldm_x4(ah[0], ah[1], ah[2], ah[3], tQ + SWZ(arow, akc));
        #pragma unroll
        for (int g4 = 0; g4 < 4; g4++) {
            const int brow = g4 * 16 + ((mat >> 1) << 3) + lrow;
            const int bkc  = kc16 * 2 + (mat & 1);
            uint32_t bh2[2][2];
            ldm_x4(bh2[0][0], bh2[0][1], bh2[1][0], bh2[1][1], tK + SWZ(brow, bkc));
            #pragma unroll
            for (int u = 0; u < 2; u++) {
                const int t = g4 * 2 + u;
                if (t < 7) mma_f16(acc[t], ah, bh2[u]);
            }
        }
    }

    // ---- bias add (includes -1e30 masking) + unconditional softmax ----
    const float4* bfp = biasF + ((size_t)(((b & (NW - 1)) << 3) + h) * 4 + wl) * 7 * 32 + lane;
    float mx0 = NEG_BIG, mx1 = NEG_BIG;
    #pragma unroll
    for (int t = 0; t < 7; t++) {
        const float4 bv = __ldg(&bfp[t * 32]);
        acc[t][0] += bv.x;
        acc[t][1] += bv.y;
        acc[t][2] += bv.z;
        acc[t][3] += bv.w;
        mx0 = fmaxf(mx0, fmaxf(acc[t][0], acc[t][1]));
        mx1 = fmaxf(mx1, fmaxf(acc[t][2], acc[t][3]));
    }
    mx0 = fmaxf(mx0, __shfl_xor_sync(0xffffffffu, mx0, 1));
    mx0 = fmaxf(mx0, __shfl_xor_sync(0xffffffffu, mx0, 2));
    mx1 = fmaxf(mx1, __shfl_xor_sync(0xffffffffu, mx1, 1));
    mx1 = fmaxf(mx1, __shfl_xor_sync(0xffffffffu, mx1, 2));

    float s0 = 0.f, s1 = 0.f;
    #pragma unroll
    for (int t = 0; t < 7; t++) {
        acc[t][0] = __expf(acc[t][0] - mx0);
        acc[t][1] = __expf(acc[t][1] - mx0);
        acc[t][2] = __expf(acc[t][2] - mx1);
        acc[t][3] = __expf(acc[t][3] - mx1);
        s0 += acc[t][0] + acc[t][1];
        s1 += acc[t][2] + acc[t][3];
    }
    s0 += __shfl_xor_sync(0xffffffffu, s0, 1);
    s0 += __shfl_xor_sync(0xffffffffu, s0, 2);
    s1 += __shfl_xor_sync(0xffffffffu, s1, 1);
    s1 += __shfl_xor_sync(0xffffffffu, s1, 2);
    const float inv0 = 1.f / s0;
    const float inv1 = 1.f / s1;

    // ---- AV: P in registers as fp16 A-frags; V via ldmatrix.trans ----
    uint32_t pa[4][4];
    #pragma unroll
    for (int kc = 0; kc < 4; kc++) {
        const int t0 = kc * 2, t1 = kc * 2 + 1;
        pa[kc][0] = pack_h2(acc[t0][0] * inv0, acc[t0][1] * inv0);
        pa[kc][1] = pack_h2(acc[t0][2] * inv1, acc[t0][3] * inv1);
        if (t1 < 7) {
            pa[kc][2] = pack_h2(acc[t1][0] * inv0, acc[t1][1] * inv0);
            pa[kc][3] = pack_h2(acc[t1][2] * inv1, acc[t1][3] * inv1);
        } else {
            pa[kc][2] = 0u;
            pa[kc][3] = 0u;
        }
    }

    float av[4][4];
    #pragma unroll
    for (int nt = 0; nt < 4; nt++)
        #pragma unroll
        for (int r = 0; r < 4; r++) av[nt][r] = 0.f;

    #pragma unroll
    for (int kc = 0; kc < 4; kc++) {
        #pragma unroll
        for (int d16 = 0; d16 < 2; d16++) {
            const int vrow = kc * 16 + ((mat & 1) << 3) + lrow;
            const int vkc  = d16 * 2 + (mat >> 1);
            uint32_t bf[2][2];
            ldm_x4_t(bf[0][0], bf[0][1], bf[1][0], bf[1][1], tV + SWZ(vrow, vkc));
            mma_f16(av[d16 * 2],     pa[kc], bf[0]);
            mma_f16(av[d16 * 2 + 1], pa[kc], bf[1]);
        }
    }

    __half* ob = out + (size_t)b * NTOK * DIM + h * DH;
    if (r0 < NTOK) {
        #pragma unroll
        for (int nt = 0; nt < 4; nt++) {
            const int d = nt * 8 + tig * 2;
            *reinterpret_cast<__half2*>(&ob[(size_t)r0 * DIM + d]) =
                __floats2half2_rn(av[nt][0], av[nt][1]);
        }
    }
    if (r0 + 8 < NTOK) {
        #pragma unroll
        for (int nt = 0; nt < 4; nt++) {
            const int d = nt * 8 + tig * 2;
            *reinterpret_cast<__half2*>(&ob[(size_t)(r0 + 8) * DIM + d]) =
                __floats2half2_rn(av[nt][2], av[nt][3]);
        }
    }
}

// ---------------------------------------------------------------------------
// Launch
// ---------------------------------------------------------------------------
extern "C" void kernel_launch(void* const* d_in, const int* in_sizes, int n_in,
                              void* d_out, int out_size) {
    const float* x         = (const float*)d_in[0];
    const float* mask      = (const float*)d_in[1];
    const float* qkv_w     = (const float*)d_in[2];
    const float* qkv_b     = (const float*)d_in[3];
    const float* proj_w    = (const float*)d_in[4];
    const float* proj_b    = (const float*)d_in[5];
    const float* rpb_table = (const float*)d_in[6];
    const int*   rel_index = (const int*)d_in[7];
    float* out = (float*)d_out;

    __half *xh, *aoh, *wh, *pwh, *qh, *kh, *vh;
    float4 *biasF;
    cudaGetSymbolAddress((void**)&xh,  g_xh);
    cudaGetSymbolAddress((void**)&aoh, g_attn_outh);
    cudaGetSymbolAddress((void**)&wh,  g_wh);
    cudaGetSymbolAddress((void**)&pwh, g_pwh);
    cudaGetSymbolAddress((void**)&qh,  g_q);
    cudaGetSymbolAddress((void**)&kh,  g_k);
    cudaGetSymbolAddress((void**)&vh,  g_v);
    cudaGetSymbolAddress((void**)&biasF, g_biasF);

    cudaFuncSetAttribute(gemm_f16<0>,
                         cudaFuncAttributeMaxDynamicSharedMemorySize, GEMM_SMEM_BYTES);
    cudaFuncSetAttribute(gemm_f16<1>,
                         cudaFuncAttributeMaxDynamicSharedMemorySize, GEMM_SMEM_BYTES);

    // 0) fused prep: fragment bias + fp16 conversions (one launch)
    {
        const int na = MROWS * DIM / 4;
        const int nb = QKV_COLS * DIM / 4;
        const int nc = DIM * DIM / 4;
        const int total = na + nb + nc;
        const int cvt_blocks = (total + 255) / 256;
        prep_all<<<PREP_BIAS_BLOCKS + cvt_blocks, 256>>>(
            mask, rpb_table, rel_index, biasF,
            (const float4*)x, (uint2*)xh, na,
            (const float4*)qkv_w, (uint2*)wh, nb,
            (const float4*)proj_w, (uint2*)pwh, nc);
    }
    // 1) QKV projection with fused q/k/v epilogue
    {
        dim3 grid(QKV_COLS / 128, MROWS / 128);
        gemm_f16<1><<<grid, 256, GEMM_SMEM_BYTES>>>(xh, wh, qkv_b, nullptr,
                                                    qh, kh, vh,
                                                    MROWS, QKV_COLS, DIM);
    }
    // 2) attention (2 heads per CTA)
    attn_f16<<<NBH / 2, 256>>>(qh, kh, vh, biasF, aoh);
    // 3) output projection
    {
        dim3 grid(DIM / 128, MROWS / 128);
        gemm_f16<0><<<grid, 256, GEMM_SMEM_BYTES>>>(aoh, pwh, proj_b, out,
                                                    nullptr, nullptr, nullptr,
                                                    MROWS, DIM, DIM);
    }
}